// round 3
// baseline (speedup 1.0000x reference)
#include <cuda_runtime.h>
#include <cuda_bf16.h>
#include <math.h>

// ---------------------------------------------------------------------------
// Problem constants
//   B=4, L=4096, D_MODEL=1024, H=2, DEPTH=512, M_FEAT=256
// ---------------------------------------------------------------------------
#define BATCH     4
#define SEQ       4096
#define DMODEL    1024
#define HEADS     2
#define DEPTH     512
#define MFEAT     256
#define ROWS      (BATCH*SEQ)          // 16384
#define ROWS2     (ROWS*HEADS)         // 32768

#define SCALE2    0.044194173824159216f   // 1/sqrt(512)
#define FSCALE    0.21022410381342864f    // 512^{-0.25}
#define RATIO     0.0625f                 // 1/sqrt(256)
#define EPS       1e-6f

// ---------------------------------------------------------------------------
// Scratch (device globals; allocation is banned)
// ---------------------------------------------------------------------------
__device__ float g_Q [ (size_t)ROWS * DMODEL ];
__device__ float g_K [ (size_t)ROWS * DMODEL ];
__device__ float g_V [ (size_t)ROWS * DMODEL ];
__device__ float g_dQ[ (size_t)ROWS2 * MFEAT ];
__device__ float g_dK[ (size_t)ROWS2 * MFEAT ];
__device__ float g_diagK[ ROWS2 ];
__device__ float g_rmaxK[ ROWS2 ];
__device__ float g_kmax [ BATCH*HEADS ];
__device__ float g_C [ (size_t)ROWS * DMODEL ];
__device__ float g_featT[ (size_t)DEPTH * MFEAT ];   // feats^T : [512][256]

// ---------------------------------------------------------------------------
// TF32 helpers
// ---------------------------------------------------------------------------
__device__ __forceinline__ float to_tf32(float x) {
    float r;
    asm("cvt.rna.tf32.f32 %0, %1;" : "=f"(r) : "f"(x));
    return r;
}

__device__ __forceinline__ void mma_tf32(float c[4], const float a[4], const float b[2]) {
    asm volatile(
        "mma.sync.aligned.m16n8k8.row.col.f32.tf32.tf32.f32 "
        "{%0,%1,%2,%3}, {%4,%5,%6,%7}, {%8,%9}, {%0,%1,%2,%3};"
        : "+f"(c[0]), "+f"(c[1]), "+f"(c[2]), "+f"(c[3])
        : "r"(__float_as_uint(a[0])), "r"(__float_as_uint(a[1])),
          "r"(__float_as_uint(a[2])), "r"(__float_as_uint(a[3])),
          "r"(__float_as_uint(b[0])), "r"(__float_as_uint(b[1])));
}

// ---------------------------------------------------------------------------
// Transpose feats [256][512] -> featT [512][256]
// ---------------------------------------------------------------------------
__global__ __launch_bounds__(256)
void transpose_kernel(const float* __restrict__ in, float* __restrict__ out)
{
    __shared__ float tile[32][33];
    int bx = blockIdx.x * 32;   // column block of in (k dim, 512)
    int by = blockIdx.y * 32;   // row block of in (m dim, 256)
    int tx = threadIdx.x & 31;
    int ty = threadIdx.x >> 5;  // 0..7
    #pragma unroll
    for (int i = 0; i < 32; i += 8)
        tile[ty + i][tx] = in[(size_t)(by + ty + i) * DEPTH + bx + tx];
    __syncthreads();
    #pragma unroll
    for (int i = 0; i < 32; i += 8)
        out[(size_t)(bx + ty + i) * MFEAT + by + tx] = tile[tx][ty + i];
}

// ---------------------------------------------------------------------------
// TF32 GEMM: C = alpha * A(MxK) * B(KxN) (+ bias)
// Tiles: CTA 128x128, K-step 16, 8 warps (warp tile 64x32), double-buffered.
// Vectorized STS.128 staging with RNA tf32 conversion in registers.
// Requires M%128==0, N%128==0, K%16==0.
// ---------------------------------------------------------------------------
#define AS_STRIDE 20     // 16 k + 4 pad  (floats); 80B rows, 16B aligned
#define BS_STRIDE 136    // 128 n + 8 pad (floats); 544B rows, 16B aligned

__global__ __launch_bounds__(256)
void tf32_gemm(const float* __restrict__ A, const float* __restrict__ B,
               const float* __restrict__ bias, float* __restrict__ C,
               int M, int N, int K, float alpha)
{
    __shared__ float As[2][128][AS_STRIDE];   // [m][k]
    __shared__ float Bs[2][16][BS_STRIDE];    // [k][n]

    const int tid  = threadIdx.x;
    const int lane = tid & 31;
    const int wid  = tid >> 5;
    const int bm   = blockIdx.y * 128;
    const int bn   = blockIdx.x * 128;

    const int warp_m = (wid & 1) * 64;   // 2 warps along m
    const int warp_n = (wid >> 1) * 32;  // 4 warps along n
    const int lr = lane >> 2;            // 0..7
    const int lc = lane & 3;             // 0..3

    // staging indices
    const int a_row = tid >> 1;              // 0..127
    const int a_kg  = (tid & 1) * 8;         // 0 or 8
    const int b_kr  = tid >> 4;              // 0..15
    const int b_ng  = (tid & 15) * 8;        // 0..120

    float acc[4][4][4];
    #pragma unroll
    for (int i = 0; i < 4; i++)
        #pragma unroll
        for (int j = 0; j < 4; j++)
            #pragma unroll
            for (int r = 0; r < 4; r++) acc[i][j][r] = 0.f;

    float4 pa0, pa1, pb0, pb1;

    // ---- prefetch tile 0 into registers
    {
        const float* ap = A + (size_t)(bm + a_row) * K + a_kg;
        pa0 = *reinterpret_cast<const float4*>(ap);
        pa1 = *reinterpret_cast<const float4*>(ap + 4);
        const float* bp = B + (size_t)b_kr * N + bn + b_ng;
        pb0 = *reinterpret_cast<const float4*>(bp);
        pb1 = *reinterpret_cast<const float4*>(bp + 4);
    }

    // ---- store stage 0 (convert in regs, STS.128)
    {
        float4 ca0 = make_float4(to_tf32(pa0.x), to_tf32(pa0.y), to_tf32(pa0.z), to_tf32(pa0.w));
        float4 ca1 = make_float4(to_tf32(pa1.x), to_tf32(pa1.y), to_tf32(pa1.z), to_tf32(pa1.w));
        *reinterpret_cast<float4*>(&As[0][a_row][a_kg])     = ca0;
        *reinterpret_cast<float4*>(&As[0][a_row][a_kg + 4]) = ca1;
        float4 cb0 = make_float4(to_tf32(pb0.x), to_tf32(pb0.y), to_tf32(pb0.z), to_tf32(pb0.w));
        float4 cb1 = make_float4(to_tf32(pb1.x), to_tf32(pb1.y), to_tf32(pb1.z), to_tf32(pb1.w));
        *reinterpret_cast<float4*>(&Bs[0][b_kr][b_ng])     = cb0;
        *reinterpret_cast<float4*>(&Bs[0][b_kr][b_ng + 4]) = cb1;
    }
    __syncthreads();

    const int nstages = K >> 4;
    for (int s = 0; s < nstages; s++) {
        const int buf = s & 1;
        const int kb_next = (s + 1) << 4;

        // prefetch next tile
        if (s + 1 < nstages) {
            const float* ap = A + (size_t)(bm + a_row) * K + kb_next + a_kg;
            pa0 = *reinterpret_cast<const float4*>(ap);
            pa1 = *reinterpret_cast<const float4*>(ap + 4);
            const float* bp = B + (size_t)(kb_next + b_kr) * N + bn + b_ng;
            pb0 = *reinterpret_cast<const float4*>(bp);
            pb1 = *reinterpret_cast<const float4*>(bp + 4);
        }

        // compute on buf
        #pragma unroll
        for (int kk = 0; kk < 16; kk += 8) {
            float a[4][4], b[4][2];
            #pragma unroll
            for (int mi = 0; mi < 4; mi++) {
                int m = warp_m + mi * 16 + lr;
                a[mi][0] = As[buf][m    ][kk + lc];
                a[mi][1] = As[buf][m + 8][kk + lc];
                a[mi][2] = As[buf][m    ][kk + lc + 4];
                a[mi][3] = As[buf][m + 8][kk + lc + 4];
            }
            #pragma unroll
            for (int ni = 0; ni < 4; ni++) {
                int n = warp_n + ni * 8 + lr;
                b[ni][0] = Bs[buf][kk + lc    ][n];
                b[ni][1] = Bs[buf][kk + lc + 4][n];
            }
            #pragma unroll
            for (int mi = 0; mi < 4; mi++)
                #pragma unroll
                for (int ni = 0; ni < 4; ni++)
                    mma_tf32(acc[mi][ni], a[mi], b[ni]);
        }

        // store next stage
        if (s + 1 < nstages) {
            const int nb = buf ^ 1;
            float4 ca0 = make_float4(to_tf32(pa0.x), to_tf32(pa0.y), to_tf32(pa0.z), to_tf32(pa0.w));
            float4 ca1 = make_float4(to_tf32(pa1.x), to_tf32(pa1.y), to_tf32(pa1.z), to_tf32(pa1.w));
            *reinterpret_cast<float4*>(&As[nb][a_row][a_kg])     = ca0;
            *reinterpret_cast<float4*>(&As[nb][a_row][a_kg + 4]) = ca1;
            float4 cb0 = make_float4(to_tf32(pb0.x), to_tf32(pb0.y), to_tf32(pb0.z), to_tf32(pb0.w));
            float4 cb1 = make_float4(to_tf32(pb1.x), to_tf32(pb1.y), to_tf32(pb1.z), to_tf32(pb1.w));
            *reinterpret_cast<float4*>(&Bs[nb][b_kr][b_ng])     = cb0;
            *reinterpret_cast<float4*>(&Bs[nb][b_kr][b_ng + 4]) = cb1;
        }
        __syncthreads();
    }

    // ---- epilogue: c0,c1 at (row, 2*lc), c2,c3 at (row+8, 2*lc)
    #pragma unroll
    for (int mi = 0; mi < 4; mi++) {
        #pragma unroll
        for (int ni = 0; ni < 4; ni++) {
            int row = bm + warp_m + mi * 16 + lr;
            int col = bn + warp_n + ni * 8 + 2 * lc;
            float b0 = bias ? bias[col]     : 0.f;
            float b1 = bias ? bias[col + 1] : 0.f;
            float2 v0 = make_float2(alpha * acc[mi][ni][0] + b0,
                                    alpha * acc[mi][ni][1] + b1);
            float2 v1 = make_float2(alpha * acc[mi][ni][2] + b0,
                                    alpha * acc[mi][ni][3] + b1);
            *reinterpret_cast<float2*>(&C[(size_t)row * N + col])       = v0;
            *reinterpret_cast<float2*>(&C[(size_t)(row + 8) * N + col]) = v1;
        }
    }
}

// ---------------------------------------------------------------------------
// q' : per row (32768) diag from Y row, row-max of dash row, exp (in place)
// one warp per row
// ---------------------------------------------------------------------------
__global__ __launch_bounds__(256)
void qprime_kernel(const float* __restrict__ Y, float* __restrict__ dash)
{
    int warp = (blockIdx.x * blockDim.x + threadIdx.x) >> 5;
    int lane = threadIdx.x & 31;
    if (warp >= ROWS2) return;

    const float* y = Y + (size_t)warp * DEPTH;
    float ss = 0.f;
    #pragma unroll
    for (int i = 0; i < DEPTH/32; i++) { float v = y[lane + 32*i]; ss += v*v; }
    #pragma unroll
    for (int off = 16; off; off >>= 1) ss += __shfl_xor_sync(0xffffffff, ss, off);
    float diag = 0.5f * SCALE2 * ss;

    float* dr = dash + (size_t)warp * MFEAT;
    float vals[MFEAT/32];
    float mx = -1e30f;
    #pragma unroll
    for (int i = 0; i < MFEAT/32; i++) { vals[i] = dr[lane + 32*i]; mx = fmaxf(mx, vals[i]); }
    #pragma unroll
    for (int off = 16; off; off >>= 1) mx = fmaxf(mx, __shfl_xor_sync(0xffffffff, mx, off));

    #pragma unroll
    for (int i = 0; i < MFEAT/32; i++)
        dr[lane + 32*i] = RATIO * (expf(vals[i] - diag - mx) + EPS);
}

// ---------------------------------------------------------------------------
// k path step 1: per-row diag + per-row max
// ---------------------------------------------------------------------------
__global__ __launch_bounds__(256)
void kstat_kernel(const float* __restrict__ Y, const float* __restrict__ dash,
                  float* __restrict__ diagK, float* __restrict__ rmaxK)
{
    int warp = (blockIdx.x * blockDim.x + threadIdx.x) >> 5;
    int lane = threadIdx.x & 31;
    if (warp >= ROWS2) return;

    const float* y = Y + (size_t)warp * DEPTH;
    float ss = 0.f;
    #pragma unroll
    for (int i = 0; i < DEPTH/32; i++) { float v = y[lane + 32*i]; ss += v*v; }
    #pragma unroll
    for (int off = 16; off; off >>= 1) ss += __shfl_xor_sync(0xffffffff, ss, off);

    const float* dr = dash + (size_t)warp * MFEAT;
    float mx = -1e30f;
    #pragma unroll
    for (int i = 0; i < MFEAT/32; i++) mx = fmaxf(mx, dr[lane + 32*i]);
    #pragma unroll
    for (int off = 16; off; off >>= 1) mx = fmaxf(mx, __shfl_xor_sync(0xffffffff, mx, off));

    if (lane == 0) { diagK[warp] = 0.5f * SCALE2 * ss; rmaxK[warp] = mx; }
}

// k path step 2: reduce row maxima over the sequence per (b,h)
__global__ __launch_bounds__(256)
void kmax_kernel(const float* __restrict__ rmaxK, float* __restrict__ kmax)
{
    int bh = blockIdx.x;
    int b  = bh >> 1, h = bh & 1;
    __shared__ float sm[256];
    float mx = -1e30f;
    for (int l = threadIdx.x; l < SEQ; l += 256)
        mx = fmaxf(mx, rmaxK[b*8192 + l*2 + h]);
    sm[threadIdx.x] = mx;
    __syncthreads();
    for (int s = 128; s; s >>= 1) {
        if (threadIdx.x < s) sm[threadIdx.x] = fmaxf(sm[threadIdx.x], sm[threadIdx.x + s]);
        __syncthreads();
    }
    if (threadIdx.x == 0) kmax[bh] = sm[0];
}

// k path step 3
__global__ __launch_bounds__(256)
void kexp_kernel(float* __restrict__ dash, const float* __restrict__ diagK,
                 const float* __restrict__ kmax)
{
    size_t idx = (size_t)blockIdx.x * blockDim.x + threadIdx.x;
    size_t total = (size_t)ROWS2 * MFEAT;
    if (idx >= total) return;
    int r = (int)(idx >> 8);
    int b = r >> 13;
    int h = r & 1;
    float v = dash[idx];
    dash[idx] = RATIO * (expf(v - diagK[r] - kmax[b*2 + h]) + EPS);
}

// ---------------------------------------------------------------------------
// Attention mix: per (s,h) block; 4x4 batch mix, scrambled concat store
// ---------------------------------------------------------------------------
__global__ __launch_bounds__(256)
void attn_mix_kernel(const float* __restrict__ QP, const float* __restrict__ KP,
                     const float* __restrict__ V, float* __restrict__ C)
{
    int blk = blockIdx.x;
    int s = blk >> 1, h = blk & 1;
    __shared__ float q_s[4][MFEAT];
    __shared__ float k_s[4][MFEAT];
    __shared__ float S[4][4];
    __shared__ float rs[4];
    int tid = threadIdx.x;

    #pragma unroll
    for (int bb = 0; bb < 4; bb++) {
        size_t r = (size_t)((bb*SEQ + s)*HEADS + h);
        q_s[bb][tid] = QP[r*MFEAT + tid];
        k_s[bb][tid] = KP[r*MFEAT + tid];
    }
    __syncthreads();

    int p = tid >> 4, lane16 = tid & 15;
    int bb = p >> 2, bp = p & 3;
    float acc = 0.f;
    #pragma unroll
    for (int m = 0; m < MFEAT; m += 16) acc += q_s[bb][m + lane16] * k_s[bp][m + lane16];
    #pragma unroll
    for (int off = 8; off; off >>= 1) acc += __shfl_down_sync(0xffffffff, acc, off, 16);
    if (lane16 == 0) S[bb][bp] = acc;
    __syncthreads();
    if (tid < 4) rs[tid] = S[tid][0] + S[tid][1] + S[tid][2] + S[tid][3];
    __syncthreads();

    float s00=S[0][0],s01=S[0][1],s02=S[0][2],s03=S[0][3];
    float s10=S[1][0],s11=S[1][1],s12=S[1][2],s13=S[1][3];
    float s20=S[2][0],s21=S[2][1],s22=S[2][2],s23=S[2][3];
    float s30=S[3][0],s31=S[3][1],s32=S[3][2],s33=S[3][3];
    float r0 = 1.f/rs[0], r1 = 1.f/rs[1], r2 = 1.f/rs[2], r3 = 1.f/rs[3];

    size_t cbase = (size_t)s*4096 + (size_t)h*2048;
    for (int d = tid; d < DEPTH; d += 256) {
        float v0 = V[(size_t)((0*SEQ + s)*HEADS + h)*DEPTH + d];
        float v1 = V[(size_t)((1*SEQ + s)*HEADS + h)*DEPTH + d];
        float v2 = V[(size_t)((2*SEQ + s)*HEADS + h)*DEPTH + d];
        float v3 = V[(size_t)((3*SEQ + s)*HEADS + h)*DEPTH + d];
        C[cbase + 0*512 + d] = (s00*v0 + s01*v1 + s02*v2 + s03*v3) * r0;
        C[cbase + 1*512 + d] = (s10*v0 + s11*v1 + s12*v2 + s13*v3) * r1;
        C[cbase + 2*512 + d] = (s20*v0 + s21*v1 + s22*v2 + s23*v3) * r2;
        C[cbase + 3*512 + d] = (s30*v0 + s31*v1 + s32*v2 + s33*v3) * r3;
    }
}

// ---------------------------------------------------------------------------
// Launch
// ---------------------------------------------------------------------------
extern "C" void kernel_launch(void* const* d_in, const int* in_sizes, int n_in,
                              void* d_out, int out_size)
{
    const float* query = (const float*)d_in[0];
    const float* key   = (const float*)d_in[1];
    const float* value = (const float*)d_in[2];
    const float* Wq = (const float*)d_in[4];
    const float* bq = (const float*)d_in[5];
    const float* Wk = (const float*)d_in[6];
    const float* bk = (const float*)d_in[7];
    const float* Wv = (const float*)d_in[8];
    const float* bv = (const float*)d_in[9];
    const float* Wo = (const float*)d_in[10];
    const float* bo = (const float*)d_in[11];
    const float* feats = (const float*)d_in[12];   // [256, 512]
    float* out = (float*)d_out;

    float *Q, *K, *V, *dQ, *dK, *diagK, *rmaxK, *kmax, *C, *featT;
    cudaGetSymbolAddress((void**)&Q,     g_Q);
    cudaGetSymbolAddress((void**)&K,     g_K);
    cudaGetSymbolAddress((void**)&V,     g_V);
    cudaGetSymbolAddress((void**)&dQ,    g_dQ);
    cudaGetSymbolAddress((void**)&dK,    g_dK);
    cudaGetSymbolAddress((void**)&diagK, g_diagK);
    cudaGetSymbolAddress((void**)&rmaxK, g_rmaxK);
    cudaGetSymbolAddress((void**)&kmax,  g_kmax);
    cudaGetSymbolAddress((void**)&C,     g_C);
    cudaGetSymbolAddress((void**)&featT, g_featT);

    // 0: feats^T
    {
        dim3 gT(DEPTH/32, MFEAT/32);
        transpose_kernel<<<gT, 256>>>(feats, featT);
    }

    // 1-3: projections  Y = X @ W + b     (16384 x 1024 x 1024)
    dim3 gProj(DMODEL/128, ROWS/128);
    tf32_gemm<<<gProj, 256>>>(query, Wq, bq, Q, ROWS, DMODEL, DMODEL, 1.f);
    tf32_gemm<<<gProj, 256>>>(key,   Wk, bk, K, ROWS, DMODEL, DMODEL, 1.f);
    tf32_gemm<<<gProj, 256>>>(value, Wv, bv, V, ROWS, DMODEL, DMODEL, 1.f);

    // 4-5: feature projections  dash = (scale*Y512) @ featT   (32768 x 256 x 512)
    dim3 gFeat(MFEAT/128, ROWS2/128);
    tf32_gemm<<<gFeat, 256>>>(Q, featT, nullptr, dQ, ROWS2, MFEAT, DEPTH, FSCALE);
    tf32_gemm<<<gFeat, 256>>>(K, featT, nullptr, dK, ROWS2, MFEAT, DEPTH, FSCALE);

    // 6: q'
    qprime_kernel<<<ROWS2/8, 256>>>(Q, dQ);

    // 7-9: k'
    kstat_kernel<<<ROWS2/8, 256>>>(K, dK, diagK, rmaxK);
    kmax_kernel<<<BATCH*HEADS, 256>>>(rmaxK, kmax);
    {
        size_t total = (size_t)ROWS2 * MFEAT;
        kexp_kernel<<<(unsigned)((total + 255)/256), 256>>>(dK, diagK, kmax);
    }

    // 10: attention mix
    attn_mix_kernel<<<SEQ*HEADS, 256>>>(dQ, dK, V, C);

    // 11: out = C @ Wo + bo
    tf32_gemm<<<gProj, 256>>>(C, Wo, bo, out, ROWS, DMODEL, DMODEL, 1.f);
}

// round 5
// speedup vs baseline: 1.2548x; 1.2548x over previous
#include <cuda_runtime.h>
#include <cuda_fp16.h>
#include <math.h>
#include <stdint.h>

// ---------------------------------------------------------------------------
// Problem constants
// ---------------------------------------------------------------------------
#define BATCH     4
#define SEQ       4096
#define DMODEL    1024
#define HEADS     2
#define DEPTH     512
#define MFEAT     256
#define ROWS      (BATCH*SEQ)          // 16384
#define ROWS2     (ROWS*HEADS)         // 32768

#define SCALE2    0.044194173824159216f   // 1/sqrt(512)
#define FSCALE    0.21022410381342864f    // 512^{-0.25}
#define RATIO     0.0625f                 // 1/sqrt(256)
#define EPS       1e-6f

// ---------------------------------------------------------------------------
// Scratch (device globals; allocation is banned)
// ---------------------------------------------------------------------------
__device__ float g_Q [ (size_t)ROWS * DMODEL ];
__device__ float g_K [ (size_t)ROWS * DMODEL ];
__device__ float g_V [ (size_t)ROWS * DMODEL ];
__device__ float g_dQ[ (size_t)ROWS2 * MFEAT ];
__device__ float g_dK[ (size_t)ROWS2 * MFEAT ];
__device__ float g_diagK[ ROWS2 ];
__device__ float g_rmaxK[ ROWS2 ];
__device__ float g_kmax [ BATCH*HEADS ];
__device__ float g_C  [ (size_t)ROWS * DMODEL ];
__device__ float g_Wt [ (size_t)DMODEL * DMODEL ];   // reused weight transpose

// ---------------------------------------------------------------------------
// helpers
// ---------------------------------------------------------------------------
__device__ __forceinline__ uint32_t smem_u32(const void* p) {
    uint32_t a;
    asm("{ .reg .u64 t; cvta.to.shared.u64 t, %1; cvt.u32.u64 %0, t; }"
        : "=r"(a) : "l"(p));
    return a;
}

__device__ __forceinline__ void ldsm_x4(uint32_t& r0, uint32_t& r1,
                                        uint32_t& r2, uint32_t& r3, uint32_t addr) {
    asm volatile("ldmatrix.sync.aligned.m8n8.x4.shared.b16 {%0,%1,%2,%3}, [%4];"
                 : "=r"(r0), "=r"(r1), "=r"(r2), "=r"(r3) : "r"(addr));
}

__device__ __forceinline__ void mma_f16(float c[4], const uint32_t a[4],
                                        const uint32_t b[2]) {
    asm volatile(
        "mma.sync.aligned.m16n8k16.row.col.f32.f16.f16.f32 "
        "{%0,%1,%2,%3}, {%4,%5,%6,%7}, {%8,%9}, {%0,%1,%2,%3};"
        : "+f"(c[0]), "+f"(c[1]), "+f"(c[2]), "+f"(c[3])
        : "r"(a[0]), "r"(a[1]), "r"(a[2]), "r"(a[3]),
          "r"(b[0]), "r"(b[1]));
}

// ---------------------------------------------------------------------------
// fp16 GEMM (fp32 accumulate):  C = alpha * A(M,K) @ Bop(N,K)^T (+ bias)
//   A   : [M,K] row-major f32 (converted fp16 on staging)
//   Bop : [N,K] row-major f32 (math-B transposed; converted fp16 on staging)
// CTA tile 128x128, K-step 32, 8 warps (warp tile 64x32), double buffered,
// ldmatrix fragment loads. Requires M%128==0, N%128==0, K%32==0.
// ---------------------------------------------------------------------------
#define ASTR 40   // halves per SMEM row: 32 + 8 pad (80B; LDSM conflict-free)

__global__ __launch_bounds__(256)
void hgemm(const float* __restrict__ A, const float* __restrict__ Bop,
           const float* __restrict__ bias, float* __restrict__ C,
           int M, int N, int K, float alpha)
{
    __shared__ __half As[2][128][ASTR];   // [m][k]
    __shared__ __half Bs[2][128][ASTR];   // [n][k]

    const int tid  = threadIdx.x;
    const int lane = tid & 31;
    const int wid  = tid >> 5;
    const int bm = blockIdx.y * 128;
    const int bn = blockIdx.x * 128;

    const int warp_m = (wid & 1) * 64;    // 2 warps along m
    const int warp_n = (wid >> 1) * 32;   // 4 warps along n
    const int lr = lane >> 2;             // 0..7
    const int lc = lane & 3;              // 0..3

    // staging: thread -> (row = tid>>1, 16 k-elems at kg)
    const int st_row = tid >> 1;
    const int st_kg  = (tid & 1) * 16;

    float acc[4][4][4];
    #pragma unroll
    for (int i = 0; i < 4; i++)
        #pragma unroll
        for (int j = 0; j < 4; j++)
            #pragma unroll
            for (int r = 0; r < 4; r++) acc[i][j][r] = 0.f;

    // ldmatrix lane addressing (within a 128x32 tile, halves)
    const int a_lrow = (lane & 7) + ((lane >> 3) & 1) * 8;   // row offset in 16
    const int a_lcol = (lane >> 4) * 8;                      // col offset (halves)
    const int b_lrow = (lane & 7) + (lane >= 16 ? 8 : 0);    // row offset in 16
    const int b_lcol = ((lane >> 3) & 1) * 8;                // col offset (halves)

    float4 pa0, pa1, pa2, pa3, pb0, pb1, pb2, pb3;

    auto prefetch = [&](int k0) {
        const float* ap = A   + (size_t)(bm + st_row) * K + k0 + st_kg;
        pa0 = *reinterpret_cast<const float4*>(ap);
        pa1 = *reinterpret_cast<const float4*>(ap + 4);
        pa2 = *reinterpret_cast<const float4*>(ap + 8);
        pa3 = *reinterpret_cast<const float4*>(ap + 12);
        const float* bp = Bop + (size_t)(bn + st_row) * K + k0 + st_kg;
        pb0 = *reinterpret_cast<const float4*>(bp);
        pb1 = *reinterpret_cast<const float4*>(bp + 4);
        pb2 = *reinterpret_cast<const float4*>(bp + 8);
        pb3 = *reinterpret_cast<const float4*>(bp + 12);
    };

    auto store_stage = [&](int buf) {
        __half h[16];
        float f[16] = {pa0.x,pa0.y,pa0.z,pa0.w, pa1.x,pa1.y,pa1.z,pa1.w,
                       pa2.x,pa2.y,pa2.z,pa2.w, pa3.x,pa3.y,pa3.z,pa3.w};
        #pragma unroll
        for (int i = 0; i < 16; i++) h[i] = __float2half_rn(f[i]);
        *reinterpret_cast<uint4*>(&As[buf][st_row][st_kg])     = *reinterpret_cast<uint4*>(h);
        *reinterpret_cast<uint4*>(&As[buf][st_row][st_kg + 8]) = *reinterpret_cast<uint4*>(h + 8);
        float g[16] = {pb0.x,pb0.y,pb0.z,pb0.w, pb1.x,pb1.y,pb1.z,pb1.w,
                       pb2.x,pb2.y,pb2.z,pb2.w, pb3.x,pb3.y,pb3.z,pb3.w};
        #pragma unroll
        for (int i = 0; i < 16; i++) h[i] = __float2half_rn(g[i]);
        *reinterpret_cast<uint4*>(&Bs[buf][st_row][st_kg])     = *reinterpret_cast<uint4*>(h);
        *reinterpret_cast<uint4*>(&Bs[buf][st_row][st_kg + 8]) = *reinterpret_cast<uint4*>(h + 8);
    };

    prefetch(0);
    store_stage(0);
    __syncthreads();

    const int nstages = K >> 5;     // K/32
    for (int s = 0; s < nstages; s++) {
        const int buf = s & 1;
        if (s + 1 < nstages) prefetch((s + 1) << 5);

        #pragma unroll
        for (int kk = 0; kk < 32; kk += 16) {
            uint32_t a[4][4], b[4][2];
            #pragma unroll
            for (int mi = 0; mi < 4; mi++) {
                uint32_t addr = smem_u32(
                    &As[buf][warp_m + mi * 16 + a_lrow][kk + a_lcol]);
                ldsm_x4(a[mi][0], a[mi][1], a[mi][2], a[mi][3], addr);
            }
            #pragma unroll
            for (int nj = 0; nj < 2; nj++) {
                uint32_t addr = smem_u32(
                    &Bs[buf][warp_n + nj * 16 + b_lrow][kk + b_lcol]);
                ldsm_x4(b[2*nj][0], b[2*nj][1], b[2*nj+1][0], b[2*nj+1][1], addr);
            }
            #pragma unroll
            for (int mi = 0; mi < 4; mi++)
                #pragma unroll
                for (int ni = 0; ni < 4; ni++)
                    mma_f16(acc[mi][ni], a[mi], b[ni]);
        }

        if (s + 1 < nstages) store_stage(buf ^ 1);
        __syncthreads();
    }

    // epilogue: c0,c1 at (row, 2*lc), c2,c3 at (row+8, 2*lc)
    #pragma unroll
    for (int mi = 0; mi < 4; mi++) {
        #pragma unroll
        for (int ni = 0; ni < 4; ni++) {
            int row = bm + warp_m + mi * 16 + lr;
            int col = bn + warp_n + ni * 8 + 2 * lc;
            float b0 = bias ? bias[col]     : 0.f;
            float b1 = bias ? bias[col + 1] : 0.f;
            float2 v0 = make_float2(alpha * acc[mi][ni][0] + b0,
                                    alpha * acc[mi][ni][1] + b1);
            float2 v1 = make_float2(alpha * acc[mi][ni][2] + b0,
                                    alpha * acc[mi][ni][3] + b1);
            *reinterpret_cast<float2*>(&C[(size_t)row * N + col])       = v0;
            *reinterpret_cast<float2*>(&C[(size_t)(row + 8) * N + col]) = v1;
        }
    }
}

// ---------------------------------------------------------------------------
// Generic transpose: out[c][r] = in[r][c];  in is [R][Cin]
// ---------------------------------------------------------------------------
__global__ __launch_bounds__(256)
void transpose_kernel(const float* __restrict__ in, float* __restrict__ out,
                      int R, int Cin)
{
    __shared__ float tile[32][33];
    int bx = blockIdx.x * 32;
    int by = blockIdx.y * 32;
    int tx = threadIdx.x & 31;
    int ty = threadIdx.x >> 5;
    #pragma unroll
    for (int i = 0; i < 32; i += 8)
        tile[ty + i][tx] = in[(size_t)(by + ty + i) * Cin + bx + tx];
    __syncthreads();
    #pragma unroll
    for (int i = 0; i < 32; i += 8)
        out[(size_t)(bx + ty + i) * R + by + tx] = tile[tx][ty + i];
}

// ---------------------------------------------------------------------------
// q' : per row (32768) diag from Y row, row-max of dash row, exp (in place)
// ---------------------------------------------------------------------------
__global__ __launch_bounds__(256)
void qprime_kernel(const float* __restrict__ Y, float* __restrict__ dash)
{
    int warp = (blockIdx.x * blockDim.x + threadIdx.x) >> 5;
    int lane = threadIdx.x & 31;
    if (warp >= ROWS2) return;

    const float* y = Y + (size_t)warp * DEPTH;
    float ss = 0.f;
    #pragma unroll
    for (int i = 0; i < DEPTH/32; i++) { float v = y[lane + 32*i]; ss += v*v; }
    #pragma unroll
    for (int off = 16; off; off >>= 1) ss += __shfl_xor_sync(0xffffffff, ss, off);
    float diag = 0.5f * SCALE2 * ss;

    float* dr = dash + (size_t)warp * MFEAT;
    float vals[MFEAT/32];
    float mx = -1e30f;
    #pragma unroll
    for (int i = 0; i < MFEAT/32; i++) { vals[i] = dr[lane + 32*i]; mx = fmaxf(mx, vals[i]); }
    #pragma unroll
    for (int off = 16; off; off >>= 1) mx = fmaxf(mx, __shfl_xor_sync(0xffffffff, mx, off));

    #pragma unroll
    for (int i = 0; i < MFEAT/32; i++)
        dr[lane + 32*i] = RATIO * (expf(vals[i] - diag - mx) + EPS);
}

// ---------------------------------------------------------------------------
// k path step 1: per-row diag + per-row max
// ---------------------------------------------------------------------------
__global__ __launch_bounds__(256)
void kstat_kernel(const float* __restrict__ Y, const float* __restrict__ dash,
                  float* __restrict__ diagK, float* __restrict__ rmaxK)
{
    int warp = (blockIdx.x * blockDim.x + threadIdx.x) >> 5;
    int lane = threadIdx.x & 31;
    if (warp >= ROWS2) return;

    const float* y = Y + (size_t)warp * DEPTH;
    float ss = 0.f;
    #pragma unroll
    for (int i = 0; i < DEPTH/32; i++) { float v = y[lane + 32*i]; ss += v*v; }
    #pragma unroll
    for (int off = 16; off; off >>= 1) ss += __shfl_xor_sync(0xffffffff, ss, off);

    const float* dr = dash + (size_t)warp * MFEAT;
    float mx = -1e30f;
    #pragma unroll
    for (int i = 0; i < MFEAT/32; i++) mx = fmaxf(mx, dr[lane + 32*i]);
    #pragma unroll
    for (int off = 16; off; off >>= 1) mx = fmaxf(mx, __shfl_xor_sync(0xffffffff, mx, off));

    if (lane == 0) { diagK[warp] = 0.5f * SCALE2 * ss; rmaxK[warp] = mx; }
}

// k path step 2
__global__ __launch_bounds__(256)
void kmax_kernel(const float* __restrict__ rmaxK, float* __restrict__ kmax)
{
    int bh = blockIdx.x;
    int b  = bh >> 1, h = bh & 1;
    __shared__ float sm[256];
    float mx = -1e30f;
    for (int l = threadIdx.x; l < SEQ; l += 256)
        mx = fmaxf(mx, rmaxK[b*8192 + l*2 + h]);
    sm[threadIdx.x] = mx;
    __syncthreads();
    for (int s = 128; s; s >>= 1) {
        if (threadIdx.x < s) sm[threadIdx.x] = fmaxf(sm[threadIdx.x], sm[threadIdx.x + s]);
        __syncthreads();
    }
    if (threadIdx.x == 0) kmax[bh] = sm[0];
}

// k path step 3
__global__ __launch_bounds__(256)
void kexp_kernel(float* __restrict__ dash, const float* __restrict__ diagK,
                 const float* __restrict__ kmax)
{
    size_t idx = (size_t)blockIdx.x * blockDim.x + threadIdx.x;
    size_t total = (size_t)ROWS2 * MFEAT;
    if (idx >= total) return;
    int r = (int)(idx >> 8);
    int b = r >> 13;
    int h = r & 1;
    float v = dash[idx];
    dash[idx] = RATIO * (expf(v - diagK[r] - kmax[b*2 + h]) + EPS);
}

// ---------------------------------------------------------------------------
// Attention mix: per (s,h) block; 4x4 batch mix, scrambled concat store
// ---------------------------------------------------------------------------
__global__ __launch_bounds__(256)
void attn_mix_kernel(const float* __restrict__ QP, const float* __restrict__ KP,
                     const float* __restrict__ V, float* __restrict__ C)
{
    int blk = blockIdx.x;
    int s = blk >> 1, h = blk & 1;
    __shared__ float q_s[4][MFEAT];
    __shared__ float k_s[4][MFEAT];
    __shared__ float S[4][4];
    __shared__ float rs[4];
    int tid = threadIdx.x;

    #pragma unroll
    for (int bb = 0; bb < 4; bb++) {
        size_t r = (size_t)((bb*SEQ + s)*HEADS + h);
        q_s[bb][tid] = QP[r*MFEAT + tid];
        k_s[bb][tid] = KP[r*MFEAT + tid];
    }
    __syncthreads();

    int p = tid >> 4, lane16 = tid & 15;
    int bb = p >> 2, bp = p & 3;
    float acc = 0.f;
    #pragma unroll
    for (int m = 0; m < MFEAT; m += 16) acc += q_s[bb][m + lane16] * k_s[bp][m + lane16];
    #pragma unroll
    for (int off = 8; off; off >>= 1) acc += __shfl_down_sync(0xffffffff, acc, off, 16);
    if (lane16 == 0) S[bb][bp] = acc;
    __syncthreads();
    if (tid < 4) rs[tid] = S[tid][0] + S[tid][1] + S[tid][2] + S[tid][3];
    __syncthreads();

    float s00=S[0][0],s01=S[0][1],s02=S[0][2],s03=S[0][3];
    float s10=S[1][0],s11=S[1][1],s12=S[1][2],s13=S[1][3];
    float s20=S[2][0],s21=S[2][1],s22=S[2][2],s23=S[2][3];
    float s30=S[3][0],s31=S[3][1],s32=S[3][2],s33=S[3][3];
    float r0 = 1.f/rs[0], r1 = 1.f/rs[1], r2 = 1.f/rs[2], r3 = 1.f/rs[3];

    size_t cbase = (size_t)s*4096 + (size_t)h*2048;
    for (int d = tid; d < DEPTH; d += 256) {
        float v0 = V[(size_t)((0*SEQ + s)*HEADS + h)*DEPTH + d];
        float v1 = V[(size_t)((1*SEQ + s)*HEADS + h)*DEPTH + d];
        float v2 = V[(size_t)((2*SEQ + s)*HEADS + h)*DEPTH + d];
        float v3 = V[(size_t)((3*SEQ + s)*HEADS + h)*DEPTH + d];
        C[cbase + 0*512 + d] = (s00*v0 + s01*v1 + s02*v2 + s03*v3) * r0;
        C[cbase + 1*512 + d] = (s10*v0 + s11*v1 + s12*v2 + s13*v3) * r1;
        C[cbase + 2*512 + d] = (s20*v0 + s21*v1 + s22*v2 + s23*v3) * r2;
        C[cbase + 3*512 + d] = (s30*v0 + s31*v1 + s32*v2 + s33*v3) * r3;
    }
}

// ---------------------------------------------------------------------------
// Launch
// ---------------------------------------------------------------------------
extern "C" void kernel_launch(void* const* d_in, const int* in_sizes, int n_in,
                              void* d_out, int out_size)
{
    const float* query = (const float*)d_in[0];
    const float* key   = (const float*)d_in[1];
    const float* value = (const float*)d_in[2];
    const float* Wq = (const float*)d_in[4];
    const float* bq = (const float*)d_in[5];
    const float* Wk = (const float*)d_in[6];
    const float* bk = (const float*)d_in[7];
    const float* Wv = (const float*)d_in[8];
    const float* bv = (const float*)d_in[9];
    const float* Wo = (const float*)d_in[10];
    const float* bo = (const float*)d_in[11];
    const float* feats = (const float*)d_in[12];   // [256, 512] == [N, K]
    float* out = (float*)d_out;

    float *Q, *K, *V, *dQ, *dK, *diagK, *rmaxK, *kmax, *C, *Wt;
    cudaGetSymbolAddress((void**)&Q,     g_Q);
    cudaGetSymbolAddress((void**)&K,     g_K);
    cudaGetSymbolAddress((void**)&V,     g_V);
    cudaGetSymbolAddress((void**)&dQ,    g_dQ);
    cudaGetSymbolAddress((void**)&dK,    g_dK);
    cudaGetSymbolAddress((void**)&diagK, g_diagK);
    cudaGetSymbolAddress((void**)&rmaxK, g_rmaxK);
    cudaGetSymbolAddress((void**)&kmax,  g_kmax);
    cudaGetSymbolAddress((void**)&C,     g_C);
    cudaGetSymbolAddress((void**)&Wt,    g_Wt);

    dim3 gT(DMODEL/32, DMODEL/32);
    dim3 gProj(DMODEL/128, ROWS/128);     // N tiles x M tiles
    dim3 gFeat(MFEAT/128, ROWS2/128);

    // 1-3: projections  Y = X @ W + b   (W pre-transposed to [N,K])
    transpose_kernel<<<gT, 256>>>(Wq, Wt, DMODEL, DMODEL);
    hgemm<<<gProj, 256>>>(query, Wt, bq, Q, ROWS, DMODEL, DMODEL, 1.f);
    transpose_kernel<<<gT, 256>>>(Wk, Wt, DMODEL, DMODEL);
    hgemm<<<gProj, 256>>>(key,   Wt, bk, K, ROWS, DMODEL, DMODEL, 1.f);
    transpose_kernel<<<gT, 256>>>(Wv, Wt, DMODEL, DMODEL);
    hgemm<<<gProj, 256>>>(value, Wt, bv, V, ROWS, DMODEL, DMODEL, 1.f);

    // 4-5: feature projections  dash = (scale*Y512) @ feats^T (feats is [N,K])
    hgemm<<<gFeat, 256>>>(Q, feats, nullptr, dQ, ROWS2, MFEAT, DEPTH, FSCALE);
    hgemm<<<gFeat, 256>>>(K, feats, nullptr, dK, ROWS2, MFEAT, DEPTH, FSCALE);

    // 6: q'
    qprime_kernel<<<ROWS2/8, 256>>>(Q, dQ);

    // 7-9: k'
    kstat_kernel<<<ROWS2/8, 256>>>(K, dK, diagK, rmaxK);
    kmax_kernel<<<BATCH*HEADS, 256>>>(rmaxK, kmax);
    {
        size_t total = (size_t)ROWS2 * MFEAT;
        kexp_kernel<<<(unsigned)((total + 255)/256), 256>>>(dK, diagK, kmax);
    }

    // 10: attention mix
    attn_mix_kernel<<<SEQ*HEADS, 256>>>(dQ, dK, V, C);

    // 11: out = C @ Wo + bo
    transpose_kernel<<<gT, 256>>>(Wo, Wt, DMODEL, DMODEL);
    hgemm<<<gProj, 256>>>(C, Wt, bo, out, ROWS, DMODEL, DMODEL, 1.f);
}

// round 6
// speedup vs baseline: 1.9307x; 1.5387x over previous
#include <cuda_runtime.h>
#include <cuda_fp16.h>
#include <math.h>
#include <stdint.h>

// ---------------------------------------------------------------------------
// Problem constants
// ---------------------------------------------------------------------------
#define BATCH     4
#define SEQ       4096
#define DMODEL    1024
#define HEADS     2
#define DEPTH     512
#define MFEAT     256
#define ROWS      (BATCH*SEQ)          // 16384
#define ROWS2     (ROWS*HEADS)         // 32768

#define SCALE2    0.044194173824159216f   // 1/sqrt(512)
#define FSCALE    0.21022410381342864f    // 512^{-0.25}
#define RATIO     0.0625f                 // 1/sqrt(256)
#define EPS       1e-6f

// ---------------------------------------------------------------------------
// Scratch (device globals; allocation is banned)
// ---------------------------------------------------------------------------
__device__ float  g_Q [ (size_t)ROWS * DMODEL ];
__device__ float  g_K [ (size_t)ROWS * DMODEL ];
__device__ float  g_V [ (size_t)ROWS * DMODEL ];
__device__ float  g_dQ[ (size_t)ROWS2 * MFEAT ];
__device__ float  g_dK[ (size_t)ROWS2 * MFEAT ];
__device__ float  g_diagK[ ROWS2 ];
__device__ float  g_rmaxK[ ROWS2 ];
__device__ float  g_kmax [ BATCH*HEADS ];
__device__ __half g_Ah [ (size_t)ROWS * DMODEL ];    // fp16 input mirror (reused)
__device__ __half g_Qh [ (size_t)ROWS * DMODEL ];    // fp16 Q mirror
__device__ __half g_Kh [ (size_t)ROWS * DMODEL ];    // fp16 K mirror
__device__ __half g_Wth[ (size_t)DMODEL * DMODEL ];  // fp16 transposed weight (reused)
__device__ __half g_fh [ (size_t)MFEAT * DEPTH ];    // fp16 feats
__device__ __half g_Ch [ (size_t)ROWS * DMODEL ];    // fp16 concat

// ---------------------------------------------------------------------------
// helpers
// ---------------------------------------------------------------------------
__device__ __forceinline__ uint32_t smem_u32(const void* p) {
    uint32_t a;
    asm("{ .reg .u64 t; cvta.to.shared.u64 t, %1; cvt.u32.u64 %0, t; }"
        : "=r"(a) : "l"(p));
    return a;
}

__device__ __forceinline__ void ldsm_x4(uint32_t& r0, uint32_t& r1,
                                        uint32_t& r2, uint32_t& r3, uint32_t addr) {
    asm volatile("ldmatrix.sync.aligned.m8n8.x4.shared.b16 {%0,%1,%2,%3}, [%4];"
                 : "=r"(r0), "=r"(r1), "=r"(r2), "=r"(r3) : "r"(addr));
}

__device__ __forceinline__ void mma_f16(float c[4], const uint32_t a[4],
                                        const uint32_t b[2]) {
    asm volatile(
        "mma.sync.aligned.m16n8k16.row.col.f32.f16.f16.f32 "
        "{%0,%1,%2,%3}, {%4,%5,%6,%7}, {%8,%9}, {%0,%1,%2,%3};"
        : "+f"(c[0]), "+f"(c[1]), "+f"(c[2]), "+f"(c[3])
        : "r"(a[0]), "r"(a[1]), "r"(a[2]), "r"(a[3]),
          "r"(b[0]), "r"(b[1]));
}

__device__ __forceinline__ void cp_async16(uint32_t smem, const void* gmem) {
    asm volatile("cp.async.cg.shared.global [%0], [%1], 16;"
                 :: "r"(smem), "l"(gmem) : "memory");
}
#define CP_COMMIT()  asm volatile("cp.async.commit_group;" ::: "memory")
#define CP_WAIT2()   asm volatile("cp.async.wait_group 2;" ::: "memory")

// ---------------------------------------------------------------------------
// fp16 GEMM (fp32 accumulate):  C = alpha * A(M,K) @ Bop(N,K)^T (+ bias)
//   A, Bop fp16; cp.async 4-stage pipeline; CTA 128x128, K-step 32, 8 warps.
//   Optional fp16 mirror output Ch. Requires M%128, N%128, K%32 == 0, K>=128.
// ---------------------------------------------------------------------------
#define ASTR   40                       // halves per row: 32 + 8 pad (80B)
#define STG    (128*ASTR)               // halves per operand tile (5120)
#define NSTAGE 4
#define HSMEM  (NSTAGE * 2 * STG * 2)   // bytes = 81920

__global__ __launch_bounds__(256)
void hgemm(const __half* __restrict__ A, const __half* __restrict__ Bop,
           const float* __restrict__ bias, float* __restrict__ C,
           __half* __restrict__ Ch, int M, int N, int K, float alpha)
{
    extern __shared__ __half sm[];

    const int tid  = threadIdx.x;
    const int lane = tid & 31;
    const int wid  = tid >> 5;
    const int bm = blockIdx.y * 128;
    const int bn = blockIdx.x * 128;

    const int warp_m = (wid & 1) * 64;
    const int warp_n = (wid >> 1) * 32;
    const int lr = lane >> 2;
    const int lc = lane & 3;

    // cp.async staging: thread covers chunks {tid, tid+256} of 512 per operand
    const int r0c = tid >> 2,          ch0 = (tid & 3);          // chunk tid
    const int r1c = (tid + 256) >> 2,  ch1 = ((tid + 256) & 3);  // chunk tid+256

    const uint32_t smb = smem_u32(sm);

    auto issue_stage = [&](int s, int k0) {
        const int slot = s & (NSTAGE - 1);
        const uint32_t abase = smb + (uint32_t)(slot * 2 * STG) * 2;
        const uint32_t bbase = abase + (uint32_t)STG * 2;
        cp_async16(abase + (r0c * ASTR + ch0 * 8) * 2,
                   A + (size_t)(bm + r0c) * K + k0 + ch0 * 8);
        cp_async16(abase + (r1c * ASTR + ch1 * 8) * 2,
                   A + (size_t)(bm + r1c) * K + k0 + ch1 * 8);
        cp_async16(bbase + (r0c * ASTR + ch0 * 8) * 2,
                   Bop + (size_t)(bn + r0c) * K + k0 + ch0 * 8);
        cp_async16(bbase + (r1c * ASTR + ch1 * 8) * 2,
                   Bop + (size_t)(bn + r1c) * K + k0 + ch1 * 8);
        CP_COMMIT();
    };

    float acc[4][4][4];
    #pragma unroll
    for (int i = 0; i < 4; i++)
        #pragma unroll
        for (int j = 0; j < 4; j++)
            #pragma unroll
            for (int r = 0; r < 4; r++) acc[i][j][r] = 0.f;

    // ldmatrix lane addressing
    const int a_lrow = (lane & 7) + ((lane >> 3) & 1) * 8;
    const int a_lcol = (lane >> 4) * 8;
    const int b_lrow = (lane & 7) + (lane >= 16 ? 8 : 0);
    const int b_lcol = ((lane >> 3) & 1) * 8;

    const int nst = K >> 5;
    issue_stage(0, 0);
    issue_stage(1, 32);
    issue_stage(2, 64);

    for (int s = 0; s < nst; s++) {
        CP_WAIT2();
        __syncthreads();

        const int slot = s & (NSTAGE - 1);
        const __half* As = sm + slot * 2 * STG;
        const __half* Bs = As + STG;

        #pragma unroll
        for (int kk = 0; kk < 32; kk += 16) {
            uint32_t a[4][4], b[4][2];
            #pragma unroll
            for (int mi = 0; mi < 4; mi++) {
                uint32_t addr = smem_u32(
                    &As[(warp_m + mi * 16 + a_lrow) * ASTR + kk + a_lcol]);
                ldsm_x4(a[mi][0], a[mi][1], a[mi][2], a[mi][3], addr);
            }
            #pragma unroll
            for (int nj = 0; nj < 2; nj++) {
                uint32_t addr = smem_u32(
                    &Bs[(warp_n + nj * 16 + b_lrow) * ASTR + kk + b_lcol]);
                ldsm_x4(b[2*nj][0], b[2*nj][1], b[2*nj+1][0], b[2*nj+1][1], addr);
            }
            #pragma unroll
            for (int mi = 0; mi < 4; mi++)
                #pragma unroll
                for (int ni = 0; ni < 4; ni++)
                    mma_f16(acc[mi][ni], a[mi], b[ni]);
        }
        __syncthreads();   // all warps done with slot before it is overwritten

        if (s + 3 < nst) issue_stage(s + 3, (s + 3) << 5);
        else             CP_COMMIT();     // keep group counting aligned
    }

    // epilogue
    #pragma unroll
    for (int mi = 0; mi < 4; mi++) {
        #pragma unroll
        for (int ni = 0; ni < 4; ni++) {
            int row = bm + warp_m + mi * 16 + lr;
            int col = bn + warp_n + ni * 8 + 2 * lc;
            float b0 = bias ? bias[col]     : 0.f;
            float b1 = bias ? bias[col + 1] : 0.f;
            float2 v0 = make_float2(alpha * acc[mi][ni][0] + b0,
                                    alpha * acc[mi][ni][1] + b1);
            float2 v1 = make_float2(alpha * acc[mi][ni][2] + b0,
                                    alpha * acc[mi][ni][3] + b1);
            *reinterpret_cast<float2*>(&C[(size_t)row * N + col])       = v0;
            *reinterpret_cast<float2*>(&C[(size_t)(row + 8) * N + col]) = v1;
            if (Ch) {
                *reinterpret_cast<__half2*>(&Ch[(size_t)row * N + col]) =
                    __floats2half2_rn(v0.x, v0.y);
                *reinterpret_cast<__half2*>(&Ch[(size_t)(row + 8) * N + col]) =
                    __floats2half2_rn(v1.x, v1.y);
            }
        }
    }
}

// ---------------------------------------------------------------------------
// f32 -> fp16 elementwise convert (n % 8 == 0)
// ---------------------------------------------------------------------------
__global__ __launch_bounds__(256)
void f2h_kernel(const float* __restrict__ in, __half* __restrict__ out, size_t n)
{
    size_t i = ((size_t)blockIdx.x * blockDim.x + threadIdx.x) * 8;
    if (i >= n) return;
    float4 v0 = *reinterpret_cast<const float4*>(in + i);
    float4 v1 = *reinterpret_cast<const float4*>(in + i + 4);
    __half h[8];
    h[0]=__float2half_rn(v0.x); h[1]=__float2half_rn(v0.y);
    h[2]=__float2half_rn(v0.z); h[3]=__float2half_rn(v0.w);
    h[4]=__float2half_rn(v1.x); h[5]=__float2half_rn(v1.y);
    h[6]=__float2half_rn(v1.z); h[7]=__float2half_rn(v1.w);
    *reinterpret_cast<uint4*>(out + i) = *reinterpret_cast<uint4*>(h);
}

// ---------------------------------------------------------------------------
// transpose + convert: in f32 [R][Cin]  ->  out fp16 [Cin][R]
// ---------------------------------------------------------------------------
__global__ __launch_bounds__(256)
void tconv_kernel(const float* __restrict__ in, __half* __restrict__ out,
                  int R, int Cin)
{
    __shared__ float tile[32][33];
    int bx = blockIdx.x * 32;
    int by = blockIdx.y * 32;
    int tx = threadIdx.x & 31;
    int ty = threadIdx.x >> 5;
    #pragma unroll
    for (int i = 0; i < 32; i += 8)
        tile[ty + i][tx] = in[(size_t)(by + ty + i) * Cin + bx + tx];
    __syncthreads();
    #pragma unroll
    for (int i = 0; i < 32; i += 8)
        out[(size_t)(bx + ty + i) * R + by + tx] = __float2half_rn(tile[tx][ty + i]);
}

// ---------------------------------------------------------------------------
// q' : per row diag from Y row, row-max of dash row, exp (in place)
// ---------------------------------------------------------------------------
__global__ __launch_bounds__(256)
void qprime_kernel(const float* __restrict__ Y, float* __restrict__ dash)
{
    int warp = (blockIdx.x * blockDim.x + threadIdx.x) >> 5;
    int lane = threadIdx.x & 31;
    if (warp >= ROWS2) return;

    const float* y = Y + (size_t)warp * DEPTH;
    float ss = 0.f;
    #pragma unroll
    for (int i = 0; i < DEPTH/32; i++) { float v = y[lane + 32*i]; ss += v*v; }
    #pragma unroll
    for (int off = 16; off; off >>= 1) ss += __shfl_xor_sync(0xffffffff, ss, off);
    float diag = 0.5f * SCALE2 * ss;

    float* dr = dash + (size_t)warp * MFEAT;
    float vals[MFEAT/32];
    float mx = -1e30f;
    #pragma unroll
    for (int i = 0; i < MFEAT/32; i++) { vals[i] = dr[lane + 32*i]; mx = fmaxf(mx, vals[i]); }
    #pragma unroll
    for (int off = 16; off; off >>= 1) mx = fmaxf(mx, __shfl_xor_sync(0xffffffff, mx, off));

    #pragma unroll
    for (int i = 0; i < MFEAT/32; i++)
        dr[lane + 32*i] = RATIO * (expf(vals[i] - diag - mx) + EPS);
}

// ---------------------------------------------------------------------------
// k path step 1: per-row diag + per-row max
// ---------------------------------------------------------------------------
__global__ __launch_bounds__(256)
void kstat_kernel(const float* __restrict__ Y, const float* __restrict__ dash,
                  float* __restrict__ diagK, float* __restrict__ rmaxK)
{
    int warp = (blockIdx.x * blockDim.x + threadIdx.x) >> 5;
    int lane = threadIdx.x & 31;
    if (warp >= ROWS2) return;

    const float* y = Y + (size_t)warp * DEPTH;
    float ss = 0.f;
    #pragma unroll
    for (int i = 0; i < DEPTH/32; i++) { float v = y[lane + 32*i]; ss += v*v; }
    #pragma unroll
    for (int off = 16; off; off >>= 1) ss += __shfl_xor_sync(0xffffffff, ss, off);

    const float* dr = dash + (size_t)warp * MFEAT;
    float mx = -1e30f;
    #pragma unroll
    for (int i = 0; i < MFEAT/32; i++) mx = fmaxf(mx, dr[lane + 32*i]);
    #pragma unroll
    for (int off = 16; off; off >>= 1) mx = fmaxf(mx, __shfl_xor_sync(0xffffffff, mx, off));

    if (lane == 0) { diagK[warp] = 0.5f * SCALE2 * ss; rmaxK[warp] = mx; }
}

// k path step 2
__global__ __launch_bounds__(256)
void kmax_kernel(const float* __restrict__ rmaxK, float* __restrict__ kmax)
{
    int bh = blockIdx.x;
    int b  = bh >> 1, h = bh & 1;
    __shared__ float sm[256];
    float mx = -1e30f;
    for (int l = threadIdx.x; l < SEQ; l += 256)
        mx = fmaxf(mx, rmaxK[b*8192 + l*2 + h]);
    sm[threadIdx.x] = mx;
    __syncthreads();
    for (int s = 128; s; s >>= 1) {
        if (threadIdx.x < s) sm[threadIdx.x] = fmaxf(sm[threadIdx.x], sm[threadIdx.x + s]);
        __syncthreads();
    }
    if (threadIdx.x == 0) kmax[bh] = sm[0];
}

// k path step 3
__global__ __launch_bounds__(256)
void kexp_kernel(float* __restrict__ dash, const float* __restrict__ diagK,
                 const float* __restrict__ kmax)
{
    size_t idx = (size_t)blockIdx.x * blockDim.x + threadIdx.x;
    size_t total = (size_t)ROWS2 * MFEAT;
    if (idx >= total) return;
    int r = (int)(idx >> 8);
    int b = r >> 13;
    int h = r & 1;
    float v = dash[idx];
    dash[idx] = RATIO * (expf(v - diagK[r] - kmax[b*2 + h]) + EPS);
}

// ---------------------------------------------------------------------------
// Attention mix: per (s,h) block; 4x4 batch mix, scrambled concat store (fp16)
// ---------------------------------------------------------------------------
__global__ __launch_bounds__(256)
void attn_mix_kernel(const float* __restrict__ QP, const float* __restrict__ KP,
                     const float* __restrict__ V, __half* __restrict__ C)
{
    int blk = blockIdx.x;
    int s = blk >> 1, h = blk & 1;
    __shared__ float q_s[4][MFEAT];
    __shared__ float k_s[4][MFEAT];
    __shared__ float S[4][4];
    __shared__ float rs[4];
    int tid = threadIdx.x;

    #pragma unroll
    for (int bb = 0; bb < 4; bb++) {
        size_t r = (size_t)((bb*SEQ + s)*HEADS + h);
        q_s[bb][tid] = QP[r*MFEAT + tid];
        k_s[bb][tid] = KP[r*MFEAT + tid];
    }
    __syncthreads();

    int p = tid >> 4, lane16 = tid & 15;
    int bb = p >> 2, bp = p & 3;
    float acc = 0.f;
    #pragma unroll
    for (int m = 0; m < MFEAT; m += 16) acc += q_s[bb][m + lane16] * k_s[bp][m + lane16];
    #pragma unroll
    for (int off = 8; off; off >>= 1) acc += __shfl_down_sync(0xffffffff, acc, off, 16);
    if (lane16 == 0) S[bb][bp] = acc;
    __syncthreads();
    if (tid < 4) rs[tid] = S[tid][0] + S[tid][1] + S[tid][2] + S[tid][3];
    __syncthreads();

    float s00=S[0][0],s01=S[0][1],s02=S[0][2],s03=S[0][3];
    float s10=S[1][0],s11=S[1][1],s12=S[1][2],s13=S[1][3];
    float s20=S[2][0],s21=S[2][1],s22=S[2][2],s23=S[2][3];
    float s30=S[3][0],s31=S[3][1],s32=S[3][2],s33=S[3][3];
    float r0 = 1.f/rs[0], r1 = 1.f/rs[1], r2 = 1.f/rs[2], r3 = 1.f/rs[3];

    size_t cbase = (size_t)s*4096 + (size_t)h*2048;
    for (int d = tid; d < DEPTH; d += 256) {
        float v0 = V[(size_t)((0*SEQ + s)*HEADS + h)*DEPTH + d];
        float v1 = V[(size_t)((1*SEQ + s)*HEADS + h)*DEPTH + d];
        float v2 = V[(size_t)((2*SEQ + s)*HEADS + h)*DEPTH + d];
        float v3 = V[(size_t)((3*SEQ + s)*HEADS + h)*DEPTH + d];
        C[cbase + 0*512 + d] = __float2half_rn((s00*v0 + s01*v1 + s02*v2 + s03*v3) * r0);
        C[cbase + 1*512 + d] = __float2half_rn((s10*v0 + s11*v1 + s12*v2 + s13*v3) * r1);
        C[cbase + 2*512 + d] = __float2half_rn((s20*v0 + s21*v1 + s22*v2 + s23*v3) * r2);
        C[cbase + 3*512 + d] = __float2half_rn((s30*v0 + s31*v1 + s32*v2 + s33*v3) * r3);
    }
}

// ---------------------------------------------------------------------------
// Launch
// ---------------------------------------------------------------------------
extern "C" void kernel_launch(void* const* d_in, const int* in_sizes, int n_in,
                              void* d_out, int out_size)
{
    const float* query = (const float*)d_in[0];
    const float* key   = (const float*)d_in[1];
    const float* value = (const float*)d_in[2];
    const float* Wq = (const float*)d_in[4];
    const float* bq = (const float*)d_in[5];
    const float* Wk = (const float*)d_in[6];
    const float* bk = (const float*)d_in[7];
    const float* Wv = (const float*)d_in[8];
    const float* bv = (const float*)d_in[9];
    const float* Wo = (const float*)d_in[10];
    const float* bo = (const float*)d_in[11];
    const float* feats = (const float*)d_in[12];   // [256, 512] == [N, K]
    float* out = (float*)d_out;

    float *Q, *K, *V, *dQ, *dK, *diagK, *rmaxK, *kmax;
    __half *Ah, *Qh, *Kh, *Wth, *fh, *Ch;
    cudaGetSymbolAddress((void**)&Q,     g_Q);
    cudaGetSymbolAddress((void**)&K,     g_K);
    cudaGetSymbolAddress((void**)&V,     g_V);
    cudaGetSymbolAddress((void**)&dQ,    g_dQ);
    cudaGetSymbolAddress((void**)&dK,    g_dK);
    cudaGetSymbolAddress((void**)&diagK, g_diagK);
    cudaGetSymbolAddress((void**)&rmaxK, g_rmaxK);
    cudaGetSymbolAddress((void**)&kmax,  g_kmax);
    cudaGetSymbolAddress((void**)&Ah,    g_Ah);
    cudaGetSymbolAddress((void**)&Qh,    g_Qh);
    cudaGetSymbolAddress((void**)&Kh,    g_Kh);
    cudaGetSymbolAddress((void**)&Wth,   g_Wth);
    cudaGetSymbolAddress((void**)&fh,    g_fh);
    cudaGetSymbolAddress((void**)&Ch,    g_Ch);

    cudaFuncSetAttribute(hgemm, cudaFuncAttributeMaxDynamicSharedMemorySize, HSMEM);

    dim3 gT(DMODEL/32, DMODEL/32);
    dim3 gProj(DMODEL/128, ROWS/128);
    dim3 gFeat(MFEAT/128, ROWS2/128);
    const size_t NELEM = (size_t)ROWS * DMODEL;
    const unsigned gConv = (unsigned)((NELEM/8 + 255) / 256);

    // feats fp16 (once)
    f2h_kernel<<<(unsigned)((MFEAT*DEPTH/8 + 255)/256), 256>>>(feats, fh, MFEAT*DEPTH);

    // 1-3: projections  Y = X @ W + b   (X, W^T pre-converted fp16)
    f2h_kernel<<<gConv, 256>>>(query, Ah, NELEM);
    tconv_kernel<<<gT, 256>>>(Wq, Wth, DMODEL, DMODEL);
    hgemm<<<gProj, 256, HSMEM>>>(Ah, Wth, bq, Q, Qh, ROWS, DMODEL, DMODEL, 1.f);

    f2h_kernel<<<gConv, 256>>>(key, Ah, NELEM);
    tconv_kernel<<<gT, 256>>>(Wk, Wth, DMODEL, DMODEL);
    hgemm<<<gProj, 256, HSMEM>>>(Ah, Wth, bk, K, Kh, ROWS, DMODEL, DMODEL, 1.f);

    f2h_kernel<<<gConv, 256>>>(value, Ah, NELEM);
    tconv_kernel<<<gT, 256>>>(Wv, Wth, DMODEL, DMODEL);
    hgemm<<<gProj, 256, HSMEM>>>(Ah, Wth, bv, V, nullptr, ROWS, DMODEL, DMODEL, 1.f);

    // 4-5: feature projections  dash = (scale*Y512) @ feats^T
    hgemm<<<gFeat, 256, HSMEM>>>(Qh, fh, nullptr, dQ, nullptr, ROWS2, MFEAT, DEPTH, FSCALE);
    hgemm<<<gFeat, 256, HSMEM>>>(Kh, fh, nullptr, dK, nullptr, ROWS2, MFEAT, DEPTH, FSCALE);

    // 6: q'
    qprime_kernel<<<ROWS2/8, 256>>>(Q, dQ);

    // 7-9: k'
    kstat_kernel<<<ROWS2/8, 256>>>(K, dK, diagK, rmaxK);
    kmax_kernel<<<BATCH*HEADS, 256>>>(rmaxK, kmax);
    {
        size_t total = (size_t)ROWS2 * MFEAT;
        kexp_kernel<<<(unsigned)((total + 255)/256), 256>>>(dK, diagK, kmax);
    }

    // 10: attention mix -> fp16 concat
    attn_mix_kernel<<<SEQ*HEADS, 256>>>(dQ, dK, V, Ch);

    // 11: out = C @ Wo + bo
    tconv_kernel<<<gT, 256>>>(Wo, Wth, DMODEL, DMODEL);
    hgemm<<<gProj, 256, HSMEM>>>(Ch, Wth, bo, out, nullptr, ROWS, DMODEL, DMODEL, 1.f);
}

// round 7
// speedup vs baseline: 2.1741x; 1.1261x over previous
#include <cuda_runtime.h>
#include <cuda_fp16.h>
#include <math.h>
#include <stdint.h>

// ---------------------------------------------------------------------------
// Problem constants
// ---------------------------------------------------------------------------
#define BATCH     4
#define SEQ       4096
#define DMODEL    1024
#define HEADS     2
#define DEPTH     512
#define MFEAT     256
#define ROWS      (BATCH*SEQ)          // 16384
#define ROWS2     (ROWS*HEADS)         // 32768

#define SCALE2    0.044194173824159216f   // 1/sqrt(512)
#define FSCALE    0.21022410381342864f    // 512^{-0.25}
#define RATIO     0.0625f                 // 1/sqrt(256)
#define EPS       1e-6f

// ---------------------------------------------------------------------------
// Scratch (device globals; allocation is banned)
// ---------------------------------------------------------------------------
__device__ float  g_Q [ (size_t)ROWS * DMODEL ];
__device__ float  g_K [ (size_t)ROWS * DMODEL ];
__device__ float  g_V [ (size_t)ROWS * DMODEL ];
__device__ float  g_dQ[ (size_t)ROWS2 * MFEAT ];
__device__ float  g_dK[ (size_t)ROWS2 * MFEAT ];
__device__ float  g_diagK[ ROWS2 ];
__device__ float  g_rmaxK[ ROWS2 ];
__device__ float  g_kmax [ BATCH*HEADS ];
__device__ __half g_Ah [ (size_t)ROWS * DMODEL ];    // fp16 input mirror (reused)
__device__ __half g_Qh [ (size_t)ROWS * DMODEL ];    // fp16 Q mirror
__device__ __half g_Kh [ (size_t)ROWS * DMODEL ];    // fp16 K mirror
__device__ __half g_Wth[ (size_t)DMODEL * DMODEL ];  // fp16 transposed weight (reused)
__device__ __half g_fh [ (size_t)MFEAT * DEPTH ];    // fp16 feats
__device__ __half g_Ch [ (size_t)ROWS * DMODEL ];    // fp16 concat

// ---------------------------------------------------------------------------
// helpers
// ---------------------------------------------------------------------------
__device__ __forceinline__ uint32_t smem_u32(const void* p) {
    uint32_t a;
    asm("{ .reg .u64 t; cvta.to.shared.u64 t, %1; cvt.u32.u64 %0, t; }"
        : "=r"(a) : "l"(p));
    return a;
}

__device__ __forceinline__ void ldsm_x4(uint32_t& r0, uint32_t& r1,
                                        uint32_t& r2, uint32_t& r3, uint32_t addr) {
    asm volatile("ldmatrix.sync.aligned.m8n8.x4.shared.b16 {%0,%1,%2,%3}, [%4];"
                 : "=r"(r0), "=r"(r1), "=r"(r2), "=r"(r3) : "r"(addr));
}

__device__ __forceinline__ void mma_f16(float c[4], const uint32_t a[4],
                                        const uint32_t b[2]) {
    asm volatile(
        "mma.sync.aligned.m16n8k16.row.col.f32.f16.f16.f32 "
        "{%0,%1,%2,%3}, {%4,%5,%6,%7}, {%8,%9}, {%0,%1,%2,%3};"
        : "+f"(c[0]), "+f"(c[1]), "+f"(c[2]), "+f"(c[3])
        : "r"(a[0]), "r"(a[1]), "r"(a[2]), "r"(a[3]),
          "r"(b[0]), "r"(b[1]));
}

__device__ __forceinline__ void cp_async16(uint32_t smem, const void* gmem) {
    asm volatile("cp.async.cg.shared.global [%0], [%1], 16;"
                 :: "r"(smem), "l"(gmem) : "memory");
}
#define CP_COMMIT()  asm volatile("cp.async.commit_group;" ::: "memory")
#define CP_WAIT1()   asm volatile("cp.async.wait_group 1;" ::: "memory")

// ---------------------------------------------------------------------------
// fp16 GEMM (fp32 accumulate):  C = alpha * A(M,K) @ Bop(N,K)^T (+ bias)
//   A, Bop fp16; cp.async 3-stage pipeline, ONE barrier per stage;
//   CTA 128x128, K-step 32, 8 warps (warp tile 64x32).
//   Optional fp16 mirror output Ch. Requires M%128, N%128, K%32 == 0, K>=96.
// ---------------------------------------------------------------------------
#define ASTR   40                       // halves per row: 32 + 8 pad (80B)
#define STG    (128*ASTR)               // halves per operand tile (5120)
#define NSTAGE 3
#define HSMEM  (NSTAGE * 2 * STG * 2)   // bytes = 61440

__global__ __launch_bounds__(256)
void hgemm(const __half* __restrict__ A, const __half* __restrict__ Bop,
           const float* __restrict__ bias, float* __restrict__ C,
           __half* __restrict__ Ch, int M, int N, int K, float alpha)
{
    extern __shared__ __half sm[];

    const int tid  = threadIdx.x;
    const int lane = tid & 31;
    const int wid  = tid >> 5;
    const int bm = blockIdx.y * 128;
    const int bn = blockIdx.x * 128;

    const int warp_m = (wid & 1) * 64;
    const int warp_n = (wid >> 1) * 32;
    const int lr = lane >> 2;
    const int lc = lane & 3;

    // cp.async staging: thread covers chunks {tid, tid+256} of 512 per operand
    const int r0c = tid >> 2,          ch0 = (tid & 3);
    const int r1c = (tid + 256) >> 2,  ch1 = ((tid + 256) & 3);

    const uint32_t smb = smem_u32(sm);

    auto issue_stage = [&](int s, int k0) {
        const int slot = s % NSTAGE;
        const uint32_t abase = smb + (uint32_t)(slot * 2 * STG) * 2;
        const uint32_t bbase = abase + (uint32_t)STG * 2;
        cp_async16(abase + (r0c * ASTR + ch0 * 8) * 2,
                   A + (size_t)(bm + r0c) * K + k0 + ch0 * 8);
        cp_async16(abase + (r1c * ASTR + ch1 * 8) * 2,
                   A + (size_t)(bm + r1c) * K + k0 + ch1 * 8);
        cp_async16(bbase + (r0c * ASTR + ch0 * 8) * 2,
                   Bop + (size_t)(bn + r0c) * K + k0 + ch0 * 8);
        cp_async16(bbase + (r1c * ASTR + ch1 * 8) * 2,
                   Bop + (size_t)(bn + r1c) * K + k0 + ch1 * 8);
        CP_COMMIT();
    };

    float acc[4][4][4];
    #pragma unroll
    for (int i = 0; i < 4; i++)
        #pragma unroll
        for (int j = 0; j < 4; j++)
            #pragma unroll
            for (int r = 0; r < 4; r++) acc[i][j][r] = 0.f;

    // ldmatrix lane addressing
    const int a_lrow = (lane & 7) + ((lane >> 3) & 1) * 8;
    const int a_lcol = (lane >> 4) * 8;
    const int b_lrow = (lane & 7) + (lane >= 16 ? 8 : 0);
    const int b_lcol = ((lane >> 3) & 1) * 8;

    const int nst = K >> 5;
    issue_stage(0, 0);
    issue_stage(1, 32);

    for (int s = 0; s < nst; s++) {
        CP_WAIT1();                      // stage s complete (s+1 may be in flight)
        __syncthreads();                 // also: all warps done reading slot (s-1)%3

        // slot (s+2)%3 == slot (s-1)%3 — safe to overwrite after the barrier
        if (s + 2 < nst) issue_stage(s + 2, (s + 2) << 5);
        else             CP_COMMIT();    // empty group keeps wait_group counting exact

        const int slot = s % NSTAGE;
        const __half* As = sm + slot * 2 * STG;
        const __half* Bs = As + STG;

        #pragma unroll
        for (int kk = 0; kk < 32; kk += 16) {
            uint32_t a[4][4], b[4][2];
            #pragma unroll
            for (int mi = 0; mi < 4; mi++) {
                uint32_t addr = smem_u32(
                    &As[(warp_m + mi * 16 + a_lrow) * ASTR + kk + a_lcol]);
                ldsm_x4(a[mi][0], a[mi][1], a[mi][2], a[mi][3], addr);
            }
            #pragma unroll
            for (int nj = 0; nj < 2; nj++) {
                uint32_t addr = smem_u32(
                    &Bs[(warp_n + nj * 16 + b_lrow) * ASTR + kk + b_lcol]);
                ldsm_x4(b[2*nj][0], b[2*nj][1], b[2*nj+1][0], b[2*nj+1][1], addr);
            }
            #pragma unroll
            for (int mi = 0; mi < 4; mi++)
                #pragma unroll
                for (int ni = 0; ni < 4; ni++)
                    mma_f16(acc[mi][ni], a[mi], b[ni]);
        }
    }

    // epilogue
    #pragma unroll
    for (int mi = 0; mi < 4; mi++) {
        #pragma unroll
        for (int ni = 0; ni < 4; ni++) {
            int row = bm + warp_m + mi * 16 + lr;
            int col = bn + warp_n + ni * 8 + 2 * lc;
            float b0 = bias ? bias[col]     : 0.f;
            float b1 = bias ? bias[col + 1] : 0.f;
            float2 v0 = make_float2(alpha * acc[mi][ni][0] + b0,
                                    alpha * acc[mi][ni][1] + b1);
            float2 v1 = make_float2(alpha * acc[mi][ni][2] + b0,
                                    alpha * acc[mi][ni][3] + b1);
            *reinterpret_cast<float2*>(&C[(size_t)row * N + col])       = v0;
            *reinterpret_cast<float2*>(&C[(size_t)(row + 8) * N + col]) = v1;
            if (Ch) {
                *reinterpret_cast<__half2*>(&Ch[(size_t)row * N + col]) =
                    __floats2half2_rn(v0.x, v0.y);
                *reinterpret_cast<__half2*>(&Ch[(size_t)(row + 8) * N + col]) =
                    __floats2half2_rn(v1.x, v1.y);
            }
        }
    }
}

// ---------------------------------------------------------------------------
// f32 -> fp16 elementwise convert (n % 8 == 0)
// ---------------------------------------------------------------------------
__global__ __launch_bounds__(256)
void f2h_kernel(const float* __restrict__ in, __half* __restrict__ out, size_t n)
{
    size_t i = ((size_t)blockIdx.x * blockDim.x + threadIdx.x) * 8;
    if (i >= n) return;
    float4 v0 = *reinterpret_cast<const float4*>(in + i);
    float4 v1 = *reinterpret_cast<const float4*>(in + i + 4);
    __half h[8];
    h[0]=__float2half_rn(v0.x); h[1]=__float2half_rn(v0.y);
    h[2]=__float2half_rn(v0.z); h[3]=__float2half_rn(v0.w);
    h[4]=__float2half_rn(v1.x); h[5]=__float2half_rn(v1.y);
    h[6]=__float2half_rn(v1.z); h[7]=__float2half_rn(v1.w);
    *reinterpret_cast<uint4*>(out + i) = *reinterpret_cast<uint4*>(h);
}

// ---------------------------------------------------------------------------
// transpose + convert: in f32 [R][Cin]  ->  out fp16 [Cin][R]
// ---------------------------------------------------------------------------
__global__ __launch_bounds__(256)
void tconv_kernel(const float* __restrict__ in, __half* __restrict__ out,
                  int R, int Cin)
{
    __shared__ float tile[32][33];
    int bx = blockIdx.x * 32;
    int by = blockIdx.y * 32;
    int tx = threadIdx.x & 31;
    int ty = threadIdx.x >> 5;
    #pragma unroll
    for (int i = 0; i < 32; i += 8)
        tile[ty + i][tx] = in[(size_t)(by + ty + i) * Cin + bx + tx];
    __syncthreads();
    #pragma unroll
    for (int i = 0; i < 32; i += 8)
        out[(size_t)(bx + ty + i) * R + by + tx] = __float2half_rn(tile[tx][ty + i]);
}

// ---------------------------------------------------------------------------
// q' : per row diag from Y row, row-max of dash row, exp (in place)
// ---------------------------------------------------------------------------
__global__ __launch_bounds__(256)
void qprime_kernel(const float* __restrict__ Y, float* __restrict__ dash)
{
    int warp = (blockIdx.x * blockDim.x + threadIdx.x) >> 5;
    int lane = threadIdx.x & 31;
    if (warp >= ROWS2) return;

    const float* y = Y + (size_t)warp * DEPTH;
    float ss = 0.f;
    #pragma unroll
    for (int i = 0; i < DEPTH/32; i++) { float v = y[lane + 32*i]; ss += v*v; }
    #pragma unroll
    for (int off = 16; off; off >>= 1) ss += __shfl_xor_sync(0xffffffff, ss, off);
    float diag = 0.5f * SCALE2 * ss;

    float* dr = dash + (size_t)warp * MFEAT;
    float vals[MFEAT/32];
    float mx = -1e30f;
    #pragma unroll
    for (int i = 0; i < MFEAT/32; i++) { vals[i] = dr[lane + 32*i]; mx = fmaxf(mx, vals[i]); }
    #pragma unroll
    for (int off = 16; off; off >>= 1) mx = fmaxf(mx, __shfl_xor_sync(0xffffffff, mx, off));

    #pragma unroll
    for (int i = 0; i < MFEAT/32; i++)
        dr[lane + 32*i] = RATIO * (expf(vals[i] - diag - mx) + EPS);
}

// ---------------------------------------------------------------------------
// k path step 1: per-row diag + per-row max
// ---------------------------------------------------------------------------
__global__ __launch_bounds__(256)
void kstat_kernel(const float* __restrict__ Y, const float* __restrict__ dash,
                  float* __restrict__ diagK, float* __restrict__ rmaxK)
{
    int warp = (blockIdx.x * blockDim.x + threadIdx.x) >> 5;
    int lane = threadIdx.x & 31;
    if (warp >= ROWS2) return;

    const float* y = Y + (size_t)warp * DEPTH;
    float ss = 0.f;
    #pragma unroll
    for (int i = 0; i < DEPTH/32; i++) { float v = y[lane + 32*i]; ss += v*v; }
    #pragma unroll
    for (int off = 16; off; off >>= 1) ss += __shfl_xor_sync(0xffffffff, ss, off);

    const float* dr = dash + (size_t)warp * MFEAT;
    float mx = -1e30f;
    #pragma unroll
    for (int i = 0; i < MFEAT/32; i++) mx = fmaxf(mx, dr[lane + 32*i]);
    #pragma unroll
    for (int off = 16; off; off >>= 1) mx = fmaxf(mx, __shfl_xor_sync(0xffffffff, mx, off));

    if (lane == 0) { diagK[warp] = 0.5f * SCALE2 * ss; rmaxK[warp] = mx; }
}

// k path step 2
__global__ __launch_bounds__(256)
void kmax_kernel(const float* __restrict__ rmaxK, float* __restrict__ kmax)
{
    int bh = blockIdx.x;
    int b  = bh >> 1, h = bh & 1;
    __shared__ float sm[256];
    float mx = -1e30f;
    for (int l = threadIdx.x; l < SEQ; l += 256)
        mx = fmaxf(mx, rmaxK[b*8192 + l*2 + h]);
    sm[threadIdx.x] = mx;
    __syncthreads();
    for (int s = 128; s; s >>= 1) {
        if (threadIdx.x < s) sm[threadIdx.x] = fmaxf(sm[threadIdx.x], sm[threadIdx.x + s]);
        __syncthreads();
    }
    if (threadIdx.x == 0) kmax[bh] = sm[0];
}

// k path step 3
__global__ __launch_bounds__(256)
void kexp_kernel(float* __restrict__ dash, const float* __restrict__ diagK,
                 const float* __restrict__ kmax)
{
    size_t idx = (size_t)blockIdx.x * blockDim.x + threadIdx.x;
    size_t total = (size_t)ROWS2 * MFEAT;
    if (idx >= total) return;
    int r = (int)(idx >> 8);
    int b = r >> 13;
    int h = r & 1;
    float v = dash[idx];
    dash[idx] = RATIO * (expf(v - diagK[r] - kmax[b*2 + h]) + EPS);
}

// ---------------------------------------------------------------------------
// Attention mix: per (s,h) block; 4x4 batch mix, scrambled concat store (fp16)
// ---------------------------------------------------------------------------
__global__ __launch_bounds__(256)
void attn_mix_kernel(const float* __restrict__ QP, const float* __restrict__ KP,
                     const float* __restrict__ V, __half* __restrict__ C)
{
    int blk = blockIdx.x;
    int s = blk >> 1, h = blk & 1;
    __shared__ float q_s[4][MFEAT];
    __shared__ float k_s[4][MFEAT];
    __shared__ float S[4][4];
    __shared__ float rs[4];
    int tid = threadIdx.x;

    #pragma unroll
    for (int bb = 0; bb < 4; bb++) {
        size_t r = (size_t)((bb*SEQ + s)*HEADS + h);
        q_s[bb][tid] = QP[r*MFEAT + tid];
        k_s[bb][tid] = KP[r*MFEAT + tid];
    }
    __syncthreads();

    int p = tid >> 4, lane16 = tid & 15;
    int bb = p >> 2, bp = p & 3;
    float acc = 0.f;
    #pragma unroll
    for (int m = 0; m < MFEAT; m += 16) acc += q_s[bb][m + lane16] * k_s[bp][m + lane16];
    #pragma unroll
    for (int off = 8; off; off >>= 1) acc += __shfl_down_sync(0xffffffff, acc, off, 16);
    if (lane16 == 0) S[bb][bp] = acc;
    __syncthreads();
    if (tid < 4) rs[tid] = S[tid][0] + S[tid][1] + S[tid][2] + S[tid][3];
    __syncthreads();

    float s00=S[0][0],s01=S[0][1],s02=S[0][2],s03=S[0][3];
    float s10=S[1][0],s11=S[1][1],s12=S[1][2],s13=S[1][3];
    float s20=S[2][0],s21=S[2][1],s22=S[2][2],s23=S[2][3];
    float s30=S[3][0],s31=S[3][1],s32=S[3][2],s33=S[3][3];
    float r0 = 1.f/rs[0], r1 = 1.f/rs[1], r2 = 1.f/rs[2], r3 = 1.f/rs[3];

    size_t cbase = (size_t)s*4096 + (size_t)h*2048;
    for (int d = tid; d < DEPTH; d += 256) {
        float v0 = V[(size_t)((0*SEQ + s)*HEADS + h)*DEPTH + d];
        float v1 = V[(size_t)((1*SEQ + s)*HEADS + h)*DEPTH + d];
        float v2 = V[(size_t)((2*SEQ + s)*HEADS + h)*DEPTH + d];
        float v3 = V[(size_t)((3*SEQ + s)*HEADS + h)*DEPTH + d];
        C[cbase + 0*512 + d] = __float2half_rn((s00*v0 + s01*v1 + s02*v2 + s03*v3) * r0);
        C[cbase + 1*512 + d] = __float2half_rn((s10*v0 + s11*v1 + s12*v2 + s13*v3) * r1);
        C[cbase + 2*512 + d] = __float2half_rn((s20*v0 + s21*v1 + s22*v2 + s23*v3) * r2);
        C[cbase + 3*512 + d] = __float2half_rn((s30*v0 + s31*v1 + s32*v2 + s33*v3) * r3);
    }
}

// ---------------------------------------------------------------------------
// Launch
// ---------------------------------------------------------------------------
extern "C" void kernel_launch(void* const* d_in, const int* in_sizes, int n_in,
                              void* d_out, int out_size)
{
    const float* query = (const float*)d_in[0];
    const float* key   = (const float*)d_in[1];
    const float* value = (const float*)d_in[2];
    const float* Wq = (const float*)d_in[4];
    const float* bq = (const float*)d_in[5];
    const float* Wk = (const float*)d_in[6];
    const float* bk = (const float*)d_in[7];
    const float* Wv = (const float*)d_in[8];
    const float* bv = (const float*)d_in[9];
    const float* Wo = (const float*)d_in[10];
    const float* bo = (const float*)d_in[11];
    const float* feats = (const float*)d_in[12];   // [256, 512] == [N, K]
    float* out = (float*)d_out;

    float *Q, *K, *V, *dQ, *dK, *diagK, *rmaxK, *kmax;
    __half *Ah, *Qh, *Kh, *Wth, *fh, *Ch;
    cudaGetSymbolAddress((void**)&Q,     g_Q);
    cudaGetSymbolAddress((void**)&K,     g_K);
    cudaGetSymbolAddress((void**)&V,     g_V);
    cudaGetSymbolAddress((void**)&dQ,    g_dQ);
    cudaGetSymbolAddress((void**)&dK,    g_dK);
    cudaGetSymbolAddress((void**)&diagK, g_diagK);
    cudaGetSymbolAddress((void**)&rmaxK, g_rmaxK);
    cudaGetSymbolAddress((void**)&kmax,  g_kmax);
    cudaGetSymbolAddress((void**)&Ah,    g_Ah);
    cudaGetSymbolAddress((void**)&Qh,    g_Qh);
    cudaGetSymbolAddress((void**)&Kh,    g_Kh);
    cudaGetSymbolAddress((void**)&Wth,   g_Wth);
    cudaGetSymbolAddress((void**)&fh,    g_fh);
    cudaGetSymbolAddress((void**)&Ch,    g_Ch);

    cudaFuncSetAttribute(hgemm, cudaFuncAttributeMaxDynamicSharedMemorySize, HSMEM);

    dim3 gT(DMODEL/32, DMODEL/32);
    dim3 gProj(DMODEL/128, ROWS/128);
    dim3 gFeat(MFEAT/128, ROWS2/128);
    const size_t NELEM = (size_t)ROWS * DMODEL;
    const unsigned gConv = (unsigned)((NELEM/8 + 255) / 256);

    // feats fp16 (once)
    f2h_kernel<<<(unsigned)((MFEAT*DEPTH/8 + 255)/256), 256>>>(feats, fh, MFEAT*DEPTH);

    // 1-3: projections  Y = X @ W + b   (X, W^T pre-converted fp16)
    f2h_kernel<<<gConv, 256>>>(query, Ah, NELEM);
    tconv_kernel<<<gT, 256>>>(Wq, Wth, DMODEL, DMODEL);
    hgemm<<<gProj, 256, HSMEM>>>(Ah, Wth, bq, Q, Qh, ROWS, DMODEL, DMODEL, 1.f);

    f2h_kernel<<<gConv, 256>>>(key, Ah, NELEM);
    tconv_kernel<<<gT, 256>>>(Wk, Wth, DMODEL, DMODEL);
    hgemm<<<gProj, 256, HSMEM>>>(Ah, Wth, bk, K, Kh, ROWS, DMODEL, DMODEL, 1.f);

    f2h_kernel<<<gConv, 256>>>(value, Ah, NELEM);
    tconv_kernel<<<gT, 256>>>(Wv, Wth, DMODEL, DMODEL);
    hgemm<<<gProj, 256, HSMEM>>>(Ah, Wth, bv, V, nullptr, ROWS, DMODEL, DMODEL, 1.f);

    // 4-5: feature projections  dash = (scale*Y512) @ feats^T
    hgemm<<<gFeat, 256, HSMEM>>>(Qh, fh, nullptr, dQ, nullptr, ROWS2, MFEAT, DEPTH, FSCALE);
    hgemm<<<gFeat, 256, HSMEM>>>(Kh, fh, nullptr, dK, nullptr, ROWS2, MFEAT, DEPTH, FSCALE);

    // 6: q'
    qprime_kernel<<<ROWS2/8, 256>>>(Q, dQ);

    // 7-9: k'
    kstat_kernel<<<ROWS2/8, 256>>>(K, dK, diagK, rmaxK);
    kmax_kernel<<<BATCH*HEADS, 256>>>(rmaxK, kmax);
    {
        size_t total = (size_t)ROWS2 * MFEAT;
        kexp_kernel<<<(unsigned)((total + 255)/256), 256>>>(dK, diagK, kmax);
    }

    // 10: attention mix -> fp16 concat
    attn_mix_kernel<<<SEQ*HEADS, 256>>>(dQ, dK, V, Ch);

    // 11: out = C @ Wo + bo
    tconv_kernel<<<gT, 256>>>(Wo, Wth, DMODEL, DMODEL);
    hgemm<<<gProj, 256, HSMEM>>>(Ch, Wth, bo, out, nullptr, ROWS, DMODEL, DMODEL, 1.f);
}

// round 8
// speedup vs baseline: 2.2894x; 1.0530x over previous
#include <cuda_runtime.h>
#include <cuda_fp16.h>
#include <math.h>
#include <stdint.h>

// ---------------------------------------------------------------------------
// Problem constants
// ---------------------------------------------------------------------------
#define BATCH     4
#define SEQ       4096
#define DMODEL    1024
#define HEADS     2
#define DEPTH     512
#define MFEAT     256
#define ROWS      (BATCH*SEQ)          // 16384
#define ROWS2     (ROWS*HEADS)         // 32768

#define SCALE2    0.044194173824159216f   // 1/sqrt(512)
#define FSCALE    0.21022410381342864f    // 512^{-0.25}
#define RATIO     0.0625f                 // 1/sqrt(256)
#define EPS       1e-6f

// ---------------------------------------------------------------------------
// Scratch (device globals; allocation is banned)
// ---------------------------------------------------------------------------
__device__ float  g_Q [ (size_t)ROWS * DMODEL ];
__device__ float  g_K [ (size_t)ROWS * DMODEL ];
__device__ float  g_V [ (size_t)ROWS * DMODEL ];
__device__ float  g_dQ[ (size_t)ROWS2 * MFEAT ];
__device__ float  g_dK[ (size_t)ROWS2 * MFEAT ];
__device__ float  g_diagK[ ROWS2 ];
__device__ float  g_rmaxK[ ROWS2 ];
__device__ float  g_kmax [ BATCH*HEADS ];
__device__ __half g_Ah [ (size_t)ROWS * DMODEL ];    // fp16 input mirror (reused)
__device__ __half g_Qh [ (size_t)ROWS * DMODEL ];    // fp16 Q mirror
__device__ __half g_Kh [ (size_t)ROWS * DMODEL ];    // fp16 K mirror
__device__ __half g_Wth[ (size_t)DMODEL * DMODEL ];  // fp16 transposed weight (reused)
__device__ __half g_fh [ (size_t)MFEAT * DEPTH ];    // fp16 feats
__device__ __half g_Ch [ (size_t)ROWS * DMODEL ];    // fp16 concat

// ---------------------------------------------------------------------------
// helpers
// ---------------------------------------------------------------------------
__device__ __forceinline__ uint32_t smem_u32(const void* p) {
    uint32_t a;
    asm("{ .reg .u64 t; cvta.to.shared.u64 t, %1; cvt.u32.u64 %0, t; }"
        : "=r"(a) : "l"(p));
    return a;
}

__device__ __forceinline__ void ldsm_x4(uint32_t& r0, uint32_t& r1,
                                        uint32_t& r2, uint32_t& r3, uint32_t addr) {
    asm volatile("ldmatrix.sync.aligned.m8n8.x4.shared.b16 {%0,%1,%2,%3}, [%4];"
                 : "=r"(r0), "=r"(r1), "=r"(r2), "=r"(r3) : "r"(addr));
}

__device__ __forceinline__ void mma_f16(float c[4], const uint32_t a[4],
                                        const uint32_t b[2]) {
    asm volatile(
        "mma.sync.aligned.m16n8k16.row.col.f32.f16.f16.f32 "
        "{%0,%1,%2,%3}, {%4,%5,%6,%7}, {%8,%9}, {%0,%1,%2,%3};"
        : "+f"(c[0]), "+f"(c[1]), "+f"(c[2]), "+f"(c[3])
        : "r"(a[0]), "r"(a[1]), "r"(a[2]), "r"(a[3]),
          "r"(b[0]), "r"(b[1]));
}

__device__ __forceinline__ void cp_async16(uint32_t smem, const void* gmem) {
    asm volatile("cp.async.cg.shared.global [%0], [%1], 16;"
                 :: "r"(smem), "l"(gmem) : "memory");
}
#define CP_COMMIT()  asm volatile("cp.async.commit_group;" ::: "memory")
#define CP_WAIT0()   asm volatile("cp.async.wait_group 0;" ::: "memory")

// ---------------------------------------------------------------------------
// fp16 GEMM (fp32 accumulate):  C = alpha * A(M,K) @ Bop(N,K)^T (+ bias)
//   A, Bop fp16; cp.async 2-stage pipeline w/ K-step 64, ONE barrier/stage;
//   A-fragment double buffering. CTA 128x128, 8 warps (warp tile 64x32).
//   Optional fp16 mirror output Ch. Requires M%128, N%128, K%64 == 0, K>=128.
// ---------------------------------------------------------------------------
#define ASTR   72                       // halves per row: 64 + 8 pad (144B)
#define STG    (128*ASTR)               // halves per operand tile (9216)
#define NSTAGE 2
#define HSMEM  (NSTAGE * 2 * STG * 2)   // bytes = 73728

__global__ __launch_bounds__(256)
void hgemm(const __half* __restrict__ A, const __half* __restrict__ Bop,
           const float* __restrict__ bias, float* __restrict__ C,
           __half* __restrict__ Ch, int M, int N, int K, float alpha)
{
    extern __shared__ __half sm[];

    const int tid  = threadIdx.x;
    const int lane = tid & 31;
    const int wid  = tid >> 5;
    const int bm = blockIdx.y * 128;
    const int bn = blockIdx.x * 128;

    const int warp_m = (wid & 1) * 64;
    const int warp_n = (wid >> 1) * 32;
    const int lr = lane >> 2;
    const int lc = lane & 3;

    const uint32_t smb = smem_u32(sm);

    // staging: 1024 16B-chunks per operand per stage; 4 per thread
    auto issue_stage = [&](int s, int k0) {
        const int slot = s & 1;
        const uint32_t abase = smb + (uint32_t)(slot * 2 * STG) * 2;
        const uint32_t bbase = abase + (uint32_t)STG * 2;
        #pragma unroll
        for (int c = 0; c < 4; c++) {
            int chunk = tid + 256 * c;       // 0..1023
            int row = chunk >> 3;            // 0..127
            int col = (chunk & 7) * 8;       // halves 0..56
            cp_async16(abase + (uint32_t)(row * ASTR + col) * 2,
                       A + (size_t)(bm + row) * K + k0 + col);
            cp_async16(bbase + (uint32_t)(row * ASTR + col) * 2,
                       Bop + (size_t)(bn + row) * K + k0 + col);
        }
        CP_COMMIT();
    };

    float acc[4][4][4];
    #pragma unroll
    for (int i = 0; i < 4; i++)
        #pragma unroll
        for (int j = 0; j < 4; j++)
            #pragma unroll
            for (int r = 0; r < 4; r++) acc[i][j][r] = 0.f;

    // ldmatrix lane addressing
    const int a_lrow = (lane & 7) + ((lane >> 3) & 1) * 8;
    const int a_lcol = (lane >> 4) * 8;
    const int b_lrow = (lane & 7) + (lane >= 16 ? 8 : 0);
    const int b_lcol = ((lane >> 3) & 1) * 8;

    const int nst = K >> 6;              // K/64
    issue_stage(0, 0);

    for (int s = 0; s < nst; s++) {
        CP_WAIT0();                      // stage s fully resident
        __syncthreads();                 // + all warps done reading other slot

        if (s + 1 < nst) issue_stage(s + 1, (s + 1) << 6);

        const __half* As = sm + (s & 1) * 2 * STG;
        const __half* Bs = As + STG;

        uint32_t fa[2][4][4];
        // preload A fragments for kk=0
        #pragma unroll
        for (int mi = 0; mi < 4; mi++) {
            uint32_t addr = smem_u32(
                &As[(warp_m + mi * 16 + a_lrow) * ASTR + a_lcol]);
            ldsm_x4(fa[0][mi][0], fa[0][mi][1], fa[0][mi][2], fa[0][mi][3], addr);
        }

        #pragma unroll
        for (int kk = 0; kk < 4; kk++) {
            const int pb = kk & 1;
            uint32_t fb[4][2];
            #pragma unroll
            for (int nj = 0; nj < 2; nj++) {
                uint32_t addr = smem_u32(
                    &Bs[(warp_n + nj * 16 + b_lrow) * ASTR + kk * 16 + b_lcol]);
                ldsm_x4(fb[2*nj][0], fb[2*nj][1], fb[2*nj+1][0], fb[2*nj+1][1], addr);
            }
            if (kk < 3) {   // prefetch next A fragments ahead of the MMA burst
                #pragma unroll
                for (int mi = 0; mi < 4; mi++) {
                    uint32_t addr = smem_u32(
                        &As[(warp_m + mi * 16 + a_lrow) * ASTR + (kk + 1) * 16 + a_lcol]);
                    ldsm_x4(fa[pb^1][mi][0], fa[pb^1][mi][1],
                            fa[pb^1][mi][2], fa[pb^1][mi][3], addr);
                }
            }
            #pragma unroll
            for (int mi = 0; mi < 4; mi++)
                #pragma unroll
                for (int ni = 0; ni < 4; ni++)
                    mma_f16(acc[mi][ni], fa[pb][mi], fb[ni]);
        }
    }

    // epilogue
    #pragma unroll
    for (int mi = 0; mi < 4; mi++) {
        #pragma unroll
        for (int ni = 0; ni < 4; ni++) {
            int row = bm + warp_m + mi * 16 + lr;
            int col = bn + warp_n + ni * 8 + 2 * lc;
            float b0 = bias ? bias[col]     : 0.f;
            float b1 = bias ? bias[col + 1] : 0.f;
            float2 v0 = make_float2(alpha * acc[mi][ni][0] + b0,
                                    alpha * acc[mi][ni][1] + b1);
            float2 v1 = make_float2(alpha * acc[mi][ni][2] + b0,
                                    alpha * acc[mi][ni][3] + b1);
            *reinterpret_cast<float2*>(&C[(size_t)row * N + col])       = v0;
            *reinterpret_cast<float2*>(&C[(size_t)(row + 8) * N + col]) = v1;
            if (Ch) {
                *reinterpret_cast<__half2*>(&Ch[(size_t)row * N + col]) =
                    __floats2half2_rn(v0.x, v0.y);
                *reinterpret_cast<__half2*>(&Ch[(size_t)(row + 8) * N + col]) =
                    __floats2half2_rn(v1.x, v1.y);
            }
        }
    }
}

// ---------------------------------------------------------------------------
// f32 -> fp16 elementwise convert (n % 8 == 0)
// ---------------------------------------------------------------------------
__global__ __launch_bounds__(256)
void f2h_kernel(const float* __restrict__ in, __half* __restrict__ out, size_t n)
{
    size_t i = ((size_t)blockIdx.x * blockDim.x + threadIdx.x) * 8;
    if (i >= n) return;
    float4 v0 = *reinterpret_cast<const float4*>(in + i);
    float4 v1 = *reinterpret_cast<const float4*>(in + i + 4);
    __half h[8];
    h[0]=__float2half_rn(v0.x); h[1]=__float2half_rn(v0.y);
    h[2]=__float2half_rn(v0.z); h[3]=__float2half_rn(v0.w);
    h[4]=__float2half_rn(v1.x); h[5]=__float2half_rn(v1.y);
    h[6]=__float2half_rn(v1.z); h[7]=__float2half_rn(v1.w);
    *reinterpret_cast<uint4*>(out + i) = *reinterpret_cast<uint4*>(h);
}

// ---------------------------------------------------------------------------
// transpose + convert: in f32 [R][Cin]  ->  out fp16 [Cin][R]
// ---------------------------------------------------------------------------
__global__ __launch_bounds__(256)
void tconv_kernel(const float* __restrict__ in, __half* __restrict__ out,
                  int R, int Cin)
{
    __shared__ float tile[32][33];
    int bx = blockIdx.x * 32;
    int by = blockIdx.y * 32;
    int tx = threadIdx.x & 31;
    int ty = threadIdx.x >> 5;
    #pragma unroll
    for (int i = 0; i < 32; i += 8)
        tile[ty + i][tx] = in[(size_t)(by + ty + i) * Cin + bx + tx];
    __syncthreads();
    #pragma unroll
    for (int i = 0; i < 32; i += 8)
        out[(size_t)(bx + ty + i) * R + by + tx] = __float2half_rn(tile[tx][ty + i]);
}

// ---------------------------------------------------------------------------
// q' : per row diag from Y row, row-max of dash row, exp (in place)
// ---------------------------------------------------------------------------
__global__ __launch_bounds__(256)
void qprime_kernel(const float* __restrict__ Y, float* __restrict__ dash)
{
    int warp = (blockIdx.x * blockDim.x + threadIdx.x) >> 5;
    int lane = threadIdx.x & 31;
    if (warp >= ROWS2) return;

    const float* y = Y + (size_t)warp * DEPTH;
    float ss = 0.f;
    #pragma unroll
    for (int i = 0; i < DEPTH/32; i++) { float v = y[lane + 32*i]; ss += v*v; }
    #pragma unroll
    for (int off = 16; off; off >>= 1) ss += __shfl_xor_sync(0xffffffff, ss, off);
    float diag = 0.5f * SCALE2 * ss;

    float* dr = dash + (size_t)warp * MFEAT;
    float vals[MFEAT/32];
    float mx = -1e30f;
    #pragma unroll
    for (int i = 0; i < MFEAT/32; i++) { vals[i] = dr[lane + 32*i]; mx = fmaxf(mx, vals[i]); }
    #pragma unroll
    for (int off = 16; off; off >>= 1) mx = fmaxf(mx, __shfl_xor_sync(0xffffffff, mx, off));

    #pragma unroll
    for (int i = 0; i < MFEAT/32; i++)
        dr[lane + 32*i] = RATIO * (expf(vals[i] - diag - mx) + EPS);
}

// ---------------------------------------------------------------------------
// k path step 1: per-row diag + per-row max
// ---------------------------------------------------------------------------
__global__ __launch_bounds__(256)
void kstat_kernel(const float* __restrict__ Y, const float* __restrict__ dash,
                  float* __restrict__ diagK, float* __restrict__ rmaxK)
{
    int warp = (blockIdx.x * blockDim.x + threadIdx.x) >> 5;
    int lane = threadIdx.x & 31;
    if (warp >= ROWS2) return;

    const float* y = Y + (size_t)warp * DEPTH;
    float ss = 0.f;
    #pragma unroll
    for (int i = 0; i < DEPTH/32; i++) { float v = y[lane + 32*i]; ss += v*v; }
    #pragma unroll
    for (int off = 16; off; off >>= 1) ss += __shfl_xor_sync(0xffffffff, ss, off);

    const float* dr = dash + (size_t)warp * MFEAT;
    float mx = -1e30f;
    #pragma unroll
    for (int i = 0; i < MFEAT/32; i++) mx = fmaxf(mx, dr[lane + 32*i]);
    #pragma unroll
    for (int off = 16; off; off >>= 1) mx = fmaxf(mx, __shfl_xor_sync(0xffffffff, mx, off));

    if (lane == 0) { diagK[warp] = 0.5f * SCALE2 * ss; rmaxK[warp] = mx; }
}

// k path step 2
__global__ __launch_bounds__(256)
void kmax_kernel(const float* __restrict__ rmaxK, float* __restrict__ kmax)
{
    int bh = blockIdx.x;
    int b  = bh >> 1, h = bh & 1;
    __shared__ float sm[256];
    float mx = -1e30f;
    for (int l = threadIdx.x; l < SEQ; l += 256)
        mx = fmaxf(mx, rmaxK[b*8192 + l*2 + h]);
    sm[threadIdx.x] = mx;
    __syncthreads();
    for (int s = 128; s; s >>= 1) {
        if (threadIdx.x < s) sm[threadIdx.x] = fmaxf(sm[threadIdx.x], sm[threadIdx.x + s]);
        __syncthreads();
    }
    if (threadIdx.x == 0) kmax[bh] = sm[0];
}

// k path step 3
__global__ __launch_bounds__(256)
void kexp_kernel(float* __restrict__ dash, const float* __restrict__ diagK,
                 const float* __restrict__ kmax)
{
    size_t idx = (size_t)blockIdx.x * blockDim.x + threadIdx.x;
    size_t total = (size_t)ROWS2 * MFEAT;
    if (idx >= total) return;
    int r = (int)(idx >> 8);
    int b = r >> 13;
    int h = r & 1;
    float v = dash[idx];
    dash[idx] = RATIO * (expf(v - diagK[r] - kmax[b*2 + h]) + EPS);
}

// ---------------------------------------------------------------------------
// Attention mix: per (s,h) block; 4x4 batch mix, scrambled concat store (fp16)
// ---------------------------------------------------------------------------
__global__ __launch_bounds__(256)
void attn_mix_kernel(const float* __restrict__ QP, const float* __restrict__ KP,
                     const float* __restrict__ V, __half* __restrict__ C)
{
    int blk = blockIdx.x;
    int s = blk >> 1, h = blk & 1;
    __shared__ float q_s[4][MFEAT];
    __shared__ float k_s[4][MFEAT];
    __shared__ float S[4][4];
    __shared__ float rs[4];
    int tid = threadIdx.x;

    #pragma unroll
    for (int bb = 0; bb < 4; bb++) {
        size_t r = (size_t)((bb*SEQ + s)*HEADS + h);
        q_s[bb][tid] = QP[r*MFEAT + tid];
        k_s[bb][tid] = KP[r*MFEAT + tid];
    }
    __syncthreads();

    int p = tid >> 4, lane16 = tid & 15;
    int bb = p >> 2, bp = p & 3;
    float acc = 0.f;
    #pragma unroll
    for (int m = 0; m < MFEAT; m += 16) acc += q_s[bb][m + lane16] * k_s[bp][m + lane16];
    #pragma unroll
    for (int off = 8; off; off >>= 1) acc += __shfl_down_sync(0xffffffff, acc, off, 16);
    if (lane16 == 0) S[bb][bp] = acc;
    __syncthreads();
    if (tid < 4) rs[tid] = S[tid][0] + S[tid][1] + S[tid][2] + S[tid][3];
    __syncthreads();

    float s00=S[0][0],s01=S[0][1],s02=S[0][2],s03=S[0][3];
    float s10=S[1][0],s11=S[1][1],s12=S[1][2],s13=S[1][3];
    float s20=S[2][0],s21=S[2][1],s22=S[2][2],s23=S[2][3];
    float s30=S[3][0],s31=S[3][1],s32=S[3][2],s33=S[3][3];
    float r0 = 1.f/rs[0], r1 = 1.f/rs[1], r2 = 1.f/rs[2], r3 = 1.f/rs[3];

    size_t cbase = (size_t)s*4096 + (size_t)h*2048;
    for (int d = tid; d < DEPTH; d += 256) {
        float v0 = V[(size_t)((0*SEQ + s)*HEADS + h)*DEPTH + d];
        float v1 = V[(size_t)((1*SEQ + s)*HEADS + h)*DEPTH + d];
        float v2 = V[(size_t)((2*SEQ + s)*HEADS + h)*DEPTH + d];
        float v3 = V[(size_t)((3*SEQ + s)*HEADS + h)*DEPTH + d];
        C[cbase + 0*512 + d] = __float2half_rn((s00*v0 + s01*v1 + s02*v2 + s03*v3) * r0);
        C[cbase + 1*512 + d] = __float2half_rn((s10*v0 + s11*v1 + s12*v2 + s13*v3) * r1);
        C[cbase + 2*512 + d] = __float2half_rn((s20*v0 + s21*v1 + s22*v2 + s23*v3) * r2);
        C[cbase + 3*512 + d] = __float2half_rn((s30*v0 + s31*v1 + s32*v2 + s33*v3) * r3);
    }
}

// ---------------------------------------------------------------------------
// Launch
// ---------------------------------------------------------------------------
extern "C" void kernel_launch(void* const* d_in, const int* in_sizes, int n_in,
                              void* d_out, int out_size)
{
    const float* query = (const float*)d_in[0];
    const float* key   = (const float*)d_in[1];
    const float* value = (const float*)d_in[2];
    const float* Wq = (const float*)d_in[4];
    const float* bq = (const float*)d_in[5];
    const float* Wk = (const float*)d_in[6];
    const float* bk = (const float*)d_in[7];
    const float* Wv = (const float*)d_in[8];
    const float* bv = (const float*)d_in[9];
    const float* Wo = (const float*)d_in[10];
    const float* bo = (const float*)d_in[11];
    const float* feats = (const float*)d_in[12];   // [256, 512] == [N, K]
    float* out = (float*)d_out;

    float *Q, *K, *V, *dQ, *dK, *diagK, *rmaxK, *kmax;
    __half *Ah, *Qh, *Kh, *Wth, *fh, *Ch;
    cudaGetSymbolAddress((void**)&Q,     g_Q);
    cudaGetSymbolAddress((void**)&K,     g_K);
    cudaGetSymbolAddress((void**)&V,     g_V);
    cudaGetSymbolAddress((void**)&dQ,    g_dQ);
    cudaGetSymbolAddress((void**)&dK,    g_dK);
    cudaGetSymbolAddress((void**)&diagK, g_diagK);
    cudaGetSymbolAddress((void**)&rmaxK, g_rmaxK);
    cudaGetSymbolAddress((void**)&kmax,  g_kmax);
    cudaGetSymbolAddress((void**)&Ah,    g_Ah);
    cudaGetSymbolAddress((void**)&Qh,    g_Qh);
    cudaGetSymbolAddress((void**)&Kh,    g_Kh);
    cudaGetSymbolAddress((void**)&Wth,   g_Wth);
    cudaGetSymbolAddress((void**)&fh,    g_fh);
    cudaGetSymbolAddress((void**)&Ch,    g_Ch);

    cudaFuncSetAttribute(hgemm, cudaFuncAttributeMaxDynamicSharedMemorySize, HSMEM);

    dim3 gT(DMODEL/32, DMODEL/32);
    dim3 gProj(DMODEL/128, ROWS/128);
    dim3 gFeat(MFEAT/128, ROWS2/128);
    const size_t NELEM = (size_t)ROWS * DMODEL;
    const unsigned gConv = (unsigned)((NELEM/8 + 255) / 256);

    // feats fp16 (once)
    f2h_kernel<<<(unsigned)((MFEAT*DEPTH/8 + 255)/256), 256>>>(feats, fh, MFEAT*DEPTH);

    // 1-3: projections  Y = X @ W + b   (X, W^T pre-converted fp16)
    f2h_kernel<<<gConv, 256>>>(query, Ah, NELEM);
    tconv_kernel<<<gT, 256>>>(Wq, Wth, DMODEL, DMODEL);
    hgemm<<<gProj, 256, HSMEM>>>(Ah, Wth, bq, Q, Qh, ROWS, DMODEL, DMODEL, 1.f);

    f2h_kernel<<<gConv, 256>>>(key, Ah, NELEM);
    tconv_kernel<<<gT, 256>>>(Wk, Wth, DMODEL, DMODEL);
    hgemm<<<gProj, 256, HSMEM>>>(Ah, Wth, bk, K, Kh, ROWS, DMODEL, DMODEL, 1.f);

    f2h_kernel<<<gConv, 256>>>(value, Ah, NELEM);
    tconv_kernel<<<gT, 256>>>(Wv, Wth, DMODEL, DMODEL);
    hgemm<<<gProj, 256, HSMEM>>>(Ah, Wth, bv, V, nullptr, ROWS, DMODEL, DMODEL, 1.f);

    // 4-5: feature projections  dash = (scale*Y512) @ feats^T
    hgemm<<<gFeat, 256, HSMEM>>>(Qh, fh, nullptr, dQ, nullptr, ROWS2, MFEAT, DEPTH, FSCALE);
    hgemm<<<gFeat, 256, HSMEM>>>(Kh, fh, nullptr, dK, nullptr, ROWS2, MFEAT, DEPTH, FSCALE);

    // 6: q'
    qprime_kernel<<<ROWS2/8, 256>>>(Q, dQ);

    // 7-9: k'
    kstat_kernel<<<ROWS2/8, 256>>>(K, dK, diagK, rmaxK);
    kmax_kernel<<<BATCH*HEADS, 256>>>(rmaxK, kmax);
    {
        size_t total = (size_t)ROWS2 * MFEAT;
        kexp_kernel<<<(unsigned)((total + 255)/256), 256>>>(dK, diagK, kmax);
    }

    // 10: attention mix -> fp16 concat
    attn_mix_kernel<<<SEQ*HEADS, 256>>>(dQ, dK, V, Ch);

    // 11: out = C @ Wo + bo
    tconv_kernel<<<gT, 256>>>(Wo, Wth, DMODEL, DMODEL);
    hgemm<<<gProj, 256, HSMEM>>>(Ch, Wth, bo, out, nullptr, ROWS, DMODEL, DMODEL, 1.f);
}

// round 9
// speedup vs baseline: 2.3887x; 1.0433x over previous
#include <cuda_runtime.h>
#include <cuda_fp16.h>
#include <math.h>
#include <stdint.h>

// ---------------------------------------------------------------------------
// Problem constants
// ---------------------------------------------------------------------------
#define BATCH     4
#define SEQ       4096
#define DMODEL    1024
#define HEADS     2
#define DEPTH     512
#define MFEAT     256
#define ROWS      (BATCH*SEQ)          // 16384
#define ROWS2     (ROWS*HEADS)         // 32768

#define SCALE2    0.044194173824159216f   // 1/sqrt(512)
#define FSCALE    0.21022410381342864f    // 512^{-0.25}
#define RATIO     0.0625f                 // 1/sqrt(256)
#define EPS       1e-6f

// ---------------------------------------------------------------------------
// Scratch (device globals; allocation is banned)
// ---------------------------------------------------------------------------
__device__ float  g_dQ[ (size_t)ROWS2 * MFEAT ];
__device__ float  g_dK[ (size_t)ROWS2 * MFEAT ];
__device__ float  g_diagQ[ ROWS2 ];
__device__ float  g_diagK[ ROWS2 ];
__device__ float  g_rmaxK[ ROWS2 ];
__device__ float  g_kmax [ BATCH*HEADS ];
__device__ float  g_sqp [ 8 * ROWS ];                // per-CTA-col-block Σy² partials
__device__ __half g_Ah [ (size_t)ROWS * DMODEL ];    // fp16 input mirror (reused)
__device__ __half g_Qh [ (size_t)ROWS * DMODEL ];    // fp16 Q
__device__ __half g_Kh [ (size_t)ROWS * DMODEL ];    // fp16 K
__device__ __half g_Vh [ (size_t)ROWS * DMODEL ];    // fp16 V
__device__ __half g_Wth[ (size_t)DMODEL * DMODEL ];  // fp16 transposed weight (reused)
__device__ __half g_fh [ (size_t)MFEAT * DEPTH ];    // fp16 feats
__device__ __half g_Ch [ (size_t)ROWS * DMODEL ];    // fp16 concat

// ---------------------------------------------------------------------------
// helpers
// ---------------------------------------------------------------------------
__device__ __forceinline__ uint32_t smem_u32(const void* p) {
    uint32_t a;
    asm("{ .reg .u64 t; cvta.to.shared.u64 t, %1; cvt.u32.u64 %0, t; }"
        : "=r"(a) : "l"(p));
    return a;
}

__device__ __forceinline__ void ldsm_x4(uint32_t& r0, uint32_t& r1,
                                        uint32_t& r2, uint32_t& r3, uint32_t addr) {
    asm volatile("ldmatrix.sync.aligned.m8n8.x4.shared.b16 {%0,%1,%2,%3}, [%4];"
                 : "=r"(r0), "=r"(r1), "=r"(r2), "=r"(r3) : "r"(addr));
}

__device__ __forceinline__ void mma_f16(float c[4], const uint32_t a[4],
                                        const uint32_t b[2]) {
    asm volatile(
        "mma.sync.aligned.m16n8k16.row.col.f32.f16.f16.f32 "
        "{%0,%1,%2,%3}, {%4,%5,%6,%7}, {%8,%9}, {%0,%1,%2,%3};"
        : "+f"(c[0]), "+f"(c[1]), "+f"(c[2]), "+f"(c[3])
        : "r"(a[0]), "r"(a[1]), "r"(a[2]), "r"(a[3]),
          "r"(b[0]), "r"(b[1]));
}

__device__ __forceinline__ void cp_async16(uint32_t smem, const void* gmem) {
    asm volatile("cp.async.cg.shared.global [%0], [%1], 16;"
                 :: "r"(smem), "l"(gmem) : "memory");
}
#define CP_COMMIT()  asm volatile("cp.async.commit_group;" ::: "memory")
#define CP_WAIT0()   asm volatile("cp.async.wait_group 0;" ::: "memory")

// ---------------------------------------------------------------------------
// fp16 GEMM (fp32 accumulate):  C = alpha * A(M,K) @ Bop(N,K)^T (+ bias)
//   2-stage cp.async pipeline, K-step 64, A-fragment double buffering.
//   Optional: fp32 out C, fp16 out Ch, per-row sum-of-squares partials sq
//   (sq[blockIdx.x * M + row] = sum over this CTA's 128 columns, deterministic).
// ---------------------------------------------------------------------------
#define ASTR   72                       // halves per row: 64 + 8 pad (144B)
#define STG    (128*ASTR)               // halves per operand tile (9216)
#define HSMEM  (2 * 2 * STG * 2)        // bytes = 73728

__global__ __launch_bounds__(256)
void hgemm(const __half* __restrict__ A, const __half* __restrict__ Bop,
           const float* __restrict__ bias, float* __restrict__ C,
           __half* __restrict__ Ch, float* __restrict__ sq,
           int M, int N, int K, float alpha)
{
    extern __shared__ __half sm[];

    const int tid  = threadIdx.x;
    const int lane = tid & 31;
    const int wid  = tid >> 5;
    const int bm = blockIdx.y * 128;
    const int bn = blockIdx.x * 128;

    const int warp_m = (wid & 1) * 64;
    const int warp_n = (wid >> 1) * 32;
    const int lr = lane >> 2;
    const int lc = lane & 3;

    const uint32_t smb = smem_u32(sm);

    auto issue_stage = [&](int s, int k0) {
        const int slot = s & 1;
        const uint32_t abase = smb + (uint32_t)(slot * 2 * STG) * 2;
        const uint32_t bbase = abase + (uint32_t)STG * 2;
        #pragma unroll
        for (int c = 0; c < 4; c++) {
            int chunk = tid + 256 * c;
            int row = chunk >> 3;
            int col = (chunk & 7) * 8;
            cp_async16(abase + (uint32_t)(row * ASTR + col) * 2,
                       A + (size_t)(bm + row) * K + k0 + col);
            cp_async16(bbase + (uint32_t)(row * ASTR + col) * 2,
                       Bop + (size_t)(bn + row) * K + k0 + col);
        }
        CP_COMMIT();
    };

    float acc[4][4][4];
    #pragma unroll
    for (int i = 0; i < 4; i++)
        #pragma unroll
        for (int j = 0; j < 4; j++)
            #pragma unroll
            for (int r = 0; r < 4; r++) acc[i][j][r] = 0.f;

    const int a_lrow = (lane & 7) + ((lane >> 3) & 1) * 8;
    const int a_lcol = (lane >> 4) * 8;
    const int b_lrow = (lane & 7) + (lane >= 16 ? 8 : 0);
    const int b_lcol = ((lane >> 3) & 1) * 8;

    const int nst = K >> 6;
    issue_stage(0, 0);

    for (int s = 0; s < nst; s++) {
        CP_WAIT0();
        __syncthreads();

        if (s + 1 < nst) issue_stage(s + 1, (s + 1) << 6);

        const __half* As = sm + (s & 1) * 2 * STG;
        const __half* Bs = As + STG;

        uint32_t fa[2][4][4];
        #pragma unroll
        for (int mi = 0; mi < 4; mi++) {
            uint32_t addr = smem_u32(
                &As[(warp_m + mi * 16 + a_lrow) * ASTR + a_lcol]);
            ldsm_x4(fa[0][mi][0], fa[0][mi][1], fa[0][mi][2], fa[0][mi][3], addr);
        }

        #pragma unroll
        for (int kk = 0; kk < 4; kk++) {
            const int pb = kk & 1;
            uint32_t fb[4][2];
            #pragma unroll
            for (int nj = 0; nj < 2; nj++) {
                uint32_t addr = smem_u32(
                    &Bs[(warp_n + nj * 16 + b_lrow) * ASTR + kk * 16 + b_lcol]);
                ldsm_x4(fb[2*nj][0], fb[2*nj][1], fb[2*nj+1][0], fb[2*nj+1][1], addr);
            }
            if (kk < 3) {
                #pragma unroll
                for (int mi = 0; mi < 4; mi++) {
                    uint32_t addr = smem_u32(
                        &As[(warp_m + mi * 16 + a_lrow) * ASTR + (kk + 1) * 16 + a_lcol]);
                    ldsm_x4(fa[pb^1][mi][0], fa[pb^1][mi][1],
                            fa[pb^1][mi][2], fa[pb^1][mi][3], addr);
                }
            }
            #pragma unroll
            for (int mi = 0; mi < 4; mi++)
                #pragma unroll
                for (int ni = 0; ni < 4; ni++)
                    mma_f16(acc[mi][ni], fa[pb][mi], fb[ni]);
        }
    }

    // epilogue (+ optional per-row sum of squares of the final values)
    float sA[4], sB[4];
    #pragma unroll
    for (int mi = 0; mi < 4; mi++) { sA[mi] = 0.f; sB[mi] = 0.f; }

    #pragma unroll
    for (int mi = 0; mi < 4; mi++) {
        #pragma unroll
        for (int ni = 0; ni < 4; ni++) {
            int row = bm + warp_m + mi * 16 + lr;
            int col = bn + warp_n + ni * 8 + 2 * lc;
            float b0 = bias ? bias[col]     : 0.f;
            float b1 = bias ? bias[col + 1] : 0.f;
            float2 v0 = make_float2(alpha * acc[mi][ni][0] + b0,
                                    alpha * acc[mi][ni][1] + b1);
            float2 v1 = make_float2(alpha * acc[mi][ni][2] + b0,
                                    alpha * acc[mi][ni][3] + b1);
            if (C) {
                *reinterpret_cast<float2*>(&C[(size_t)row * N + col])       = v0;
                *reinterpret_cast<float2*>(&C[(size_t)(row + 8) * N + col]) = v1;
            }
            if (Ch) {
                *reinterpret_cast<__half2*>(&Ch[(size_t)row * N + col]) =
                    __floats2half2_rn(v0.x, v0.y);
                *reinterpret_cast<__half2*>(&Ch[(size_t)(row + 8) * N + col]) =
                    __floats2half2_rn(v1.x, v1.y);
            }
            if (sq) {
                sA[mi] += v0.x * v0.x + v0.y * v0.y;
                sB[mi] += v1.x * v1.x + v1.y * v1.y;
            }
        }
    }

    if (sq) {
        // reduce over the 4 lc lanes (deterministic shfl tree)
        #pragma unroll
        for (int mi = 0; mi < 4; mi++) {
            #pragma unroll
            for (int o = 1; o <= 2; o <<= 1) {
                sA[mi] += __shfl_xor_sync(0xffffffff, sA[mi], o);
                sB[mi] += __shfl_xor_sync(0xffffffff, sB[mi], o);
            }
        }
        __syncthreads();                       // pipeline smem reads all done
        float* smf = reinterpret_cast<float*>(sm);  // [4][128]
        if (lc == 0) {
            #pragma unroll
            for (int mi = 0; mi < 4; mi++) {
                smf[(wid >> 1) * 128 + warp_m + mi * 16 + lr]     = sA[mi];
                smf[(wid >> 1) * 128 + warp_m + mi * 16 + lr + 8] = sB[mi];
            }
        }
        __syncthreads();
        if (tid < 128) {
            float t = smf[tid] + smf[128 + tid] + smf[256 + tid] + smf[384 + tid];
            sq[(size_t)blockIdx.x * M + bm + tid] = t;
        }
    }
}

// ---------------------------------------------------------------------------
// diag reduce: diag[r*2+h] = 0.5*SCALE2 * sum_j part[(4h+j)*ROWS + r]
// ---------------------------------------------------------------------------
__global__ __launch_bounds__(256)
void sqreduce_kernel(const float* __restrict__ part, float* __restrict__ diag)
{
    int r2 = blockIdx.x * blockDim.x + threadIdx.x;
    if (r2 >= ROWS2) return;
    int r = r2 >> 1, h = r2 & 1;
    const float* p = part + (size_t)(h * 4) * ROWS + r;
    float s = p[0] + p[ROWS] + p[2 * ROWS] + p[3 * ROWS];
    diag[r2] = 0.5f * SCALE2 * s;
}

// ---------------------------------------------------------------------------
// f32 -> fp16 elementwise convert (n % 8 == 0)
// ---------------------------------------------------------------------------
__global__ __launch_bounds__(256)
void f2h_kernel(const float* __restrict__ in, __half* __restrict__ out, size_t n)
{
    size_t i = ((size_t)blockIdx.x * blockDim.x + threadIdx.x) * 8;
    if (i >= n) return;
    float4 v0 = *reinterpret_cast<const float4*>(in + i);
    float4 v1 = *reinterpret_cast<const float4*>(in + i + 4);
    __half h[8];
    h[0]=__float2half_rn(v0.x); h[1]=__float2half_rn(v0.y);
    h[2]=__float2half_rn(v0.z); h[3]=__float2half_rn(v0.w);
    h[4]=__float2half_rn(v1.x); h[5]=__float2half_rn(v1.y);
    h[6]=__float2half_rn(v1.z); h[7]=__float2half_rn(v1.w);
    *reinterpret_cast<uint4*>(out + i) = *reinterpret_cast<uint4*>(h);
}

// ---------------------------------------------------------------------------
// transpose + convert: in f32 [R][Cin]  ->  out fp16 [Cin][R]
// ---------------------------------------------------------------------------
__global__ __launch_bounds__(256)
void tconv_kernel(const float* __restrict__ in, __half* __restrict__ out,
                  int R, int Cin)
{
    __shared__ float tile[32][33];
    int bx = blockIdx.x * 32;
    int by = blockIdx.y * 32;
    int tx = threadIdx.x & 31;
    int ty = threadIdx.x >> 5;
    #pragma unroll
    for (int i = 0; i < 32; i += 8)
        tile[ty + i][tx] = in[(size_t)(by + ty + i) * Cin + bx + tx];
    __syncthreads();
    #pragma unroll
    for (int i = 0; i < 32; i += 8)
        out[(size_t)(bx + ty + i) * R + by + tx] = __float2half_rn(tile[tx][ty + i]);
}

// ---------------------------------------------------------------------------
// q' : per row: rowmax of dash, exp with precomputed diag (in place)
// ---------------------------------------------------------------------------
__global__ __launch_bounds__(256)
void qprime_kernel(const float* __restrict__ diagQ, float* __restrict__ dash)
{
    int warp = (blockIdx.x * blockDim.x + threadIdx.x) >> 5;
    int lane = threadIdx.x & 31;
    if (warp >= ROWS2) return;

    float diag = diagQ[warp];
    float* dr = dash + (size_t)warp * MFEAT;
    float vals[MFEAT/32];
    float mx = -1e30f;
    #pragma unroll
    for (int i = 0; i < MFEAT/32; i++) { vals[i] = dr[lane + 32*i]; mx = fmaxf(mx, vals[i]); }
    #pragma unroll
    for (int off = 16; off; off >>= 1) mx = fmaxf(mx, __shfl_xor_sync(0xffffffff, mx, off));

    #pragma unroll
    for (int i = 0; i < MFEAT/32; i++)
        dr[lane + 32*i] = RATIO * (expf(vals[i] - diag - mx) + EPS);
}

// ---------------------------------------------------------------------------
// k path step 1: per-row max of dash
// ---------------------------------------------------------------------------
__global__ __launch_bounds__(256)
void kstat_kernel(const float* __restrict__ dash, float* __restrict__ rmaxK)
{
    int warp = (blockIdx.x * blockDim.x + threadIdx.x) >> 5;
    int lane = threadIdx.x & 31;
    if (warp >= ROWS2) return;

    const float* dr = dash + (size_t)warp * MFEAT;
    float mx = -1e30f;
    #pragma unroll
    for (int i = 0; i < MFEAT/32; i++) mx = fmaxf(mx, dr[lane + 32*i]);
    #pragma unroll
    for (int off = 16; off; off >>= 1) mx = fmaxf(mx, __shfl_xor_sync(0xffffffff, mx, off));

    if (lane == 0) rmaxK[warp] = mx;
}

// k path step 2
__global__ __launch_bounds__(256)
void kmax_kernel(const float* __restrict__ rmaxK, float* __restrict__ kmax)
{
    int bh = blockIdx.x;
    int b  = bh >> 1, h = bh & 1;
    __shared__ float sm[256];
    float mx = -1e30f;
    for (int l = threadIdx.x; l < SEQ; l += 256)
        mx = fmaxf(mx, rmaxK[b*8192 + l*2 + h]);
    sm[threadIdx.x] = mx;
    __syncthreads();
    for (int s = 128; s; s >>= 1) {
        if (threadIdx.x < s) sm[threadIdx.x] = fmaxf(sm[threadIdx.x], sm[threadIdx.x + s]);
        __syncthreads();
    }
    if (threadIdx.x == 0) kmax[bh] = sm[0];
}

// k path step 3
__global__ __launch_bounds__(256)
void kexp_kernel(float* __restrict__ dash, const float* __restrict__ diagK,
                 const float* __restrict__ kmax)
{
    size_t idx = (size_t)blockIdx.x * blockDim.x + threadIdx.x;
    size_t total = (size_t)ROWS2 * MFEAT;
    if (idx >= total) return;
    int r = (int)(idx >> 8);
    int b = r >> 13;
    int h = r & 1;
    float v = dash[idx];
    dash[idx] = RATIO * (expf(v - diagK[r] - kmax[b*2 + h]) + EPS);
}

// ---------------------------------------------------------------------------
// Attention mix: per (s,h) block; 4x4 batch mix; fp16 V in, fp16 concat out
// ---------------------------------------------------------------------------
__global__ __launch_bounds__(256)
void attn_mix_kernel(const float* __restrict__ QP, const float* __restrict__ KP,
                     const __half* __restrict__ Vh, __half* __restrict__ C)
{
    int blk = blockIdx.x;
    int s = blk >> 1, h = blk & 1;
    __shared__ float q_s[4][MFEAT];
    __shared__ float k_s[4][MFEAT];
    __shared__ float S[4][4];
    __shared__ float rs[4];
    int tid = threadIdx.x;

    #pragma unroll
    for (int bb = 0; bb < 4; bb++) {
        size_t r = (size_t)((bb*SEQ + s)*HEADS + h);
        q_s[bb][tid] = QP[r*MFEAT + tid];
        k_s[bb][tid] = KP[r*MFEAT + tid];
    }
    __syncthreads();

    int p = tid >> 4, lane16 = tid & 15;
    int bb = p >> 2, bp = p & 3;
    float acc = 0.f;
    #pragma unroll
    for (int m = 0; m < MFEAT; m += 16) acc += q_s[bb][m + lane16] * k_s[bp][m + lane16];
    #pragma unroll
    for (int off = 8; off; off >>= 1) acc += __shfl_down_sync(0xffffffff, acc, off, 16);
    if (lane16 == 0) S[bb][bp] = acc;
    __syncthreads();
    if (tid < 4) rs[tid] = S[tid][0] + S[tid][1] + S[tid][2] + S[tid][3];
    __syncthreads();

    float s00=S[0][0],s01=S[0][1],s02=S[0][2],s03=S[0][3];
    float s10=S[1][0],s11=S[1][1],s12=S[1][2],s13=S[1][3];
    float s20=S[2][0],s21=S[2][1],s22=S[2][2],s23=S[2][3];
    float s30=S[3][0],s31=S[3][1],s32=S[3][2],s33=S[3][3];
    float r0 = 1.f/rs[0], r1 = 1.f/rs[1], r2 = 1.f/rs[2], r3 = 1.f/rs[3];

    const __half2* V2 = reinterpret_cast<const __half2*>(Vh);
    __half2* C2 = reinterpret_cast<__half2*>(C);
    size_t cb2 = ((size_t)s*4096 + (size_t)h*2048) >> 1;
    int d2 = tid;                                  // 256 threads = 256 half2 = 512 halves
    {
        float2 v0 = __half22float2(V2[(size_t)((0*SEQ + s)*HEADS + h)*(DEPTH/2) + d2]);
        float2 v1 = __half22float2(V2[(size_t)((1*SEQ + s)*HEADS + h)*(DEPTH/2) + d2]);
        float2 v2 = __half22float2(V2[(size_t)((2*SEQ + s)*HEADS + h)*(DEPTH/2) + d2]);
        float2 v3 = __half22float2(V2[(size_t)((3*SEQ + s)*HEADS + h)*(DEPTH/2) + d2]);
        C2[cb2 + 0*256 + d2] = __floats2half2_rn((s00*v0.x + s01*v1.x + s02*v2.x + s03*v3.x) * r0,
                                                 (s00*v0.y + s01*v1.y + s02*v2.y + s03*v3.y) * r0);
        C2[cb2 + 1*256 + d2] = __floats2half2_rn((s10*v0.x + s11*v1.x + s12*v2.x + s13*v3.x) * r1,
                                                 (s10*v0.y + s11*v1.y + s12*v2.y + s13*v3.y) * r1);
        C2[cb2 + 2*256 + d2] = __floats2half2_rn((s20*v0.x + s21*v1.x + s22*v2.x + s23*v3.x) * r2,
                                                 (s20*v0.y + s21*v1.y + s22*v2.y + s23*v3.y) * r2);
        C2[cb2 + 3*256 + d2] = __floats2half2_rn((s30*v0.x + s31*v1.x + s32*v2.x + s33*v3.x) * r3,
                                                 (s30*v0.y + s31*v1.y + s32*v2.y + s33*v3.y) * r3);
    }
}

// ---------------------------------------------------------------------------
// Launch
// ---------------------------------------------------------------------------
extern "C" void kernel_launch(void* const* d_in, const int* in_sizes, int n_in,
                              void* d_out, int out_size)
{
    const float* query = (const float*)d_in[0];
    const float* key   = (const float*)d_in[1];
    const float* value = (const float*)d_in[2];
    const float* Wq = (const float*)d_in[4];
    const float* bq = (const float*)d_in[5];
    const float* Wk = (const float*)d_in[6];
    const float* bk = (const float*)d_in[7];
    const float* Wv = (const float*)d_in[8];
    const float* bv = (const float*)d_in[9];
    const float* Wo = (const float*)d_in[10];
    const float* bo = (const float*)d_in[11];
    const float* feats = (const float*)d_in[12];   // [256, 512] == [N, K]
    float* out = (float*)d_out;

    float *dQ, *dK, *diagQ, *diagK, *rmaxK, *kmax, *sqp;
    __half *Ah, *Qh, *Kh, *Vh, *Wth, *fh, *Ch;
    cudaGetSymbolAddress((void**)&dQ,    g_dQ);
    cudaGetSymbolAddress((void**)&dK,    g_dK);
    cudaGetSymbolAddress((void**)&diagQ, g_diagQ);
    cudaGetSymbolAddress((void**)&diagK, g_diagK);
    cudaGetSymbolAddress((void**)&rmaxK, g_rmaxK);
    cudaGetSymbolAddress((void**)&kmax,  g_kmax);
    cudaGetSymbolAddress((void**)&sqp,   g_sqp);
    cudaGetSymbolAddress((void**)&Ah,    g_Ah);
    cudaGetSymbolAddress((void**)&Qh,    g_Qh);
    cudaGetSymbolAddress((void**)&Kh,    g_Kh);
    cudaGetSymbolAddress((void**)&Vh,    g_Vh);
    cudaGetSymbolAddress((void**)&Wth,   g_Wth);
    cudaGetSymbolAddress((void**)&fh,    g_fh);
    cudaGetSymbolAddress((void**)&Ch,    g_Ch);

    cudaFuncSetAttribute(hgemm, cudaFuncAttributeMaxDynamicSharedMemorySize, HSMEM);

    dim3 gT(DMODEL/32, DMODEL/32);
    dim3 gProj(DMODEL/128, ROWS/128);
    dim3 gFeat(MFEAT/128, ROWS2/128);
    const size_t NELEM = (size_t)ROWS * DMODEL;
    const unsigned gConv = (unsigned)((NELEM/8 + 255) / 256);
    const unsigned gR2   = (ROWS2 + 255) / 256;

    // feats fp16 (once)
    f2h_kernel<<<(unsigned)((MFEAT*DEPTH/8 + 255)/256), 256>>>(feats, fh, MFEAT*DEPTH);

    // 1: Q projection -> Qh (fp16 only) + diagQ via epilogue partials
    f2h_kernel<<<gConv, 256>>>(query, Ah, NELEM);
    tconv_kernel<<<gT, 256>>>(Wq, Wth, DMODEL, DMODEL);
    hgemm<<<gProj, 256, HSMEM>>>(Ah, Wth, bq, nullptr, Qh, sqp, ROWS, DMODEL, DMODEL, 1.f);
    sqreduce_kernel<<<gR2, 256>>>(sqp, diagQ);

    // 2: K projection -> Kh + diagK
    f2h_kernel<<<gConv, 256>>>(key, Ah, NELEM);
    tconv_kernel<<<gT, 256>>>(Wk, Wth, DMODEL, DMODEL);
    hgemm<<<gProj, 256, HSMEM>>>(Ah, Wth, bk, nullptr, Kh, sqp, ROWS, DMODEL, DMODEL, 1.f);
    sqreduce_kernel<<<gR2, 256>>>(sqp, diagK);

    // 3: V projection -> Vh (fp16 only)
    f2h_kernel<<<gConv, 256>>>(value, Ah, NELEM);
    tconv_kernel<<<gT, 256>>>(Wv, Wth, DMODEL, DMODEL);
    hgemm<<<gProj, 256, HSMEM>>>(Ah, Wth, bv, nullptr, Vh, nullptr, ROWS, DMODEL, DMODEL, 1.f);

    // 4-5: feature projections  dash = (scale*Y512) @ feats^T
    hgemm<<<gFeat, 256, HSMEM>>>(Qh, fh, nullptr, dQ, nullptr, nullptr, ROWS2, MFEAT, DEPTH, FSCALE);
    hgemm<<<gFeat, 256, HSMEM>>>(Kh, fh, nullptr, dK, nullptr, nullptr, ROWS2, MFEAT, DEPTH, FSCALE);

    // 6: q'
    qprime_kernel<<<ROWS2/8, 256>>>(diagQ, dQ);

    // 7-9: k'
    kstat_kernel<<<ROWS2/8, 256>>>(dK, rmaxK);
    kmax_kernel<<<BATCH*HEADS, 256>>>(rmaxK, kmax);
    {
        size_t total = (size_t)ROWS2 * MFEAT;
        kexp_kernel<<<(unsigned)((total + 255)/256), 256>>>(dK, diagK, kmax);
    }

    // 10: attention mix -> fp16 concat
    attn_mix_kernel<<<SEQ*HEADS, 256>>>(dQ, dK, Vh, Ch);

    // 11: out = C @ Wo + bo
    tconv_kernel<<<gT, 256>>>(Wo, Wth, DMODEL, DMODEL);
    hgemm<<<gProj, 256, HSMEM>>>(Ch, Wth, bo, out, nullptr, nullptr, ROWS, DMODEL, DMODEL, 1.f);
}

// round 10
// speedup vs baseline: 2.4120x; 1.0098x over previous
#include <cuda_runtime.h>
#include <cuda_fp16.h>
#include <math.h>
#include <stdint.h>

// ---------------------------------------------------------------------------
// Problem constants
// ---------------------------------------------------------------------------
#define BATCH     4
#define SEQ       4096
#define DMODEL    1024
#define HEADS     2
#define DEPTH     512
#define MFEAT     256
#define ROWS      (BATCH*SEQ)          // 16384
#define ROWS2     (ROWS*HEADS)         // 32768

#define SCALE2    0.044194173824159216f   // 1/sqrt(512)
#define FSCALE    0.21022410381342864f    // 512^{-0.25}
#define RATIO     0.0625f                 // 1/sqrt(256)
#define EPS       1e-6f

// ---------------------------------------------------------------------------
// Scratch (device globals; allocation is banned)
// ---------------------------------------------------------------------------
__device__ float  g_dQ[ (size_t)ROWS2 * MFEAT ];
__device__ float  g_dK[ (size_t)ROWS2 * MFEAT ];
__device__ float  g_diagQ[ ROWS2 ];
__device__ float  g_diagK[ ROWS2 ];
__device__ float  g_rmxp [ 2 * ROWS2 ];              // per-CTA-colblock rowmax partials
__device__ float  g_kmax [ BATCH*HEADS ];
__device__ float  g_sqp [ 8 * ROWS ];                // per-CTA-colblock Σy² partials
__device__ __half g_Ah [ (size_t)ROWS * DMODEL ];    // fp16 input mirror (reused)
__device__ __half g_Qh [ (size_t)ROWS * DMODEL ];    // fp16 Q
__device__ __half g_Kh [ (size_t)ROWS * DMODEL ];    // fp16 K
__device__ __half g_Vh [ (size_t)ROWS * DMODEL ];    // fp16 V
__device__ __half g_Wth[ (size_t)DMODEL * DMODEL ];  // fp16 transposed weight (reused)
__device__ __half g_fh [ (size_t)MFEAT * DEPTH ];    // fp16 feats
__device__ __half g_Ch [ (size_t)ROWS * DMODEL ];    // fp16 concat

// ---------------------------------------------------------------------------
// helpers
// ---------------------------------------------------------------------------
__device__ __forceinline__ uint32_t smem_u32(const void* p) {
    uint32_t a;
    asm("{ .reg .u64 t; cvta.to.shared.u64 t, %1; cvt.u32.u64 %0, t; }"
        : "=r"(a) : "l"(p));
    return a;
}

__device__ __forceinline__ void ldsm_x4(uint32_t& r0, uint32_t& r1,
                                        uint32_t& r2, uint32_t& r3, uint32_t addr) {
    asm volatile("ldmatrix.sync.aligned.m8n8.x4.shared.b16 {%0,%1,%2,%3}, [%4];"
                 : "=r"(r0), "=r"(r1), "=r"(r2), "=r"(r3) : "r"(addr));
}

__device__ __forceinline__ void mma_f16(float c[4], const uint32_t a[4],
                                        const uint32_t b[2]) {
    asm volatile(
        "mma.sync.aligned.m16n8k16.row.col.f32.f16.f16.f32 "
        "{%0,%1,%2,%3}, {%4,%5,%6,%7}, {%8,%9}, {%0,%1,%2,%3};"
        : "+f"(c[0]), "+f"(c[1]), "+f"(c[2]), "+f"(c[3])
        : "r"(a[0]), "r"(a[1]), "r"(a[2]), "r"(a[3]),
          "r"(b[0]), "r"(b[1]));
}

__device__ __forceinline__ void cp_async16(uint32_t smem, const void* gmem) {
    asm volatile("cp.async.cg.shared.global [%0], [%1], 16;"
                 :: "r"(smem), "l"(gmem) : "memory");
}
#define CP_COMMIT()  asm volatile("cp.async.commit_group;" ::: "memory")
#define CP_WAIT1()   asm volatile("cp.async.wait_group 1;" ::: "memory")

// ---------------------------------------------------------------------------
// fp16 GEMM (fp32 accumulate):  C = alpha * A(M,K) @ Bop(N,K)^T (+ bias)
//   3-stage cp.async pipeline, K-step 64, A-fragment double buffering.
//   Optional outputs: fp32 C, fp16 Ch, per-row Σv² partials sq, per-row max
//   partials rmx (both indexed [blockIdx.x * M + row], deterministic).
//   Requires M%128, N%128, K%64 == 0, K>=128.
// ---------------------------------------------------------------------------
#define ASTR   72                       // halves per row: 64 + 8 pad (144B)
#define STG    (128*ASTR)               // halves per operand tile (9216)
#define HSMEM  (3 * 2 * STG * 2)        // bytes = 110592

__global__ __launch_bounds__(256)
void hgemm(const __half* __restrict__ A, const __half* __restrict__ Bop,
           const float* __restrict__ bias, float* __restrict__ C,
           __half* __restrict__ Ch, float* __restrict__ sq,
           float* __restrict__ rmx,
           int M, int N, int K, float alpha)
{
    extern __shared__ __half sm[];

    const int tid  = threadIdx.x;
    const int lane = tid & 31;
    const int wid  = tid >> 5;
    const int bm = blockIdx.y * 128;
    const int bn = blockIdx.x * 128;

    const int warp_m = (wid & 1) * 64;
    const int warp_n = (wid >> 1) * 32;
    const int lr = lane >> 2;
    const int lc = lane & 3;

    const uint32_t smb = smem_u32(sm);

    auto issue_stage = [&](int s, int k0) {
        const int slot = s % 3;
        const uint32_t abase = smb + (uint32_t)(slot * 2 * STG) * 2;
        const uint32_t bbase = abase + (uint32_t)STG * 2;
        #pragma unroll
        for (int c = 0; c < 4; c++) {
            int chunk = tid + 256 * c;
            int row = chunk >> 3;
            int col = (chunk & 7) * 8;
            cp_async16(abase + (uint32_t)(row * ASTR + col) * 2,
                       A + (size_t)(bm + row) * K + k0 + col);
            cp_async16(bbase + (uint32_t)(row * ASTR + col) * 2,
                       Bop + (size_t)(bn + row) * K + k0 + col);
        }
        CP_COMMIT();
    };

    float acc[4][4][4];
    #pragma unroll
    for (int i = 0; i < 4; i++)
        #pragma unroll
        for (int j = 0; j < 4; j++)
            #pragma unroll
            for (int r = 0; r < 4; r++) acc[i][j][r] = 0.f;

    const int a_lrow = (lane & 7) + ((lane >> 3) & 1) * 8;
    const int a_lcol = (lane >> 4) * 8;
    const int b_lrow = (lane & 7) + (lane >= 16 ? 8 : 0);
    const int b_lcol = ((lane >> 3) & 1) * 8;

    const int nst = K >> 6;
    issue_stage(0, 0);
    issue_stage(1, 64);

    for (int s = 0; s < nst; s++) {
        CP_WAIT1();                      // stage s resident (s+1 may be in flight)
        __syncthreads();                 // + all warps done reading slot (s+2)%3

        if (s + 2 < nst) issue_stage(s + 2, (s + 2) << 6);
        else             CP_COMMIT();    // empty group keeps counting exact

        const __half* As = sm + (s % 3) * 2 * STG;
        const __half* Bs = As + STG;

        uint32_t fa[2][4][4];
        #pragma unroll
        for (int mi = 0; mi < 4; mi++) {
            uint32_t addr = smem_u32(
                &As[(warp_m + mi * 16 + a_lrow) * ASTR + a_lcol]);
            ldsm_x4(fa[0][mi][0], fa[0][mi][1], fa[0][mi][2], fa[0][mi][3], addr);
        }

        #pragma unroll
        for (int kk = 0; kk < 4; kk++) {
            const int pb = kk & 1;
            uint32_t fb[4][2];
            #pragma unroll
            for (int nj = 0; nj < 2; nj++) {
                uint32_t addr = smem_u32(
                    &Bs[(warp_n + nj * 16 + b_lrow) * ASTR + kk * 16 + b_lcol]);
                ldsm_x4(fb[2*nj][0], fb[2*nj][1], fb[2*nj+1][0], fb[2*nj+1][1], addr);
            }
            if (kk < 3) {
                #pragma unroll
                for (int mi = 0; mi < 4; mi++) {
                    uint32_t addr = smem_u32(
                        &As[(warp_m + mi * 16 + a_lrow) * ASTR + (kk + 1) * 16 + a_lcol]);
                    ldsm_x4(fa[pb^1][mi][0], fa[pb^1][mi][1],
                            fa[pb^1][mi][2], fa[pb^1][mi][3], addr);
                }
            }
            #pragma unroll
            for (int mi = 0; mi < 4; mi++)
                #pragma unroll
                for (int ni = 0; ni < 4; ni++)
                    mma_f16(acc[mi][ni], fa[pb][mi], fb[ni]);
        }
    }

    // epilogue (+ optional per-row Σv² / rowmax partials)
    float sA[4], sB[4], mA[4], mB[4];
    #pragma unroll
    for (int mi = 0; mi < 4; mi++) {
        sA[mi] = 0.f; sB[mi] = 0.f; mA[mi] = -1e30f; mB[mi] = -1e30f;
    }

    #pragma unroll
    for (int mi = 0; mi < 4; mi++) {
        #pragma unroll
        for (int ni = 0; ni < 4; ni++) {
            int row = bm + warp_m + mi * 16 + lr;
            int col = bn + warp_n + ni * 8 + 2 * lc;
            float b0 = bias ? bias[col]     : 0.f;
            float b1 = bias ? bias[col + 1] : 0.f;
            float2 v0 = make_float2(alpha * acc[mi][ni][0] + b0,
                                    alpha * acc[mi][ni][1] + b1);
            float2 v1 = make_float2(alpha * acc[mi][ni][2] + b0,
                                    alpha * acc[mi][ni][3] + b1);
            if (C) {
                *reinterpret_cast<float2*>(&C[(size_t)row * N + col])       = v0;
                *reinterpret_cast<float2*>(&C[(size_t)(row + 8) * N + col]) = v1;
            }
            if (Ch) {
                *reinterpret_cast<__half2*>(&Ch[(size_t)row * N + col]) =
                    __floats2half2_rn(v0.x, v0.y);
                *reinterpret_cast<__half2*>(&Ch[(size_t)(row + 8) * N + col]) =
                    __floats2half2_rn(v1.x, v1.y);
            }
            if (sq) {
                sA[mi] += v0.x * v0.x + v0.y * v0.y;
                sB[mi] += v1.x * v1.x + v1.y * v1.y;
            }
            if (rmx) {
                mA[mi] = fmaxf(mA[mi], fmaxf(v0.x, v0.y));
                mB[mi] = fmaxf(mB[mi], fmaxf(v1.x, v1.y));
            }
        }
    }

    float* smf = reinterpret_cast<float*>(sm);  // [4][128]
    if (sq) {
        #pragma unroll
        for (int mi = 0; mi < 4; mi++) {
            #pragma unroll
            for (int o = 1; o <= 2; o <<= 1) {
                sA[mi] += __shfl_xor_sync(0xffffffff, sA[mi], o);
                sB[mi] += __shfl_xor_sync(0xffffffff, sB[mi], o);
            }
        }
        __syncthreads();
        if (lc == 0) {
            #pragma unroll
            for (int mi = 0; mi < 4; mi++) {
                smf[(wid >> 1) * 128 + warp_m + mi * 16 + lr]     = sA[mi];
                smf[(wid >> 1) * 128 + warp_m + mi * 16 + lr + 8] = sB[mi];
            }
        }
        __syncthreads();
        if (tid < 128) {
            float t = smf[tid] + smf[128 + tid] + smf[256 + tid] + smf[384 + tid];
            sq[(size_t)blockIdx.x * M + bm + tid] = t;
        }
    }
    if (rmx) {
        #pragma unroll
        for (int mi = 0; mi < 4; mi++) {
            #pragma unroll
            for (int o = 1; o <= 2; o <<= 1) {
                mA[mi] = fmaxf(mA[mi], __shfl_xor_sync(0xffffffff, mA[mi], o));
                mB[mi] = fmaxf(mB[mi], __shfl_xor_sync(0xffffffff, mB[mi], o));
            }
        }
        __syncthreads();
        if (lc == 0) {
            #pragma unroll
            for (int mi = 0; mi < 4; mi++) {
                smf[(wid >> 1) * 128 + warp_m + mi * 16 + lr]     = mA[mi];
                smf[(wid >> 1) * 128 + warp_m + mi * 16 + lr + 8] = mB[mi];
            }
        }
        __syncthreads();
        if (tid < 128) {
            float t = fmaxf(fmaxf(smf[tid], smf[128 + tid]),
                            fmaxf(smf[256 + tid], smf[384 + tid]));
            rmx[(size_t)blockIdx.x * M + bm + tid] = t;
        }
    }
}

// ---------------------------------------------------------------------------
// diag reduce: diag[r*2+h] = 0.5*SCALE2 * sum_j part[(4h+j)*ROWS + r]
// ---------------------------------------------------------------------------
__global__ __launch_bounds__(256)
void sqreduce_kernel(const float* __restrict__ part, float* __restrict__ diag)
{
    int r2 = blockIdx.x * blockDim.x + threadIdx.x;
    if (r2 >= ROWS2) return;
    int r = r2 >> 1, h = r2 & 1;
    const float* p = part + (size_t)(h * 4) * ROWS + r;
    float s = p[0] + p[ROWS] + p[2 * ROWS] + p[3 * ROWS];
    diag[r2] = 0.5f * SCALE2 * s;
}

// ---------------------------------------------------------------------------
// kmax: per (b,h) global max over sequence of dK rowmax partials
// rmxp layout: [cb (2)][row (ROWS2)], row r = b*8192 + l*2 + h
// ---------------------------------------------------------------------------
__global__ __launch_bounds__(256)
void kmax_kernel(const float* __restrict__ rmxp, float* __restrict__ kmax)
{
    int bh = blockIdx.x;
    int b  = bh >> 1, h = bh & 1;
    __shared__ float sm[256];
    float mx = -1e30f;
    for (int l = threadIdx.x; l < SEQ; l += 256) {
        int r = b * 8192 + l * 2 + h;
        mx = fmaxf(mx, fmaxf(rmxp[r], rmxp[ROWS2 + r]));
    }
    sm[threadIdx.x] = mx;
    __syncthreads();
    for (int s = 128; s; s >>= 1) {
        if (threadIdx.x < s) sm[threadIdx.x] = fmaxf(sm[threadIdx.x], sm[threadIdx.x + s]);
        __syncthreads();
    }
    if (threadIdx.x == 0) kmax[bh] = sm[0];
}

// ---------------------------------------------------------------------------
// f32 -> fp16 elementwise convert (n % 8 == 0)
// ---------------------------------------------------------------------------
__global__ __launch_bounds__(256)
void f2h_kernel(const float* __restrict__ in, __half* __restrict__ out, size_t n)
{
    size_t i = ((size_t)blockIdx.x * blockDim.x + threadIdx.x) * 8;
    if (i >= n) return;
    float4 v0 = *reinterpret_cast<const float4*>(in + i);
    float4 v1 = *reinterpret_cast<const float4*>(in + i + 4);
    __half h[8];
    h[0]=__float2half_rn(v0.x); h[1]=__float2half_rn(v0.y);
    h[2]=__float2half_rn(v0.z); h[3]=__float2half_rn(v0.w);
    h[4]=__float2half_rn(v1.x); h[5]=__float2half_rn(v1.y);
    h[6]=__float2half_rn(v1.z); h[7]=__float2half_rn(v1.w);
    *reinterpret_cast<uint4*>(out + i) = *reinterpret_cast<uint4*>(h);
}

// ---------------------------------------------------------------------------
// transpose + convert: in f32 [R][Cin]  ->  out fp16 [Cin][R]
// ---------------------------------------------------------------------------
__global__ __launch_bounds__(256)
void tconv_kernel(const float* __restrict__ in, __half* __restrict__ out,
                  int R, int Cin)
{
    __shared__ float tile[32][33];
    int bx = blockIdx.x * 32;
    int by = blockIdx.y * 32;
    int tx = threadIdx.x & 31;
    int ty = threadIdx.x >> 5;
    #pragma unroll
    for (int i = 0; i < 32; i += 8)
        tile[ty + i][tx] = in[(size_t)(by + ty + i) * Cin + bx + tx];
    __syncthreads();
    #pragma unroll
    for (int i = 0; i < 32; i += 8)
        out[(size_t)(bx + ty + i) * R + by + tx] = __float2half_rn(tile[tx][ty + i]);
}

// ---------------------------------------------------------------------------
// Attention mix (fused q'/k'): per (s,h) block.
//   loads raw dash rows, applies softmax-kernel transform in-smem,
//   4x4 batch mix, fp16 V in, fp16 concat out.
// ---------------------------------------------------------------------------
__global__ __launch_bounds__(256)
void attn_mix_kernel(const float* __restrict__ dQ, const float* __restrict__ dK,
                     const float* __restrict__ diagQ, const float* __restrict__ diagK,
                     const float* __restrict__ kmax,
                     const __half* __restrict__ Vh, __half* __restrict__ C)
{
    int blk = blockIdx.x;
    int s = blk >> 1, h = blk & 1;
    __shared__ float q_s[4][MFEAT];
    __shared__ float k_s[4][MFEAT];
    __shared__ float red[4][8];
    __shared__ float S[4][4];
    __shared__ float rs[4];
    int tid = threadIdx.x;
    int wid = tid >> 5, lane = tid & 31;

    float qv[4], kv[4];
    int ridx[4];
    #pragma unroll
    for (int bb = 0; bb < 4; bb++) {
        size_t r = (size_t)((bb*SEQ + s)*HEADS + h);
        ridx[bb] = (int)r;
        qv[bb] = dQ[r*MFEAT + tid];
        kv[bb] = dK[r*MFEAT + tid];
    }
    // per-row max of qv across the 256 threads
    #pragma unroll
    for (int bb = 0; bb < 4; bb++) {
        float m = qv[bb];
        #pragma unroll
        for (int off = 16; off; off >>= 1)
            m = fmaxf(m, __shfl_xor_sync(0xffffffff, m, off));
        if (lane == 0) red[bb][wid] = m;
    }
    __syncthreads();
    // exp transforms into smem
    #pragma unroll
    for (int bb = 0; bb < 4; bb++) {
        float qm = red[bb][0];
        #pragma unroll
        for (int w = 1; w < 8; w++) qm = fmaxf(qm, red[bb][w]);
        q_s[bb][tid] = RATIO * (expf(qv[bb] - diagQ[ridx[bb]] - qm) + EPS);
        k_s[bb][tid] = RATIO * (expf(kv[bb] - diagK[ridx[bb]] - kmax[bb*2 + h]) + EPS);
    }
    __syncthreads();

    int p = tid >> 4, lane16 = tid & 15;
    int bb = p >> 2, bp = p & 3;
    float acc = 0.f;
    #pragma unroll
    for (int m = 0; m < MFEAT; m += 16) acc += q_s[bb][m + lane16] * k_s[bp][m + lane16];
    #pragma unroll
    for (int off = 8; off; off >>= 1) acc += __shfl_down_sync(0xffffffff, acc, off, 16);
    if (lane16 == 0) S[bb][bp] = acc;
    __syncthreads();
    if (tid < 4) rs[tid] = S[tid][0] + S[tid][1] + S[tid][2] + S[tid][3];
    __syncthreads();

    float s00=S[0][0],s01=S[0][1],s02=S[0][2],s03=S[0][3];
    float s10=S[1][0],s11=S[1][1],s12=S[1][2],s13=S[1][3];
    float s20=S[2][0],s21=S[2][1],s22=S[2][2],s23=S[2][3];
    float s30=S[3][0],s31=S[3][1],s32=S[3][2],s33=S[3][3];
    float r0 = 1.f/rs[0], r1 = 1.f/rs[1], r2 = 1.f/rs[2], r3 = 1.f/rs[3];

    const __half2* V2 = reinterpret_cast<const __half2*>(Vh);
    __half2* C2 = reinterpret_cast<__half2*>(C);
    size_t cb2 = ((size_t)s*4096 + (size_t)h*2048) >> 1;
    int d2 = tid;
    {
        float2 v0 = __half22float2(V2[(size_t)((0*SEQ + s)*HEADS + h)*(DEPTH/2) + d2]);
        float2 v1 = __half22float2(V2[(size_t)((1*SEQ + s)*HEADS + h)*(DEPTH/2) + d2]);
        float2 v2 = __half22float2(V2[(size_t)((2*SEQ + s)*HEADS + h)*(DEPTH/2) + d2]);
        float2 v3 = __half22float2(V2[(size_t)((3*SEQ + s)*HEADS + h)*(DEPTH/2) + d2]);
        C2[cb2 + 0*256 + d2] = __floats2half2_rn((s00*v0.x + s01*v1.x + s02*v2.x + s03*v3.x) * r0,
                                                 (s00*v0.y + s01*v1.y + s02*v2.y + s03*v3.y) * r0);
        C2[cb2 + 1*256 + d2] = __floats2half2_rn((s10*v0.x + s11*v1.x + s12*v2.x + s13*v3.x) * r1,
                                                 (s10*v0.y + s11*v1.y + s12*v2.y + s13*v3.y) * r1);
        C2[cb2 + 2*256 + d2] = __floats2half2_rn((s20*v0.x + s21*v1.x + s22*v2.x + s23*v3.x) * r2,
                                                 (s20*v0.y + s21*v1.y + s22*v2.y + s23*v3.y) * r2);
        C2[cb2 + 3*256 + d2] = __floats2half2_rn((s30*v0.x + s31*v1.x + s32*v2.x + s33*v3.x) * r3,
                                                 (s30*v0.y + s31*v1.y + s32*v2.y + s33*v3.y) * r3);
    }
}

// ---------------------------------------------------------------------------
// Launch
// ---------------------------------------------------------------------------
extern "C" void kernel_launch(void* const* d_in, const int* in_sizes, int n_in,
                              void* d_out, int out_size)
{
    const float* query = (const float*)d_in[0];
    const float* key   = (const float*)d_in[1];
    const float* value = (const float*)d_in[2];
    const float* Wq = (const float*)d_in[4];
    const float* bq = (const float*)d_in[5];
    const float* Wk = (const float*)d_in[6];
    const float* bk = (const float*)d_in[7];
    const float* Wv = (const float*)d_in[8];
    const float* bv = (const float*)d_in[9];
    const float* Wo = (const float*)d_in[10];
    const float* bo = (const float*)d_in[11];
    const float* feats = (const float*)d_in[12];   // [256, 512] == [N, K]
    float* out = (float*)d_out;

    float *dQ, *dK, *diagQ, *diagK, *rmxp, *kmax, *sqp;
    __half *Ah, *Qh, *Kh, *Vh, *Wth, *fh, *Ch;
    cudaGetSymbolAddress((void**)&dQ,    g_dQ);
    cudaGetSymbolAddress((void**)&dK,    g_dK);
    cudaGetSymbolAddress((void**)&diagQ, g_diagQ);
    cudaGetSymbolAddress((void**)&diagK, g_diagK);
    cudaGetSymbolAddress((void**)&rmxp,  g_rmxp);
    cudaGetSymbolAddress((void**)&kmax,  g_kmax);
    cudaGetSymbolAddress((void**)&sqp,   g_sqp);
    cudaGetSymbolAddress((void**)&Ah,    g_Ah);
    cudaGetSymbolAddress((void**)&Qh,    g_Qh);
    cudaGetSymbolAddress((void**)&Kh,    g_Kh);
    cudaGetSymbolAddress((void**)&Vh,    g_Vh);
    cudaGetSymbolAddress((void**)&Wth,   g_Wth);
    cudaGetSymbolAddress((void**)&fh,    g_fh);
    cudaGetSymbolAddress((void**)&Ch,    g_Ch);

    cudaFuncSetAttribute(hgemm, cudaFuncAttributeMaxDynamicSharedMemorySize, HSMEM);

    dim3 gT(DMODEL/32, DMODEL/32);
    dim3 gProj(DMODEL/128, ROWS/128);
    dim3 gFeat(MFEAT/128, ROWS2/128);
    const size_t NELEM = (size_t)ROWS * DMODEL;
    const unsigned gConv = (unsigned)((NELEM/8 + 255) / 256);
    const unsigned gR2   = (ROWS2 + 255) / 256;

    // feats fp16 (once)
    f2h_kernel<<<(unsigned)((MFEAT*DEPTH/8 + 255)/256), 256>>>(feats, fh, MFEAT*DEPTH);

    // 1: Q projection -> Qh + diagQ partials
    f2h_kernel<<<gConv, 256>>>(query, Ah, NELEM);
    tconv_kernel<<<gT, 256>>>(Wq, Wth, DMODEL, DMODEL);
    hgemm<<<gProj, 256, HSMEM>>>(Ah, Wth, bq, nullptr, Qh, sqp, nullptr,
                                 ROWS, DMODEL, DMODEL, 1.f);
    sqreduce_kernel<<<gR2, 256>>>(sqp, diagQ);

    // 2: K projection -> Kh + diagK partials
    f2h_kernel<<<gConv, 256>>>(key, Ah, NELEM);
    tconv_kernel<<<gT, 256>>>(Wk, Wth, DMODEL, DMODEL);
    hgemm<<<gProj, 256, HSMEM>>>(Ah, Wth, bk, nullptr, Kh, sqp, nullptr,
                                 ROWS, DMODEL, DMODEL, 1.f);
    sqreduce_kernel<<<gR2, 256>>>(sqp, diagK);

    // 3: V projection -> Vh
    f2h_kernel<<<gConv, 256>>>(value, Ah, NELEM);
    tconv_kernel<<<gT, 256>>>(Wv, Wth, DMODEL, DMODEL);
    hgemm<<<gProj, 256, HSMEM>>>(Ah, Wth, bv, nullptr, Vh, nullptr, nullptr,
                                 ROWS, DMODEL, DMODEL, 1.f);

    // 4: dQ = (scale*Q512) @ feats^T      (raw dash; exp fused into attn_mix)
    hgemm<<<gFeat, 256, HSMEM>>>(Qh, fh, nullptr, dQ, nullptr, nullptr, nullptr,
                                 ROWS2, MFEAT, DEPTH, FSCALE);
    // 5: dK = (scale*K512) @ feats^T  + rowmax partials for kmax
    hgemm<<<gFeat, 256, HSMEM>>>(Kh, fh, nullptr, dK, nullptr, nullptr, rmxp,
                                 ROWS2, MFEAT, DEPTH, FSCALE);
    kmax_kernel<<<BATCH*HEADS, 256>>>(rmxp, kmax);

    // 6: fused q'/k' + attention mix -> fp16 concat
    attn_mix_kernel<<<SEQ*HEADS, 256>>>(dQ, dK, diagQ, diagK, kmax, Vh, Ch);

    // 7: out = C @ Wo + bo
    tconv_kernel<<<gT, 256>>>(Wo, Wth, DMODEL, DMODEL);
    hgemm<<<gProj, 256, HSMEM>>>(Ch, Wth, bo, out, nullptr, nullptr, nullptr,
                                 ROWS, DMODEL, DMODEL, 1.f);
}

// round 11
// speedup vs baseline: 2.6724x; 1.1080x over previous
#include <cuda_runtime.h>
#include <cuda_fp16.h>
#include <math.h>
#include <stdint.h>

// ---------------------------------------------------------------------------
// Problem constants
// ---------------------------------------------------------------------------
#define BATCH     4
#define SEQ       4096
#define DMODEL    1024
#define HEADS     2
#define DEPTH     512
#define MFEAT     256
#define ROWS      (BATCH*SEQ)          // 16384
#define ROWS2     (ROWS*HEADS)         // 32768

#define SCALE2    0.044194173824159216f   // 1/sqrt(512)
#define FSCALE    0.21022410381342864f    // 512^{-0.25}
#define RATIO     0.0625f                 // 1/sqrt(256)
#define EPS       1e-6f

// ---------------------------------------------------------------------------
// Scratch (device globals; allocation is banned)
// ---------------------------------------------------------------------------
__device__ float  g_dQ[ (size_t)ROWS2 * MFEAT ];
__device__ float  g_dK[ (size_t)ROWS2 * MFEAT ];
__device__ float  g_diagQ[ ROWS2 ];
__device__ float  g_diagK[ ROWS2 ];
__device__ float  g_rmxp [ 2 * ROWS2 ];              // per-CTA-colblock rowmax partials
__device__ float  g_kmax [ BATCH*HEADS ];
__device__ float  g_sqpQ[ 8 * ROWS ];                // per-CTA-colblock Σy² partials (Q)
__device__ float  g_sqpK[ 8 * ROWS ];                // (K)
__device__ __half g_A0 [ (size_t)ROWS * DMODEL ];    // fp16 query
__device__ __half g_A1 [ (size_t)ROWS * DMODEL ];    // fp16 key
__device__ __half g_A2 [ (size_t)ROWS * DMODEL ];    // fp16 value
__device__ __half g_Qh [ (size_t)ROWS * DMODEL ];    // fp16 Q
__device__ __half g_Kh [ (size_t)ROWS * DMODEL ];    // fp16 K
__device__ __half g_Vh [ (size_t)ROWS * DMODEL ];    // fp16 V
__device__ __half g_W0 [ (size_t)DMODEL * DMODEL ];  // fp16 Wq^T
__device__ __half g_W1 [ (size_t)DMODEL * DMODEL ];  // fp16 Wk^T
__device__ __half g_W2 [ (size_t)DMODEL * DMODEL ];  // fp16 Wv^T (reused for Wo^T)
__device__ __half g_fh [ (size_t)MFEAT * DEPTH ];    // fp16 feats
__device__ __half g_Ch [ (size_t)ROWS * DMODEL ];    // fp16 concat

// ---------------------------------------------------------------------------
// helpers
// ---------------------------------------------------------------------------
__device__ __forceinline__ uint32_t smem_u32(const void* p) {
    uint32_t a;
    asm("{ .reg .u64 t; cvta.to.shared.u64 t, %1; cvt.u32.u64 %0, t; }"
        : "=r"(a) : "l"(p));
    return a;
}

__device__ __forceinline__ void ldsm_x4(uint32_t& r0, uint32_t& r1,
                                        uint32_t& r2, uint32_t& r3, uint32_t addr) {
    asm volatile("ldmatrix.sync.aligned.m8n8.x4.shared.b16 {%0,%1,%2,%3}, [%4];"
                 : "=r"(r0), "=r"(r1), "=r"(r2), "=r"(r3) : "r"(addr));
}

__device__ __forceinline__ void mma_f16(float c[4], const uint32_t a[4],
                                        const uint32_t b[2]) {
    asm volatile(
        "mma.sync.aligned.m16n8k16.row.col.f32.f16.f16.f32 "
        "{%0,%1,%2,%3}, {%4,%5,%6,%7}, {%8,%9}, {%0,%1,%2,%3};"
        : "+f"(c[0]), "+f"(c[1]), "+f"(c[2]), "+f"(c[3])
        : "r"(a[0]), "r"(a[1]), "r"(a[2]), "r"(a[3]),
          "r"(b[0]), "r"(b[1]));
}

__device__ __forceinline__ void cp_async16(uint32_t smem, const void* gmem) {
    asm volatile("cp.async.cg.shared.global [%0], [%1], 16;"
                 :: "r"(smem), "l"(gmem) : "memory");
}
#define CP_COMMIT()  asm volatile("cp.async.commit_group;" ::: "memory")
#define CP_WAIT0()   asm volatile("cp.async.wait_group 0;" ::: "memory")

// ---------------------------------------------------------------------------
// Batched fp16 GEMM jobs (selected by blockIdx.z)
// ---------------------------------------------------------------------------
struct GemmJob {
    const __half* A;      // [M,K]
    const __half* Bop;    // [N,K]
    const float*  bias;   // [N] or null
    float*        C;      // fp32 out or null
    __half*       Ch;     // fp16 out or null
    float*        sq;     // per-row sum-sq partials [2 or 8][M] or null
    float*        rmx;    // per-row max partials [N/128][M] or null
};
struct GemmJobs { GemmJob j[3]; };

// ---------------------------------------------------------------------------
// fp16 GEMM (fp32 accumulate):  C = alpha * A(M,K) @ Bop(N,K)^T (+ bias)
//   2-stage cp.async pipeline, K-step 64, A-fragment double buffering.
//   Requires M%128, N%128, K%64 == 0, K>=128.
// ---------------------------------------------------------------------------
#define ASTR   72                       // halves per row: 64 + 8 pad (144B)
#define STG    (128*ASTR)               // halves per operand tile (9216)
#define HSMEM  (2 * 2 * STG * 2)        // bytes = 73728

__global__ __launch_bounds__(256)
void hgemm(GemmJobs jobs, int M, int N, int K, float alpha)
{
    extern __shared__ __half sm[];
    const GemmJob job = jobs.j[blockIdx.z];
    const __half* __restrict__ A   = job.A;
    const __half* __restrict__ Bop = job.Bop;

    const int tid  = threadIdx.x;
    const int lane = tid & 31;
    const int wid  = tid >> 5;
    const int bm = blockIdx.y * 128;
    const int bn = blockIdx.x * 128;

    const int warp_m = (wid & 1) * 64;
    const int warp_n = (wid >> 1) * 32;
    const int lr = lane >> 2;
    const int lc = lane & 3;

    const uint32_t smb = smem_u32(sm);

    auto issue_stage = [&](int s, int k0) {
        const int slot = s & 1;
        const uint32_t abase = smb + (uint32_t)(slot * 2 * STG) * 2;
        const uint32_t bbase = abase + (uint32_t)STG * 2;
        #pragma unroll
        for (int c = 0; c < 4; c++) {
            int chunk = tid + 256 * c;
            int row = chunk >> 3;
            int col = (chunk & 7) * 8;
            cp_async16(abase + (uint32_t)(row * ASTR + col) * 2,
                       A + (size_t)(bm + row) * K + k0 + col);
            cp_async16(bbase + (uint32_t)(row * ASTR + col) * 2,
                       Bop + (size_t)(bn + row) * K + k0 + col);
        }
        CP_COMMIT();
    };

    float acc[4][4][4];
    #pragma unroll
    for (int i = 0; i < 4; i++)
        #pragma unroll
        for (int j = 0; j < 4; j++)
            #pragma unroll
            for (int r = 0; r < 4; r++) acc[i][j][r] = 0.f;

    const int a_lrow = (lane & 7) + ((lane >> 3) & 1) * 8;
    const int a_lcol = (lane >> 4) * 8;
    const int b_lrow = (lane & 7) + (lane >= 16 ? 8 : 0);
    const int b_lcol = ((lane >> 3) & 1) * 8;

    const int nst = K >> 6;
    issue_stage(0, 0);

    for (int s = 0; s < nst; s++) {
        CP_WAIT0();
        __syncthreads();

        if (s + 1 < nst) issue_stage(s + 1, (s + 1) << 6);

        const __half* As = sm + (s & 1) * 2 * STG;
        const __half* Bs = As + STG;

        uint32_t fa[2][4][4];
        #pragma unroll
        for (int mi = 0; mi < 4; mi++) {
            uint32_t addr = smem_u32(
                &As[(warp_m + mi * 16 + a_lrow) * ASTR + a_lcol]);
            ldsm_x4(fa[0][mi][0], fa[0][mi][1], fa[0][mi][2], fa[0][mi][3], addr);
        }

        #pragma unroll
        for (int kk = 0; kk < 4; kk++) {
            const int pb = kk & 1;
            uint32_t fb[4][2];
            #pragma unroll
            for (int nj = 0; nj < 2; nj++) {
                uint32_t addr = smem_u32(
                    &Bs[(warp_n + nj * 16 + b_lrow) * ASTR + kk * 16 + b_lcol]);
                ldsm_x4(fb[2*nj][0], fb[2*nj][1], fb[2*nj+1][0], fb[2*nj+1][1], addr);
            }
            if (kk < 3) {
                #pragma unroll
                for (int mi = 0; mi < 4; mi++) {
                    uint32_t addr = smem_u32(
                        &As[(warp_m + mi * 16 + a_lrow) * ASTR + (kk + 1) * 16 + a_lcol]);
                    ldsm_x4(fa[pb^1][mi][0], fa[pb^1][mi][1],
                            fa[pb^1][mi][2], fa[pb^1][mi][3], addr);
                }
            }
            #pragma unroll
            for (int mi = 0; mi < 4; mi++)
                #pragma unroll
                for (int ni = 0; ni < 4; ni++)
                    mma_f16(acc[mi][ni], fa[pb][mi], fb[ni]);
        }
    }

    // epilogue (+ optional per-row Σv² / rowmax partials)
    float sA[4], sB[4], mA[4], mB[4];
    #pragma unroll
    for (int mi = 0; mi < 4; mi++) {
        sA[mi] = 0.f; sB[mi] = 0.f; mA[mi] = -1e30f; mB[mi] = -1e30f;
    }

    #pragma unroll
    for (int mi = 0; mi < 4; mi++) {
        #pragma unroll
        for (int ni = 0; ni < 4; ni++) {
            int row = bm + warp_m + mi * 16 + lr;
            int col = bn + warp_n + ni * 8 + 2 * lc;
            float b0 = job.bias ? job.bias[col]     : 0.f;
            float b1 = job.bias ? job.bias[col + 1] : 0.f;
            float2 v0 = make_float2(alpha * acc[mi][ni][0] + b0,
                                    alpha * acc[mi][ni][1] + b1);
            float2 v1 = make_float2(alpha * acc[mi][ni][2] + b0,
                                    alpha * acc[mi][ni][3] + b1);
            if (job.C) {
                *reinterpret_cast<float2*>(&job.C[(size_t)row * N + col])       = v0;
                *reinterpret_cast<float2*>(&job.C[(size_t)(row + 8) * N + col]) = v1;
            }
            if (job.Ch) {
                *reinterpret_cast<__half2*>(&job.Ch[(size_t)row * N + col]) =
                    __floats2half2_rn(v0.x, v0.y);
                *reinterpret_cast<__half2*>(&job.Ch[(size_t)(row + 8) * N + col]) =
                    __floats2half2_rn(v1.x, v1.y);
            }
            if (job.sq) {
                sA[mi] += v0.x * v0.x + v0.y * v0.y;
                sB[mi] += v1.x * v1.x + v1.y * v1.y;
            }
            if (job.rmx) {
                mA[mi] = fmaxf(mA[mi], fmaxf(v0.x, v0.y));
                mB[mi] = fmaxf(mB[mi], fmaxf(v1.x, v1.y));
            }
        }
    }

    float* smf = reinterpret_cast<float*>(sm);  // [4][128]
    if (job.sq) {
        #pragma unroll
        for (int mi = 0; mi < 4; mi++) {
            #pragma unroll
            for (int o = 1; o <= 2; o <<= 1) {
                sA[mi] += __shfl_xor_sync(0xffffffff, sA[mi], o);
                sB[mi] += __shfl_xor_sync(0xffffffff, sB[mi], o);
            }
        }
        __syncthreads();
        if (lc == 0) {
            #pragma unroll
            for (int mi = 0; mi < 4; mi++) {
                smf[(wid >> 1) * 128 + warp_m + mi * 16 + lr]     = sA[mi];
                smf[(wid >> 1) * 128 + warp_m + mi * 16 + lr + 8] = sB[mi];
            }
        }
        __syncthreads();
        if (tid < 128) {
            float t = smf[tid] + smf[128 + tid] + smf[256 + tid] + smf[384 + tid];
            job.sq[(size_t)blockIdx.x * M + bm + tid] = t;
        }
    }
    if (job.rmx) {
        #pragma unroll
        for (int mi = 0; mi < 4; mi++) {
            #pragma unroll
            for (int o = 1; o <= 2; o <<= 1) {
                mA[mi] = fmaxf(mA[mi], __shfl_xor_sync(0xffffffff, mA[mi], o));
                mB[mi] = fmaxf(mB[mi], __shfl_xor_sync(0xffffffff, mB[mi], o));
            }
        }
        __syncthreads();
        if (lc == 0) {
            #pragma unroll
            for (int mi = 0; mi < 4; mi++) {
                smf[(wid >> 1) * 128 + warp_m + mi * 16 + lr]     = mA[mi];
                smf[(wid >> 1) * 128 + warp_m + mi * 16 + lr + 8] = mB[mi];
            }
        }
        __syncthreads();
        if (tid < 128) {
            float t = fmaxf(fmaxf(smf[tid], smf[128 + tid]),
                            fmaxf(smf[256 + tid], smf[384 + tid]));
            job.rmx[(size_t)blockIdx.x * M + bm + tid] = t;
        }
    }
}

// ---------------------------------------------------------------------------
// diag reduce: diag[r*2+h] = 0.5*SCALE2 * sum_j part[(4h+j)*ROWS + r]
// ---------------------------------------------------------------------------
__global__ __launch_bounds__(256)
void sqreduce_kernel(const float* __restrict__ partQ, float* __restrict__ diagQ,
                     const float* __restrict__ partK, float* __restrict__ diagK)
{
    int r2 = blockIdx.x * blockDim.x + threadIdx.x;
    if (r2 >= ROWS2) return;
    int r = r2 >> 1, h = r2 & 1;
    {
        const float* p = partQ + (size_t)(h * 4) * ROWS + r;
        diagQ[r2] = 0.5f * SCALE2 * (p[0] + p[ROWS] + p[2*ROWS] + p[3*ROWS]);
    }
    {
        const float* p = partK + (size_t)(h * 4) * ROWS + r;
        diagK[r2] = 0.5f * SCALE2 * (p[0] + p[ROWS] + p[2*ROWS] + p[3*ROWS]);
    }
}

// ---------------------------------------------------------------------------
// kmax: per (b,h) global max over sequence of dK rowmax partials
// ---------------------------------------------------------------------------
__global__ __launch_bounds__(256)
void kmax_kernel(const float* __restrict__ rmxp, float* __restrict__ kmax)
{
    int bh = blockIdx.x;
    int b  = bh >> 1, h = bh & 1;
    __shared__ float sm[256];
    float mx = -1e30f;
    for (int l = threadIdx.x; l < SEQ; l += 256) {
        int r = b * 8192 + l * 2 + h;
        mx = fmaxf(mx, fmaxf(rmxp[r], rmxp[ROWS2 + r]));
    }
    sm[threadIdx.x] = mx;
    __syncthreads();
    for (int s = 128; s; s >>= 1) {
        if (threadIdx.x < s) sm[threadIdx.x] = fmaxf(sm[threadIdx.x], sm[threadIdx.x + s]);
        __syncthreads();
    }
    if (threadIdx.x == 0) kmax[bh] = sm[0];
}

// ---------------------------------------------------------------------------
// f32 -> fp16 elementwise convert: three tensors in one launch (blockIdx.y)
// ---------------------------------------------------------------------------
__global__ __launch_bounds__(256)
void f2h3_kernel(const float* __restrict__ i0, __half* __restrict__ o0,
                 const float* __restrict__ i1, __half* __restrict__ o1,
                 const float* __restrict__ i2, __half* __restrict__ o2, size_t n)
{
    const float* in  = (blockIdx.y == 0) ? i0 : (blockIdx.y == 1) ? i1 : i2;
    __half*      out = (blockIdx.y == 0) ? o0 : (blockIdx.y == 1) ? o1 : o2;
    size_t i = ((size_t)blockIdx.x * blockDim.x + threadIdx.x) * 8;
    if (i >= n) return;
    float4 v0 = *reinterpret_cast<const float4*>(in + i);
    float4 v1 = *reinterpret_cast<const float4*>(in + i + 4);
    __half h[8];
    h[0]=__float2half_rn(v0.x); h[1]=__float2half_rn(v0.y);
    h[2]=__float2half_rn(v0.z); h[3]=__float2half_rn(v0.w);
    h[4]=__float2half_rn(v1.x); h[5]=__float2half_rn(v1.y);
    h[6]=__float2half_rn(v1.z); h[7]=__float2half_rn(v1.w);
    *reinterpret_cast<uint4*>(out + i) = *reinterpret_cast<uint4*>(h);
}

__global__ __launch_bounds__(256)
void f2h_kernel(const float* __restrict__ in, __half* __restrict__ out, size_t n)
{
    size_t i = ((size_t)blockIdx.x * blockDim.x + threadIdx.x) * 8;
    if (i >= n) return;
    float4 v0 = *reinterpret_cast<const float4*>(in + i);
    float4 v1 = *reinterpret_cast<const float4*>(in + i + 4);
    __half h[8];
    h[0]=__float2half_rn(v0.x); h[1]=__float2half_rn(v0.y);
    h[2]=__float2half_rn(v0.z); h[3]=__float2half_rn(v0.w);
    h[4]=__float2half_rn(v1.x); h[5]=__float2half_rn(v1.y);
    h[6]=__float2half_rn(v1.z); h[7]=__float2half_rn(v1.w);
    *reinterpret_cast<uint4*>(out + i) = *reinterpret_cast<uint4*>(h);
}

// ---------------------------------------------------------------------------
// transpose + convert: three square weights in one launch (blockIdx.z)
// ---------------------------------------------------------------------------
__global__ __launch_bounds__(256)
void tconv3_kernel(const float* __restrict__ w0, __half* __restrict__ o0,
                   const float* __restrict__ w1, __half* __restrict__ o1,
                   const float* __restrict__ w2, __half* __restrict__ o2)
{
    const float* in  = (blockIdx.z == 0) ? w0 : (blockIdx.z == 1) ? w1 : w2;
    __half*      out = (blockIdx.z == 0) ? o0 : (blockIdx.z == 1) ? o1 : o2;
    __shared__ float tile[32][33];
    int bx = blockIdx.x * 32;
    int by = blockIdx.y * 32;
    int tx = threadIdx.x & 31;
    int ty = threadIdx.x >> 5;
    #pragma unroll
    for (int i = 0; i < 32; i += 8)
        tile[ty + i][tx] = in[(size_t)(by + ty + i) * DMODEL + bx + tx];
    __syncthreads();
    #pragma unroll
    for (int i = 0; i < 32; i += 8)
        out[(size_t)(bx + ty + i) * DMODEL + by + tx] = __float2half_rn(tile[tx][ty + i]);
}

__global__ __launch_bounds__(256)
void tconv_kernel(const float* __restrict__ in, __half* __restrict__ out,
                  int R, int Cin)
{
    __shared__ float tile[32][33];
    int bx = blockIdx.x * 32;
    int by = blockIdx.y * 32;
    int tx = threadIdx.x & 31;
    int ty = threadIdx.x >> 5;
    #pragma unroll
    for (int i = 0; i < 32; i += 8)
        tile[ty + i][tx] = in[(size_t)(by + ty + i) * Cin + bx + tx];
    __syncthreads();
    #pragma unroll
    for (int i = 0; i < 32; i += 8)
        out[(size_t)(bx + ty + i) * R + by + tx] = __float2half_rn(tile[tx][ty + i]);
}

// ---------------------------------------------------------------------------
// Attention mix (fused q'/k'): per (s,h) block.
// ---------------------------------------------------------------------------
__global__ __launch_bounds__(256)
void attn_mix_kernel(const float* __restrict__ dQ, const float* __restrict__ dK,
                     const float* __restrict__ diagQ, const float* __restrict__ diagK,
                     const float* __restrict__ kmax,
                     const __half* __restrict__ Vh, __half* __restrict__ C)
{
    int blk = blockIdx.x;
    int s = blk >> 1, h = blk & 1;
    __shared__ float q_s[4][MFEAT];
    __shared__ float k_s[4][MFEAT];
    __shared__ float red[4][8];
    __shared__ float S[4][4];
    __shared__ float rs[4];
    int tid = threadIdx.x;
    int wid = tid >> 5, lane = tid & 31;

    float qv[4], kv[4];
    int ridx[4];
    #pragma unroll
    for (int bb = 0; bb < 4; bb++) {
        size_t r = (size_t)((bb*SEQ + s)*HEADS + h);
        ridx[bb] = (int)r;
        qv[bb] = dQ[r*MFEAT + tid];
        kv[bb] = dK[r*MFEAT + tid];
    }
    #pragma unroll
    for (int bb = 0; bb < 4; bb++) {
        float m = qv[bb];
        #pragma unroll
        for (int off = 16; off; off >>= 1)
            m = fmaxf(m, __shfl_xor_sync(0xffffffff, m, off));
        if (lane == 0) red[bb][wid] = m;
    }
    __syncthreads();
    #pragma unroll
    for (int bb = 0; bb < 4; bb++) {
        float qm = red[bb][0];
        #pragma unroll
        for (int w = 1; w < 8; w++) qm = fmaxf(qm, red[bb][w]);
        q_s[bb][tid] = RATIO * (expf(qv[bb] - diagQ[ridx[bb]] - qm) + EPS);
        k_s[bb][tid] = RATIO * (expf(kv[bb] - diagK[ridx[bb]] - kmax[bb*2 + h]) + EPS);
    }
    __syncthreads();

    int p = tid >> 4, lane16 = tid & 15;
    int bb = p >> 2, bp = p & 3;
    float acc = 0.f;
    #pragma unroll
    for (int m = 0; m < MFEAT; m += 16) acc += q_s[bb][m + lane16] * k_s[bp][m + lane16];
    #pragma unroll
    for (int off = 8; off; off >>= 1) acc += __shfl_down_sync(0xffffffff, acc, off, 16);
    if (lane16 == 0) S[bb][bp] = acc;
    __syncthreads();
    if (tid < 4) rs[tid] = S[tid][0] + S[tid][1] + S[tid][2] + S[tid][3];
    __syncthreads();

    float s00=S[0][0],s01=S[0][1],s02=S[0][2],s03=S[0][3];
    float s10=S[1][0],s11=S[1][1],s12=S[1][2],s13=S[1][3];
    float s20=S[2][0],s21=S[2][1],s22=S[2][2],s23=S[2][3];
    float s30=S[3][0],s31=S[3][1],s32=S[3][2],s33=S[3][3];
    float r0 = 1.f/rs[0], r1 = 1.f/rs[1], r2 = 1.f/rs[2], r3 = 1.f/rs[3];

    const __half2* V2 = reinterpret_cast<const __half2*>(Vh);
    __half2* C2 = reinterpret_cast<__half2*>(C);
    size_t cb2 = ((size_t)s*4096 + (size_t)h*2048) >> 1;
    int d2 = tid;
    {
        float2 v0 = __half22float2(V2[(size_t)((0*SEQ + s)*HEADS + h)*(DEPTH/2) + d2]);
        float2 v1 = __half22float2(V2[(size_t)((1*SEQ + s)*HEADS + h)*(DEPTH/2) + d2]);
        float2 v2 = __half22float2(V2[(size_t)((2*SEQ + s)*HEADS + h)*(DEPTH/2) + d2]);
        float2 v3 = __half22float2(V2[(size_t)((3*SEQ + s)*HEADS + h)*(DEPTH/2) + d2]);
        C2[cb2 + 0*256 + d2] = __floats2half2_rn((s00*v0.x + s01*v1.x + s02*v2.x + s03*v3.x) * r0,
                                                 (s00*v0.y + s01*v1.y + s02*v2.y + s03*v3.y) * r0);
        C2[cb2 + 1*256 + d2] = __floats2half2_rn((s10*v0.x + s11*v1.x + s12*v2.x + s13*v3.x) * r1,
                                                 (s10*v0.y + s11*v1.y + s12*v2.y + s13*v3.y) * r1);
        C2[cb2 + 2*256 + d2] = __floats2half2_rn((s20*v0.x + s21*v1.x + s22*v2.x + s23*v3.x) * r2,
                                                 (s20*v0.y + s21*v1.y + s22*v2.y + s23*v3.y) * r2);
        C2[cb2 + 3*256 + d2] = __floats2half2_rn((s30*v0.x + s31*v1.x + s32*v2.x + s33*v3.x) * r3,
                                                 (s30*v0.y + s31*v1.y + s32*v2.y + s33*v3.y) * r3);
    }
}

// ---------------------------------------------------------------------------
// Launch
// ---------------------------------------------------------------------------
extern "C" void kernel_launch(void* const* d_in, const int* in_sizes, int n_in,
                              void* d_out, int out_size)
{
    const float* query = (const float*)d_in[0];
    const float* key   = (const float*)d_in[1];
    const float* value = (const float*)d_in[2];
    const float* Wq = (const float*)d_in[4];
    const float* bq = (const float*)d_in[5];
    const float* Wk = (const float*)d_in[6];
    const float* bk = (const float*)d_in[7];
    const float* Wv = (const float*)d_in[8];
    const float* bv = (const float*)d_in[9];
    const float* Wo = (const float*)d_in[10];
    const float* bo = (const float*)d_in[11];
    const float* feats = (const float*)d_in[12];   // [256, 512] == [N, K]
    float* out = (float*)d_out;

    float *dQ, *dK, *diagQ, *diagK, *rmxp, *kmax, *sqpQ, *sqpK;
    __half *A0, *A1, *A2, *Qh, *Kh, *Vh, *W0, *W1, *W2, *fh, *Ch;
    cudaGetSymbolAddress((void**)&dQ,    g_dQ);
    cudaGetSymbolAddress((void**)&dK,    g_dK);
    cudaGetSymbolAddress((void**)&diagQ, g_diagQ);
    cudaGetSymbolAddress((void**)&diagK, g_diagK);
    cudaGetSymbolAddress((void**)&rmxp,  g_rmxp);
    cudaGetSymbolAddress((void**)&kmax,  g_kmax);
    cudaGetSymbolAddress((void**)&sqpQ,  g_sqpQ);
    cudaGetSymbolAddress((void**)&sqpK,  g_sqpK);
    cudaGetSymbolAddress((void**)&A0,    g_A0);
    cudaGetSymbolAddress((void**)&A1,    g_A1);
    cudaGetSymbolAddress((void**)&A2,    g_A2);
    cudaGetSymbolAddress((void**)&Qh,    g_Qh);
    cudaGetSymbolAddress((void**)&Kh,    g_Kh);
    cudaGetSymbolAddress((void**)&Vh,    g_Vh);
    cudaGetSymbolAddress((void**)&W0,    g_W0);
    cudaGetSymbolAddress((void**)&W1,    g_W1);
    cudaGetSymbolAddress((void**)&W2,    g_W2);
    cudaGetSymbolAddress((void**)&fh,    g_fh);
    cudaGetSymbolAddress((void**)&Ch,    g_Ch);

    cudaFuncSetAttribute(hgemm, cudaFuncAttributeMaxDynamicSharedMemorySize, HSMEM);

    const size_t NELEM = (size_t)ROWS * DMODEL;
    const unsigned gConv = (unsigned)((NELEM/8 + 255) / 256);
    const unsigned gR2   = (ROWS2 + 255) / 256;

    // 0: all fp16 conversions (inputs batched, weights batched, feats)
    {
        dim3 g(gConv, 3);
        f2h3_kernel<<<g, 256>>>(query, A0, key, A1, value, A2, NELEM);
        dim3 gT(DMODEL/32, DMODEL/32, 3);
        tconv3_kernel<<<gT, 256>>>(Wq, W0, Wk, W1, Wv, W2);
        f2h_kernel<<<(unsigned)((MFEAT*DEPTH/8 + 255)/256), 256>>>(feats, fh, MFEAT*DEPTH);
    }

    // 1: batched Q/K/V projections (one launch, z = 3)
    {
        GemmJobs jobs;
        jobs.j[0] = { A0, W0, bq, nullptr, Qh, sqpQ, nullptr };
        jobs.j[1] = { A1, W1, bk, nullptr, Kh, sqpK, nullptr };
        jobs.j[2] = { A2, W2, bv, nullptr, Vh, nullptr, nullptr };
        dim3 g(DMODEL/128, ROWS/128, 3);
        hgemm<<<g, 256, HSMEM>>>(jobs, ROWS, DMODEL, DMODEL, 1.f);
    }
    sqreduce_kernel<<<gR2, 256>>>(sqpQ, diagQ, sqpK, diagK);

    // 2: batched feature projections (z = 2)
    {
        GemmJobs jobs;
        jobs.j[0] = { Qh, fh, nullptr, dQ, nullptr, nullptr, nullptr };
        jobs.j[1] = { Kh, fh, nullptr, dK, nullptr, nullptr, rmxp };
        jobs.j[2] = jobs.j[0];
        dim3 g(MFEAT/128, ROWS2/128, 2);
        hgemm<<<g, 256, HSMEM>>>(jobs, ROWS2, MFEAT, DEPTH, FSCALE);
    }
    kmax_kernel<<<BATCH*HEADS, 256>>>(rmxp, kmax);

    // 3: fused q'/k' + attention mix -> fp16 concat
    attn_mix_kernel<<<SEQ*HEADS, 256>>>(dQ, dK, diagQ, diagK, kmax, Vh, Ch);

    // 4: out = C @ Wo + bo
    tconv_kernel<<<dim3(DMODEL/32, DMODEL/32), 256>>>(Wo, W2, DMODEL, DMODEL);
    {
        GemmJobs jobs;
        jobs.j[0] = { Ch, W2, bo, out, nullptr, nullptr, nullptr };
        jobs.j[1] = jobs.j[0];
        jobs.j[2] = jobs.j[0];
        dim3 g(DMODEL/128, ROWS/128, 1);
        hgemm<<<g, 256, HSMEM>>>(jobs, ROWS, DMODEL, DMODEL, 1.f);
    }
}

// round 12
// speedup vs baseline: 2.6801x; 1.0029x over previous
#include <cuda_runtime.h>
#include <cuda_fp16.h>
#include <math.h>
#include <stdint.h>

// ---------------------------------------------------------------------------
// Problem constants
// ---------------------------------------------------------------------------
#define BATCH     4
#define SEQ       4096
#define DMODEL    1024
#define HEADS     2
#define DEPTH     512
#define MFEAT     256
#define ROWS      (BATCH*SEQ)          // 16384
#define ROWS2     (ROWS*HEADS)         // 32768

#define SCALE2    0.044194173824159216f   // 1/sqrt(512)
#define FSCALE    0.21022410381342864f    // 512^{-0.25}
#define RATIO     0.0625f                 // 1/sqrt(256)
#define EPS       1e-6f

// ---------------------------------------------------------------------------
// Scratch (device globals; allocation is banned)
// ---------------------------------------------------------------------------
__device__ float  g_dQ[ (size_t)ROWS2 * MFEAT ];
__device__ float  g_dK[ (size_t)ROWS2 * MFEAT ];
__device__ float  g_diagQ[ ROWS2 ];
__device__ float  g_diagK[ ROWS2 ];
__device__ float  g_rmxp [ 4 * ROWS2 ];              // per-colblock rowmax partials
__device__ float  g_kmax [ BATCH*HEADS ];
__device__ float  g_sqpQ[ 16 * ROWS ];               // per-colblock Σy² partials (Q)
__device__ float  g_sqpK[ 16 * ROWS ];               // (K)
__device__ __half g_A0 [ (size_t)ROWS * DMODEL ];    // fp16 query
__device__ __half g_A1 [ (size_t)ROWS * DMODEL ];    // fp16 key
__device__ __half g_A2 [ (size_t)ROWS * DMODEL ];    // fp16 value
__device__ __half g_Qh [ (size_t)ROWS * DMODEL ];    // fp16 Q
__device__ __half g_Kh [ (size_t)ROWS * DMODEL ];    // fp16 K
__device__ __half g_Vh [ (size_t)ROWS * DMODEL ];    // fp16 V
__device__ __half g_W0 [ (size_t)DMODEL * DMODEL ];  // fp16 Wq^T
__device__ __half g_W1 [ (size_t)DMODEL * DMODEL ];  // fp16 Wk^T
__device__ __half g_W2 [ (size_t)DMODEL * DMODEL ];  // fp16 Wv^T (reused for Wo^T)
__device__ __half g_fh [ (size_t)MFEAT * DEPTH ];    // fp16 feats
__device__ __half g_Ch [ (size_t)ROWS * DMODEL ];    // fp16 concat

// ---------------------------------------------------------------------------
// helpers
// ---------------------------------------------------------------------------
__device__ __forceinline__ uint32_t smem_u32(const void* p) {
    uint32_t a;
    asm("{ .reg .u64 t; cvta.to.shared.u64 t, %1; cvt.u32.u64 %0, t; }"
        : "=r"(a) : "l"(p));
    return a;
}

__device__ __forceinline__ void ldsm_x4(uint32_t& r0, uint32_t& r1,
                                        uint32_t& r2, uint32_t& r3, uint32_t addr) {
    asm volatile("ldmatrix.sync.aligned.m8n8.x4.shared.b16 {%0,%1,%2,%3}, [%4];"
                 : "=r"(r0), "=r"(r1), "=r"(r2), "=r"(r3) : "r"(addr));
}

__device__ __forceinline__ void mma_f16(float c[4], const uint32_t a[4],
                                        const uint32_t b[2]) {
    asm volatile(
        "mma.sync.aligned.m16n8k16.row.col.f32.f16.f16.f32 "
        "{%0,%1,%2,%3}, {%4,%5,%6,%7}, {%8,%9}, {%0,%1,%2,%3};"
        : "+f"(c[0]), "+f"(c[1]), "+f"(c[2]), "+f"(c[3])
        : "r"(a[0]), "r"(a[1]), "r"(a[2]), "r"(a[3]),
          "r"(b[0]), "r"(b[1]));
}

__device__ __forceinline__ void cp_async16(uint32_t smem, const void* gmem) {
    asm volatile("cp.async.cg.shared.global [%0], [%1], 16;"
                 :: "r"(smem), "l"(gmem) : "memory");
}
#define CP_COMMIT()  asm volatile("cp.async.commit_group;" ::: "memory")
#define CP_WAIT0()   asm volatile("cp.async.wait_group 0;" ::: "memory")

// ---------------------------------------------------------------------------
// Batched fp16 GEMM jobs (selected by blockIdx.z)
// ---------------------------------------------------------------------------
struct GemmJob {
    const __half* A;      // [M,K]
    const __half* Bop;    // [N,K]
    const float*  bias;   // [N] or null
    float*        C;      // fp32 out or null
    __half*       Ch;     // fp16 out or null
    float*        sq;     // per-row sum-sq partials [N/64][M] or null
    float*        rmx;    // per-row max partials [N/64][M] or null
};
struct GemmJobs { GemmJob j[3]; };

// ---------------------------------------------------------------------------
// fp16 GEMM (fp32 accumulate):  C = alpha * A(M,K) @ Bop(N,K)^T (+ bias)
//   128 threads/CTA, tile 128(M) x 64(N), warp tile 64x32 (2x2 warps),
//   2-stage cp.async pipeline, K-step 64, A-fragment double buffering.
//   4 CTAs/SM (regs<=128, smem 55.3KB). Requires M%128, N%64, K%64==0, K>=128.
// ---------------------------------------------------------------------------
#define ASTR   72                       // halves per row: 64 + 8 pad (144B)
#define STG_A  (128*ASTR)               // 9216 halves
#define STG_B  (64*ASTR)                // 4608 halves
#define STG_T  (STG_A + STG_B)          // 13824 halves / stage
#define HSMEM  (2 * STG_T * 2)          // bytes = 55296

__global__ __launch_bounds__(128, 4)
void hgemm(GemmJobs jobs, int M, int N, int K, float alpha)
{
    extern __shared__ __half sm[];
    const GemmJob job = jobs.j[blockIdx.z];
    const __half* __restrict__ A   = job.A;
    const __half* __restrict__ Bop = job.Bop;

    const int tid  = threadIdx.x;
    const int lane = tid & 31;
    const int wid  = tid >> 5;            // 0..3
    const int bm = blockIdx.y * 128;
    const int bn = blockIdx.x * 64;

    const int warp_m = (wid & 1) * 64;
    const int warp_n = (wid >> 1) * 32;
    const int lr = lane >> 2;
    const int lc = lane & 3;

    const uint32_t smb = smem_u32(sm);

    auto issue_stage = [&](int s, int k0) {
        const int slot = s & 1;
        const uint32_t abase = smb + (uint32_t)(slot * STG_T) * 2;
        const uint32_t bbase = abase + (uint32_t)STG_A * 2;
        #pragma unroll
        for (int c = 0; c < 8; c++) {          // A: 1024 chunks / 128 thr
            int chunk = tid + 128 * c;
            int row = chunk >> 3;
            int col = (chunk & 7) * 8;
            cp_async16(abase + (uint32_t)(row * ASTR + col) * 2,
                       A + (size_t)(bm + row) * K + k0 + col);
        }
        #pragma unroll
        for (int c = 0; c < 4; c++) {          // B: 512 chunks / 128 thr
            int chunk = tid + 128 * c;
            int row = chunk >> 3;
            int col = (chunk & 7) * 8;
            cp_async16(bbase + (uint32_t)(row * ASTR + col) * 2,
                       Bop + (size_t)(bn + row) * K + k0 + col);
        }
        CP_COMMIT();
    };

    float acc[4][4][4];
    #pragma unroll
    for (int i = 0; i < 4; i++)
        #pragma unroll
        for (int j = 0; j < 4; j++)
            #pragma unroll
            for (int r = 0; r < 4; r++) acc[i][j][r] = 0.f;

    const int a_lrow = (lane & 7) + ((lane >> 3) & 1) * 8;
    const int a_lcol = (lane >> 4) * 8;
    const int b_lrow = (lane & 7) + (lane >= 16 ? 8 : 0);
    const int b_lcol = ((lane >> 3) & 1) * 8;

    const int nst = K >> 6;
    issue_stage(0, 0);

    for (int s = 0; s < nst; s++) {
        CP_WAIT0();
        __syncthreads();

        if (s + 1 < nst) issue_stage(s + 1, (s + 1) << 6);

        const __half* As = sm + (s & 1) * STG_T;
        const __half* Bs = As + STG_A;

        uint32_t fa[2][4][4];
        #pragma unroll
        for (int mi = 0; mi < 4; mi++) {
            uint32_t addr = smem_u32(
                &As[(warp_m + mi * 16 + a_lrow) * ASTR + a_lcol]);
            ldsm_x4(fa[0][mi][0], fa[0][mi][1], fa[0][mi][2], fa[0][mi][3], addr);
        }

        #pragma unroll
        for (int kk = 0; kk < 4; kk++) {
            const int pb = kk & 1;
            uint32_t fb[4][2];
            #pragma unroll
            for (int nj = 0; nj < 2; nj++) {
                uint32_t addr = smem_u32(
                    &Bs[(warp_n + nj * 16 + b_lrow) * ASTR + kk * 16 + b_lcol]);
                ldsm_x4(fb[2*nj][0], fb[2*nj][1], fb[2*nj+1][0], fb[2*nj+1][1], addr);
            }
            if (kk < 3) {
                #pragma unroll
                for (int mi = 0; mi < 4; mi++) {
                    uint32_t addr = smem_u32(
                        &As[(warp_m + mi * 16 + a_lrow) * ASTR + (kk + 1) * 16 + a_lcol]);
                    ldsm_x4(fa[pb^1][mi][0], fa[pb^1][mi][1],
                            fa[pb^1][mi][2], fa[pb^1][mi][3], addr);
                }
            }
            #pragma unroll
            for (int mi = 0; mi < 4; mi++)
                #pragma unroll
                for (int ni = 0; ni < 4; ni++)
                    mma_f16(acc[mi][ni], fa[pb][mi], fb[ni]);
        }
    }

    // epilogue (+ optional per-row Σv² / rowmax partials)
    float sA[4], sB[4], mA[4], mB[4];
    #pragma unroll
    for (int mi = 0; mi < 4; mi++) {
        sA[mi] = 0.f; sB[mi] = 0.f; mA[mi] = -1e30f; mB[mi] = -1e30f;
    }

    #pragma unroll
    for (int mi = 0; mi < 4; mi++) {
        #pragma unroll
        for (int ni = 0; ni < 4; ni++) {
            int row = bm + warp_m + mi * 16 + lr;
            int col = bn + warp_n + ni * 8 + 2 * lc;
            float b0 = job.bias ? job.bias[col]     : 0.f;
            float b1 = job.bias ? job.bias[col + 1] : 0.f;
            float2 v0 = make_float2(alpha * acc[mi][ni][0] + b0,
                                    alpha * acc[mi][ni][1] + b1);
            float2 v1 = make_float2(alpha * acc[mi][ni][2] + b0,
                                    alpha * acc[mi][ni][3] + b1);
            if (job.C) {
                *reinterpret_cast<float2*>(&job.C[(size_t)row * N + col])       = v0;
                *reinterpret_cast<float2*>(&job.C[(size_t)(row + 8) * N + col]) = v1;
            }
            if (job.Ch) {
                *reinterpret_cast<__half2*>(&job.Ch[(size_t)row * N + col]) =
                    __floats2half2_rn(v0.x, v0.y);
                *reinterpret_cast<__half2*>(&job.Ch[(size_t)(row + 8) * N + col]) =
                    __floats2half2_rn(v1.x, v1.y);
            }
            if (job.sq) {
                sA[mi] += v0.x * v0.x + v0.y * v0.y;
                sB[mi] += v1.x * v1.x + v1.y * v1.y;
            }
            if (job.rmx) {
                mA[mi] = fmaxf(mA[mi], fmaxf(v0.x, v0.y));
                mB[mi] = fmaxf(mB[mi], fmaxf(v1.x, v1.y));
            }
        }
    }

    float* smf = reinterpret_cast<float*>(sm);  // [2][128] floats
    if (job.sq) {
        #pragma unroll
        for (int mi = 0; mi < 4; mi++) {
            #pragma unroll
            for (int o = 1; o <= 2; o <<= 1) {
                sA[mi] += __shfl_xor_sync(0xffffffff, sA[mi], o);
                sB[mi] += __shfl_xor_sync(0xffffffff, sB[mi], o);
            }
        }
        __syncthreads();
        if (lc == 0) {
            #pragma unroll
            for (int mi = 0; mi < 4; mi++) {
                smf[(wid >> 1) * 128 + warp_m + mi * 16 + lr]     = sA[mi];
                smf[(wid >> 1) * 128 + warp_m + mi * 16 + lr + 8] = sB[mi];
            }
        }
        __syncthreads();
        {
            float t = smf[tid] + smf[128 + tid];
            job.sq[(size_t)blockIdx.x * M + bm + tid] = t;
        }
    }
    if (job.rmx) {
        #pragma unroll
        for (int mi = 0; mi < 4; mi++) {
            #pragma unroll
            for (int o = 1; o <= 2; o <<= 1) {
                mA[mi] = fmaxf(mA[mi], __shfl_xor_sync(0xffffffff, mA[mi], o));
                mB[mi] = fmaxf(mB[mi], __shfl_xor_sync(0xffffffff, mB[mi], o));
            }
        }
        __syncthreads();
        if (lc == 0) {
            #pragma unroll
            for (int mi = 0; mi < 4; mi++) {
                smf[(wid >> 1) * 128 + warp_m + mi * 16 + lr]     = mA[mi];
                smf[(wid >> 1) * 128 + warp_m + mi * 16 + lr + 8] = mB[mi];
            }
        }
        __syncthreads();
        {
            float t = fmaxf(smf[tid], smf[128 + tid]);
            job.rmx[(size_t)blockIdx.x * M + bm + tid] = t;
        }
    }
}

// ---------------------------------------------------------------------------
// diag reduce: diag[r*2+h] = 0.5*SCALE2 * sum_{j<8} part[(h*8+j)*ROWS + r]
// ---------------------------------------------------------------------------
__global__ __launch_bounds__(256)
void sqreduce_kernel(const float* __restrict__ partQ, float* __restrict__ diagQ,
                     const float* __restrict__ partK, float* __restrict__ diagK)
{
    int r2 = blockIdx.x * blockDim.x + threadIdx.x;
    if (r2 >= ROWS2) return;
    int r = r2 >> 1, h = r2 & 1;
    {
        const float* p = partQ + (size_t)(h * 8) * ROWS + r;
        float s = 0.f;
        #pragma unroll
        for (int j = 0; j < 8; j++) s += p[(size_t)j * ROWS];
        diagQ[r2] = 0.5f * SCALE2 * s;
    }
    {
        const float* p = partK + (size_t)(h * 8) * ROWS + r;
        float s = 0.f;
        #pragma unroll
        for (int j = 0; j < 8; j++) s += p[(size_t)j * ROWS];
        diagK[r2] = 0.5f * SCALE2 * s;
    }
}

// ---------------------------------------------------------------------------
// kmax: per (b,h) global max over sequence of dK rowmax partials (4 colblocks)
// ---------------------------------------------------------------------------
__global__ __launch_bounds__(256)
void kmax_kernel(const float* __restrict__ rmxp, float* __restrict__ kmax)
{
    int bh = blockIdx.x;
    int b  = bh >> 1, h = bh & 1;
    __shared__ float sm[256];
    float mx = -1e30f;
    for (int l = threadIdx.x; l < SEQ; l += 256) {
        int r = b * 8192 + l * 2 + h;
        #pragma unroll
        for (int cb = 0; cb < 4; cb++)
            mx = fmaxf(mx, rmxp[(size_t)cb * ROWS2 + r]);
    }
    sm[threadIdx.x] = mx;
    __syncthreads();
    for (int s = 128; s; s >>= 1) {
        if (threadIdx.x < s) sm[threadIdx.x] = fmaxf(sm[threadIdx.x], sm[threadIdx.x + s]);
        __syncthreads();
    }
    if (threadIdx.x == 0) kmax[bh] = sm[0];
}

// ---------------------------------------------------------------------------
// f32 -> fp16 elementwise convert: three tensors in one launch (blockIdx.y)
// ---------------------------------------------------------------------------
__global__ __launch_bounds__(256)
void f2h3_kernel(const float* __restrict__ i0, __half* __restrict__ o0,
                 const float* __restrict__ i1, __half* __restrict__ o1,
                 const float* __restrict__ i2, __half* __restrict__ o2, size_t n)
{
    const float* in  = (blockIdx.y == 0) ? i0 : (blockIdx.y == 1) ? i1 : i2;
    __half*      out = (blockIdx.y == 0) ? o0 : (blockIdx.y == 1) ? o1 : o2;
    size_t i = ((size_t)blockIdx.x * blockDim.x + threadIdx.x) * 8;
    if (i >= n) return;
    float4 v0 = *reinterpret_cast<const float4*>(in + i);
    float4 v1 = *reinterpret_cast<const float4*>(in + i + 4);
    __half h[8];
    h[0]=__float2half_rn(v0.x); h[1]=__float2half_rn(v0.y);
    h[2]=__float2half_rn(v0.z); h[3]=__float2half_rn(v0.w);
    h[4]=__float2half_rn(v1.x); h[5]=__float2half_rn(v1.y);
    h[6]=__float2half_rn(v1.z); h[7]=__float2half_rn(v1.w);
    *reinterpret_cast<uint4*>(out + i) = *reinterpret_cast<uint4*>(h);
}

__global__ __launch_bounds__(256)
void f2h_kernel(const float* __restrict__ in, __half* __restrict__ out, size_t n)
{
    size_t i = ((size_t)blockIdx.x * blockDim.x + threadIdx.x) * 8;
    if (i >= n) return;
    float4 v0 = *reinterpret_cast<const float4*>(in + i);
    float4 v1 = *reinterpret_cast<const float4*>(in + i + 4);
    __half h[8];
    h[0]=__float2half_rn(v0.x); h[1]=__float2half_rn(v0.y);
    h[2]=__float2half_rn(v0.z); h[3]=__float2half_rn(v0.w);
    h[4]=__float2half_rn(v1.x); h[5]=__float2half_rn(v1.y);
    h[6]=__float2half_rn(v1.z); h[7]=__float2half_rn(v1.w);
    *reinterpret_cast<uint4*>(out + i) = *reinterpret_cast<uint4*>(h);
}

// ---------------------------------------------------------------------------
// transpose + convert: three square weights in one launch (blockIdx.z)
// ---------------------------------------------------------------------------
__global__ __launch_bounds__(256)
void tconv3_kernel(const float* __restrict__ w0, __half* __restrict__ o0,
                   const float* __restrict__ w1, __half* __restrict__ o1,
                   const float* __restrict__ w2, __half* __restrict__ o2)
{
    const float* in  = (blockIdx.z == 0) ? w0 : (blockIdx.z == 1) ? w1 : w2;
    __half*      out = (blockIdx.z == 0) ? o0 : (blockIdx.z == 1) ? o1 : o2;
    __shared__ float tile[32][33];
    int bx = blockIdx.x * 32;
    int by = blockIdx.y * 32;
    int tx = threadIdx.x & 31;
    int ty = threadIdx.x >> 5;
    #pragma unroll
    for (int i = 0; i < 32; i += 8)
        tile[ty + i][tx] = in[(size_t)(by + ty + i) * DMODEL + bx + tx];
    __syncthreads();
    #pragma unroll
    for (int i = 0; i < 32; i += 8)
        out[(size_t)(bx + ty + i) * DMODEL + by + tx] = __float2half_rn(tile[tx][ty + i]);
}

__global__ __launch_bounds__(256)
void tconv_kernel(const float* __restrict__ in, __half* __restrict__ out,
                  int R, int Cin)
{
    __shared__ float tile[32][33];
    int bx = blockIdx.x * 32;
    int by = blockIdx.y * 32;
    int tx = threadIdx.x & 31;
    int ty = threadIdx.x >> 5;
    #pragma unroll
    for (int i = 0; i < 32; i += 8)
        tile[ty + i][tx] = in[(size_t)(by + ty + i) * Cin + bx + tx];
    __syncthreads();
    #pragma unroll
    for (int i = 0; i < 32; i += 8)
        out[(size_t)(bx + ty + i) * R + by + tx] = __float2half_rn(tile[tx][ty + i]);
}

// ---------------------------------------------------------------------------
// Attention mix (fused q'/k'): per (s,h) block.
// ---------------------------------------------------------------------------
__global__ __launch_bounds__(256)
void attn_mix_kernel(const float* __restrict__ dQ, const float* __restrict__ dK,
                     const float* __restrict__ diagQ, const float* __restrict__ diagK,
                     const float* __restrict__ kmax,
                     const __half* __restrict__ Vh, __half* __restrict__ C)
{
    int blk = blockIdx.x;
    int s = blk >> 1, h = blk & 1;
    __shared__ float q_s[4][MFEAT];
    __shared__ float k_s[4][MFEAT];
    __shared__ float red[4][8];
    __shared__ float S[4][4];
    __shared__ float rs[4];
    int tid = threadIdx.x;
    int wid = tid >> 5, lane = tid & 31;

    float qv[4], kv[4];
    int ridx[4];
    #pragma unroll
    for (int bb = 0; bb < 4; bb++) {
        size_t r = (size_t)((bb*SEQ + s)*HEADS + h);
        ridx[bb] = (int)r;
        qv[bb] = dQ[r*MFEAT + tid];
        kv[bb] = dK[r*MFEAT + tid];
    }
    #pragma unroll
    for (int bb = 0; bb < 4; bb++) {
        float m = qv[bb];
        #pragma unroll
        for (int off = 16; off; off >>= 1)
            m = fmaxf(m, __shfl_xor_sync(0xffffffff, m, off));
        if (lane == 0) red[bb][wid] = m;
    }
    __syncthreads();
    #pragma unroll
    for (int bb = 0; bb < 4; bb++) {
        float qm = red[bb][0];
        #pragma unroll
        for (int w = 1; w < 8; w++) qm = fmaxf(qm, red[bb][w]);
        q_s[bb][tid] = RATIO * (expf(qv[bb] - diagQ[ridx[bb]] - qm) + EPS);
        k_s[bb][tid] = RATIO * (expf(kv[bb] - diagK[ridx[bb]] - kmax[bb*2 + h]) + EPS);
    }
    __syncthreads();

    int p = tid >> 4, lane16 = tid & 15;
    int bb = p >> 2, bp = p & 3;
    float acc = 0.f;
    #pragma unroll
    for (int m = 0; m < MFEAT; m += 16) acc += q_s[bb][m + lane16] * k_s[bp][m + lane16];
    #pragma unroll
    for (int off = 8; off; off >>= 1) acc += __shfl_down_sync(0xffffffff, acc, off, 16);
    if (lane16 == 0) S[bb][bp] = acc;
    __syncthreads();
    if (tid < 4) rs[tid] = S[tid][0] + S[tid][1] + S[tid][2] + S[tid][3];
    __syncthreads();

    float s00=S[0][0],s01=S[0][1],s02=S[0][2],s03=S[0][3];
    float s10=S[1][0],s11=S[1][1],s12=S[1][2],s13=S[1][3];
    float s20=S[2][0],s21=S[2][1],s22=S[2][2],s23=S[2][3];
    float s30=S[3][0],s31=S[3][1],s32=S[3][2],s33=S[3][3];
    float r0 = 1.f/rs[0], r1 = 1.f/rs[1], r2 = 1.f/rs[2], r3 = 1.f/rs[3];

    const __half2* V2 = reinterpret_cast<const __half2*>(Vh);
    __half2* C2 = reinterpret_cast<__half2*>(C);
    size_t cb2 = ((size_t)s*4096 + (size_t)h*2048) >> 1;
    int d2 = tid;
    {
        float2 v0 = __half22float2(V2[(size_t)((0*SEQ + s)*HEADS + h)*(DEPTH/2) + d2]);
        float2 v1 = __half22float2(V2[(size_t)((1*SEQ + s)*HEADS + h)*(DEPTH/2) + d2]);
        float2 v2 = __half22float2(V2[(size_t)((2*SEQ + s)*HEADS + h)*(DEPTH/2) + d2]);
        float2 v3 = __half22float2(V2[(size_t)((3*SEQ + s)*HEADS + h)*(DEPTH/2) + d2]);
        C2[cb2 + 0*256 + d2] = __floats2half2_rn((s00*v0.x + s01*v1.x + s02*v2.x + s03*v3.x) * r0,
                                                 (s00*v0.y + s01*v1.y + s02*v2.y + s03*v3.y) * r0);
        C2[cb2 + 1*256 + d2] = __floats2half2_rn((s10*v0.x + s11*v1.x + s12*v2.x + s13*v3.x) * r1,
                                                 (s10*v0.y + s11*v1.y + s12*v2.y + s13*v3.y) * r1);
        C2[cb2 + 2*256 + d2] = __floats2half2_rn((s20*v0.x + s21*v1.x + s22*v2.x + s23*v3.x) * r2,
                                                 (s20*v0.y + s21*v1.y + s22*v2.y + s23*v3.y) * r2);
        C2[cb2 + 3*256 + d2] = __floats2half2_rn((s30*v0.x + s31*v1.x + s32*v2.x + s33*v3.x) * r3,
                                                 (s30*v0.y + s31*v1.y + s32*v2.y + s33*v3.y) * r3);
    }
}

// ---------------------------------------------------------------------------
// Launch
// ---------------------------------------------------------------------------
extern "C" void kernel_launch(void* const* d_in, const int* in_sizes, int n_in,
                              void* d_out, int out_size)
{
    const float* query = (const float*)d_in[0];
    const float* key   = (const float*)d_in[1];
    const float* value = (const float*)d_in[2];
    const float* Wq = (const float*)d_in[4];
    const float* bq = (const float*)d_in[5];
    const float* Wk = (const float*)d_in[6];
    const float* bk = (const float*)d_in[7];
    const float* Wv = (const float*)d_in[8];
    const float* bv = (const float*)d_in[9];
    const float* Wo = (const float*)d_in[10];
    const float* bo = (const float*)d_in[11];
    const float* feats = (const float*)d_in[12];   // [256, 512] == [N, K]
    float* out = (float*)d_out;

    float *dQ, *dK, *diagQ, *diagK, *rmxp, *kmax, *sqpQ, *sqpK;
    __half *A0, *A1, *A2, *Qh, *Kh, *Vh, *W0, *W1, *W2, *fh, *Ch;
    cudaGetSymbolAddress((void**)&dQ,    g_dQ);
    cudaGetSymbolAddress((void**)&dK,    g_dK);
    cudaGetSymbolAddress((void**)&diagQ, g_diagQ);
    cudaGetSymbolAddress((void**)&diagK, g_diagK);
    cudaGetSymbolAddress((void**)&rmxp,  g_rmxp);
    cudaGetSymbolAddress((void**)&kmax,  g_kmax);
    cudaGetSymbolAddress((void**)&sqpQ,  g_sqpQ);
    cudaGetSymbolAddress((void**)&sqpK,  g_sqpK);
    cudaGetSymbolAddress((void**)&A0,    g_A0);
    cudaGetSymbolAddress((void**)&A1,    g_A1);
    cudaGetSymbolAddress((void**)&A2,    g_A2);
    cudaGetSymbolAddress((void**)&Qh,    g_Qh);
    cudaGetSymbolAddress((void**)&Kh,    g_Kh);
    cudaGetSymbolAddress((void**)&Vh,    g_Vh);
    cudaGetSymbolAddress((void**)&W0,    g_W0);
    cudaGetSymbolAddress((void**)&W1,    g_W1);
    cudaGetSymbolAddress((void**)&W2,    g_W2);
    cudaGetSymbolAddress((void**)&fh,    g_fh);
    cudaGetSymbolAddress((void**)&Ch,    g_Ch);

    cudaFuncSetAttribute(hgemm, cudaFuncAttributeMaxDynamicSharedMemorySize, HSMEM);

    const size_t NELEM = (size_t)ROWS * DMODEL;
    const unsigned gConv = (unsigned)((NELEM/8 + 255) / 256);
    const unsigned gR2   = (ROWS2 + 255) / 256;

    // 0: all fp16 conversions (inputs batched, weights batched, feats)
    {
        dim3 g(gConv, 3);
        f2h3_kernel<<<g, 256>>>(query, A0, key, A1, value, A2, NELEM);
        dim3 gT(DMODEL/32, DMODEL/32, 3);
        tconv3_kernel<<<gT, 256>>>(Wq, W0, Wk, W1, Wv, W2);
        f2h_kernel<<<(unsigned)((MFEAT*DEPTH/8 + 255)/256), 256>>>(feats, fh, MFEAT*DEPTH);
    }

    // 1: batched Q/K/V projections (one launch, z = 3)
    {
        GemmJobs jobs;
        jobs.j[0] = { A0, W0, bq, nullptr, Qh, sqpQ, nullptr };
        jobs.j[1] = { A1, W1, bk, nullptr, Kh, sqpK, nullptr };
        jobs.j[2] = { A2, W2, bv, nullptr, Vh, nullptr, nullptr };
        dim3 g(DMODEL/64, ROWS/128, 3);
        hgemm<<<g, 128, HSMEM>>>(jobs, ROWS, DMODEL, DMODEL, 1.f);
    }
    sqreduce_kernel<<<gR2, 256>>>(sqpQ, diagQ, sqpK, diagK);

    // 2: batched feature projections (z = 2)
    {
        GemmJobs jobs;
        jobs.j[0] = { Qh, fh, nullptr, dQ, nullptr, nullptr, nullptr };
        jobs.j[1] = { Kh, fh, nullptr, dK, nullptr, nullptr, rmxp };
        jobs.j[2] = jobs.j[0];
        dim3 g(MFEAT/64, ROWS2/128, 2);
        hgemm<<<g, 128, HSMEM>>>(jobs, ROWS2, MFEAT, DEPTH, FSCALE);
    }
    kmax_kernel<<<BATCH*HEADS, 256>>>(rmxp, kmax);

    // 3: fused q'/k' + attention mix -> fp16 concat
    attn_mix_kernel<<<SEQ*HEADS, 256>>>(dQ, dK, diagQ, diagK, kmax, Vh, Ch);

    // 4: out = C @ Wo + bo
    tconv_kernel<<<dim3(DMODEL/32, DMODEL/32), 256>>>(Wo, W2, DMODEL, DMODEL);
    {
        GemmJobs jobs;
        jobs.j[0] = { Ch, W2, bo, out, nullptr, nullptr, nullptr };
        jobs.j[1] = jobs.j[0];
        jobs.j[2] = jobs.j[0];
        dim3 g(DMODEL/64, ROWS/128, 1);
        hgemm<<<g, 128, HSMEM>>>(jobs, ROWS, DMODEL, DMODEL, 1.f);
    }
}

// round 13
// speedup vs baseline: 2.7004x; 1.0076x over previous
#include <cuda_runtime.h>
#include <cuda_fp16.h>
#include <math.h>
#include <stdint.h>

// ---------------------------------------------------------------------------
// Problem constants
// ---------------------------------------------------------------------------
#define BATCH     4
#define SEQ       4096
#define DMODEL    1024
#define HEADS     2
#define DEPTH     512
#define MFEAT     256
#define ROWS      (BATCH*SEQ)          // 16384
#define ROWS2     (ROWS*HEADS)         // 32768

#define SCALE2    0.044194173824159216f   // 1/sqrt(512)
#define FSCALE    0.21022410381342864f    // 512^{-0.25}
#define RATIO     0.0625f                 // 1/sqrt(256)
#define EPS       1e-6f

// ---------------------------------------------------------------------------
// Scratch (device globals; allocation is banned)
// ---------------------------------------------------------------------------
__device__ __half g_dQh[ (size_t)ROWS2 * MFEAT ];    // fp16 dash_q
__device__ __half g_dKh[ (size_t)ROWS2 * MFEAT ];    // fp16 dash_k
__device__ float  g_diagQ[ ROWS2 ];
__device__ float  g_diagK[ ROWS2 ];
__device__ float  g_rmxp [ 4 * ROWS2 ];              // per-colblock rowmax partials
__device__ float  g_kmax [ BATCH*HEADS ];
__device__ float  g_sqpQ[ 16 * ROWS ];               // per-colblock Σy² partials (Q)
__device__ float  g_sqpK[ 16 * ROWS ];               // (K)
__device__ __half g_A0 [ (size_t)ROWS * DMODEL ];    // fp16 query
__device__ __half g_A1 [ (size_t)ROWS * DMODEL ];    // fp16 key
__device__ __half g_A2 [ (size_t)ROWS * DMODEL ];    // fp16 value
__device__ __half g_Qh [ (size_t)ROWS * DMODEL ];    // fp16 Q
__device__ __half g_Kh [ (size_t)ROWS * DMODEL ];    // fp16 K
__device__ __half g_Vh [ (size_t)ROWS * DMODEL ];    // fp16 V
__device__ __half g_W0 [ (size_t)DMODEL * DMODEL ];  // fp16 Wq^T
__device__ __half g_W1 [ (size_t)DMODEL * DMODEL ];  // fp16 Wk^T
__device__ __half g_W2 [ (size_t)DMODEL * DMODEL ];  // fp16 Wv^T (reused for Wo^T)
__device__ __half g_fh [ (size_t)MFEAT * DEPTH ];    // fp16 feats
__device__ __half g_Ch [ (size_t)ROWS * DMODEL ];    // fp16 concat

// ---------------------------------------------------------------------------
// helpers
// ---------------------------------------------------------------------------
__device__ __forceinline__ uint32_t smem_u32(const void* p) {
    uint32_t a;
    asm("{ .reg .u64 t; cvta.to.shared.u64 t, %1; cvt.u32.u64 %0, t; }"
        : "=r"(a) : "l"(p));
    return a;
}

__device__ __forceinline__ void ldsm_x4(uint32_t& r0, uint32_t& r1,
                                        uint32_t& r2, uint32_t& r3, uint32_t addr) {
    asm volatile("ldmatrix.sync.aligned.m8n8.x4.shared.b16 {%0,%1,%2,%3}, [%4];"
                 : "=r"(r0), "=r"(r1), "=r"(r2), "=r"(r3) : "r"(addr));
}

__device__ __forceinline__ void mma_f16(float c[4], const uint32_t a[4],
                                        const uint32_t b[2]) {
    asm volatile(
        "mma.sync.aligned.m16n8k16.row.col.f32.f16.f16.f32 "
        "{%0,%1,%2,%3}, {%4,%5,%6,%7}, {%8,%9}, {%0,%1,%2,%3};"
        : "+f"(c[0]), "+f"(c[1]), "+f"(c[2]), "+f"(c[3])
        : "r"(a[0]), "r"(a[1]), "r"(a[2]), "r"(a[3]),
          "r"(b[0]), "r"(b[1]));
}

__device__ __forceinline__ void cp_async16(uint32_t smem, const void* gmem) {
    asm volatile("cp.async.cg.shared.global [%0], [%1], 16;"
                 :: "r"(smem), "l"(gmem) : "memory");
}
#define CP_COMMIT()  asm volatile("cp.async.commit_group;" ::: "memory")
#define CP_WAIT0()   asm volatile("cp.async.wait_group 0;" ::: "memory")

// ---------------------------------------------------------------------------
// Batched fp16 GEMM jobs (selected by blockIdx.z)
// ---------------------------------------------------------------------------
struct GemmJob {
    const __half* A;      // [M,K]
    const __half* Bop;    // [N,K]
    const float*  bias;   // [N] or null
    float*        C;      // fp32 out or null
    __half*       Ch;     // fp16 out or null
    float*        sq;     // per-row sum-sq partials [N/64][M] or null
    float*        rmx;    // per-row max partials [N/64][M] or null
};
struct GemmJobs { GemmJob j[3]; };

// ---------------------------------------------------------------------------
// fp16 GEMM (fp32 accumulate):  C = alpha * A(M,K) @ Bop(N,K)^T (+ bias)
//   128 threads/CTA, tile 128(M) x 64(N), warp tile 64x32 (2x2 warps),
//   2-stage cp.async pipeline, K-step 64, A-fragment double buffering.
//   Requires M%128, N%64, K%64==0, K>=128.
// ---------------------------------------------------------------------------
#define ASTR   72                       // halves per row: 64 + 8 pad (144B)
#define STG_A  (128*ASTR)               // 9216 halves
#define STG_B  (64*ASTR)                // 4608 halves
#define STG_T  (STG_A + STG_B)          // 13824 halves / stage
#define HSMEM  (2 * STG_T * 2)          // bytes = 55296

__global__ __launch_bounds__(128, 4)
void hgemm(GemmJobs jobs, int M, int N, int K, float alpha)
{
    extern __shared__ __half sm[];
    const GemmJob job = jobs.j[blockIdx.z];
    const __half* __restrict__ A   = job.A;
    const __half* __restrict__ Bop = job.Bop;

    const int tid  = threadIdx.x;
    const int lane = tid & 31;
    const int wid  = tid >> 5;            // 0..3
    const int bm = blockIdx.y * 128;
    const int bn = blockIdx.x * 64;

    const int warp_m = (wid & 1) * 64;
    const int warp_n = (wid >> 1) * 32;
    const int lr = lane >> 2;
    const int lc = lane & 3;

    const uint32_t smb = smem_u32(sm);

    auto issue_stage = [&](int s, int k0) {
        const int slot = s & 1;
        const uint32_t abase = smb + (uint32_t)(slot * STG_T) * 2;
        const uint32_t bbase = abase + (uint32_t)STG_A * 2;
        #pragma unroll
        for (int c = 0; c < 8; c++) {
            int chunk = tid + 128 * c;
            int row = chunk >> 3;
            int col = (chunk & 7) * 8;
            cp_async16(abase + (uint32_t)(row * ASTR + col) * 2,
                       A + (size_t)(bm + row) * K + k0 + col);
        }
        #pragma unroll
        for (int c = 0; c < 4; c++) {
            int chunk = tid + 128 * c;
            int row = chunk >> 3;
            int col = (chunk & 7) * 8;
            cp_async16(bbase + (uint32_t)(row * ASTR + col) * 2,
                       Bop + (size_t)(bn + row) * K + k0 + col);
        }
        CP_COMMIT();
    };

    float acc[4][4][4];
    #pragma unroll
    for (int i = 0; i < 4; i++)
        #pragma unroll
        for (int j = 0; j < 4; j++)
            #pragma unroll
            for (int r = 0; r < 4; r++) acc[i][j][r] = 0.f;

    const int a_lrow = (lane & 7) + ((lane >> 3) & 1) * 8;
    const int a_lcol = (lane >> 4) * 8;
    const int b_lrow = (lane & 7) + (lane >= 16 ? 8 : 0);
    const int b_lcol = ((lane >> 3) & 1) * 8;

    const int nst = K >> 6;
    issue_stage(0, 0);

    for (int s = 0; s < nst; s++) {
        CP_WAIT0();
        __syncthreads();

        if (s + 1 < nst) issue_stage(s + 1, (s + 1) << 6);

        const __half* As = sm + (s & 1) * STG_T;
        const __half* Bs = As + STG_A;

        uint32_t fa[2][4][4];
        #pragma unroll
        for (int mi = 0; mi < 4; mi++) {
            uint32_t addr = smem_u32(
                &As[(warp_m + mi * 16 + a_lrow) * ASTR + a_lcol]);
            ldsm_x4(fa[0][mi][0], fa[0][mi][1], fa[0][mi][2], fa[0][mi][3], addr);
        }

        #pragma unroll
        for (int kk = 0; kk < 4; kk++) {
            const int pb = kk & 1;
            uint32_t fb[4][2];
            #pragma unroll
            for (int nj = 0; nj < 2; nj++) {
                uint32_t addr = smem_u32(
                    &Bs[(warp_n + nj * 16 + b_lrow) * ASTR + kk * 16 + b_lcol]);
                ldsm_x4(fb[2*nj][0], fb[2*nj][1], fb[2*nj+1][0], fb[2*nj+1][1], addr);
            }
            if (kk < 3) {
                #pragma unroll
                for (int mi = 0; mi < 4; mi++) {
                    uint32_t addr = smem_u32(
                        &As[(warp_m + mi * 16 + a_lrow) * ASTR + (kk + 1) * 16 + a_lcol]);
                    ldsm_x4(fa[pb^1][mi][0], fa[pb^1][mi][1],
                            fa[pb^1][mi][2], fa[pb^1][mi][3], addr);
                }
            }
            #pragma unroll
            for (int mi = 0; mi < 4; mi++)
                #pragma unroll
                for (int ni = 0; ni < 4; ni++)
                    mma_f16(acc[mi][ni], fa[pb][mi], fb[ni]);
        }
    }

    // epilogue (+ optional per-row Σv² / rowmax partials)
    float sA[4], sB[4], mA[4], mB[4];
    #pragma unroll
    for (int mi = 0; mi < 4; mi++) {
        sA[mi] = 0.f; sB[mi] = 0.f; mA[mi] = -1e30f; mB[mi] = -1e30f;
    }

    #pragma unroll
    for (int mi = 0; mi < 4; mi++) {
        #pragma unroll
        for (int ni = 0; ni < 4; ni++) {
            int row = bm + warp_m + mi * 16 + lr;
            int col = bn + warp_n + ni * 8 + 2 * lc;
            float b0 = job.bias ? job.bias[col]     : 0.f;
            float b1 = job.bias ? job.bias[col + 1] : 0.f;
            float2 v0 = make_float2(alpha * acc[mi][ni][0] + b0,
                                    alpha * acc[mi][ni][1] + b1);
            float2 v1 = make_float2(alpha * acc[mi][ni][2] + b0,
                                    alpha * acc[mi][ni][3] + b1);
            if (job.C) {
                *reinterpret_cast<float2*>(&job.C[(size_t)row * N + col])       = v0;
                *reinterpret_cast<float2*>(&job.C[(size_t)(row + 8) * N + col]) = v1;
            }
            if (job.Ch) {
                *reinterpret_cast<__half2*>(&job.Ch[(size_t)row * N + col]) =
                    __floats2half2_rn(v0.x, v0.y);
                *reinterpret_cast<__half2*>(&job.Ch[(size_t)(row + 8) * N + col]) =
                    __floats2half2_rn(v1.x, v1.y);
            }
            if (job.sq) {
                sA[mi] += v0.x * v0.x + v0.y * v0.y;
                sB[mi] += v1.x * v1.x + v1.y * v1.y;
            }
            if (job.rmx) {
                mA[mi] = fmaxf(mA[mi], fmaxf(v0.x, v0.y));
                mB[mi] = fmaxf(mB[mi], fmaxf(v1.x, v1.y));
            }
        }
    }

    float* smf = reinterpret_cast<float*>(sm);  // [2][128] floats
    if (job.sq) {
        #pragma unroll
        for (int mi = 0; mi < 4; mi++) {
            #pragma unroll
            for (int o = 1; o <= 2; o <<= 1) {
                sA[mi] += __shfl_xor_sync(0xffffffff, sA[mi], o);
                sB[mi] += __shfl_xor_sync(0xffffffff, sB[mi], o);
            }
        }
        __syncthreads();
        if (lc == 0) {
            #pragma unroll
            for (int mi = 0; mi < 4; mi++) {
                smf[(wid >> 1) * 128 + warp_m + mi * 16 + lr]     = sA[mi];
                smf[(wid >> 1) * 128 + warp_m + mi * 16 + lr + 8] = sB[mi];
            }
        }
        __syncthreads();
        {
            float t = smf[tid] + smf[128 + tid];
            job.sq[(size_t)blockIdx.x * M + bm + tid] = t;
        }
    }
    if (job.rmx) {
        #pragma unroll
        for (int mi = 0; mi < 4; mi++) {
            #pragma unroll
            for (int o = 1; o <= 2; o <<= 1) {
                mA[mi] = fmaxf(mA[mi], __shfl_xor_sync(0xffffffff, mA[mi], o));
                mB[mi] = fmaxf(mB[mi], __shfl_xor_sync(0xffffffff, mB[mi], o));
            }
        }
        __syncthreads();
        if (lc == 0) {
            #pragma unroll
            for (int mi = 0; mi < 4; mi++) {
                smf[(wid >> 1) * 128 + warp_m + mi * 16 + lr]     = mA[mi];
                smf[(wid >> 1) * 128 + warp_m + mi * 16 + lr + 8] = mB[mi];
            }
        }
        __syncthreads();
        {
            float t = fmaxf(smf[tid], smf[128 + tid]);
            job.rmx[(size_t)blockIdx.x * M + bm + tid] = t;
        }
    }
}

// ---------------------------------------------------------------------------
// diag reduce: diag[r*2+h] = 0.5*SCALE2 * sum_{j<8} part[(h*8+j)*ROWS + r]
// ---------------------------------------------------------------------------
__global__ __launch_bounds__(256)
void sqreduce_kernel(const float* __restrict__ partQ, float* __restrict__ diagQ,
                     const float* __restrict__ partK, float* __restrict__ diagK)
{
    int r2 = blockIdx.x * blockDim.x + threadIdx.x;
    if (r2 >= ROWS2) return;
    int r = r2 >> 1, h = r2 & 1;
    {
        const float* p = partQ + (size_t)(h * 8) * ROWS + r;
        float s = 0.f;
        #pragma unroll
        for (int j = 0; j < 8; j++) s += p[(size_t)j * ROWS];
        diagQ[r2] = 0.5f * SCALE2 * s;
    }
    {
        const float* p = partK + (size_t)(h * 8) * ROWS + r;
        float s = 0.f;
        #pragma unroll
        for (int j = 0; j < 8; j++) s += p[(size_t)j * ROWS];
        diagK[r2] = 0.5f * SCALE2 * s;
    }
}

// ---------------------------------------------------------------------------
// kmax: per (b,h) global max over sequence of dK rowmax partials (4 colblocks)
// ---------------------------------------------------------------------------
__global__ __launch_bounds__(256)
void kmax_kernel(const float* __restrict__ rmxp, float* __restrict__ kmax)
{
    int bh = blockIdx.x;
    int b  = bh >> 1, h = bh & 1;
    __shared__ float sm[256];
    float mx = -1e30f;
    for (int l = threadIdx.x; l < SEQ; l += 256) {
        int r = b * 8192 + l * 2 + h;
        #pragma unroll
        for (int cb = 0; cb < 4; cb++)
            mx = fmaxf(mx, rmxp[(size_t)cb * ROWS2 + r]);
    }
    sm[threadIdx.x] = mx;
    __syncthreads();
    for (int s = 128; s; s >>= 1) {
        if (threadIdx.x < s) sm[threadIdx.x] = fmaxf(sm[threadIdx.x], sm[threadIdx.x + s]);
        __syncthreads();
    }
    if (threadIdx.x == 0) kmax[bh] = sm[0];
}

// ---------------------------------------------------------------------------
// f32 -> fp16 elementwise convert: three tensors in one launch (blockIdx.y)
// ---------------------------------------------------------------------------
__global__ __launch_bounds__(256)
void f2h3_kernel(const float* __restrict__ i0, __half* __restrict__ o0,
                 const float* __restrict__ i1, __half* __restrict__ o1,
                 const float* __restrict__ i2, __half* __restrict__ o2, size_t n)
{
    const float* in  = (blockIdx.y == 0) ? i0 : (blockIdx.y == 1) ? i1 : i2;
    __half*      out = (blockIdx.y == 0) ? o0 : (blockIdx.y == 1) ? o1 : o2;
    size_t i = ((size_t)blockIdx.x * blockDim.x + threadIdx.x) * 8;
    if (i >= n) return;
    float4 v0 = *reinterpret_cast<const float4*>(in + i);
    float4 v1 = *reinterpret_cast<const float4*>(in + i + 4);
    __half h[8];
    h[0]=__float2half_rn(v0.x); h[1]=__float2half_rn(v0.y);
    h[2]=__float2half_rn(v0.z); h[3]=__float2half_rn(v0.w);
    h[4]=__float2half_rn(v1.x); h[5]=__float2half_rn(v1.y);
    h[6]=__float2half_rn(v1.z); h[7]=__float2half_rn(v1.w);
    *reinterpret_cast<uint4*>(out + i) = *reinterpret_cast<uint4*>(h);
}

__global__ __launch_bounds__(256)
void f2h_kernel(const float* __restrict__ in, __half* __restrict__ out, size_t n)
{
    size_t i = ((size_t)blockIdx.x * blockDim.x + threadIdx.x) * 8;
    if (i >= n) return;
    float4 v0 = *reinterpret_cast<const float4*>(in + i);
    float4 v1 = *reinterpret_cast<const float4*>(in + i + 4);
    __half h[8];
    h[0]=__float2half_rn(v0.x); h[1]=__float2half_rn(v0.y);
    h[2]=__float2half_rn(v0.z); h[3]=__float2half_rn(v0.w);
    h[4]=__float2half_rn(v1.x); h[5]=__float2half_rn(v1.y);
    h[6]=__float2half_rn(v1.z); h[7]=__float2half_rn(v1.w);
    *reinterpret_cast<uint4*>(out + i) = *reinterpret_cast<uint4*>(h);
}

// ---------------------------------------------------------------------------
// transpose + convert: three square weights in one launch (blockIdx.z)
// ---------------------------------------------------------------------------
__global__ __launch_bounds__(256)
void tconv3_kernel(const float* __restrict__ w0, __half* __restrict__ o0,
                   const float* __restrict__ w1, __half* __restrict__ o1,
                   const float* __restrict__ w2, __half* __restrict__ o2)
{
    const float* in  = (blockIdx.z == 0) ? w0 : (blockIdx.z == 1) ? w1 : w2;
    __half*      out = (blockIdx.z == 0) ? o0 : (blockIdx.z == 1) ? o1 : o2;
    __shared__ float tile[32][33];
    int bx = blockIdx.x * 32;
    int by = blockIdx.y * 32;
    int tx = threadIdx.x & 31;
    int ty = threadIdx.x >> 5;
    #pragma unroll
    for (int i = 0; i < 32; i += 8)
        tile[ty + i][tx] = in[(size_t)(by + ty + i) * DMODEL + bx + tx];
    __syncthreads();
    #pragma unroll
    for (int i = 0; i < 32; i += 8)
        out[(size_t)(bx + ty + i) * DMODEL + by + tx] = __float2half_rn(tile[tx][ty + i]);
}

__global__ __launch_bounds__(256)
void tconv_kernel(const float* __restrict__ in, __half* __restrict__ out,
                  int R, int Cin)
{
    __shared__ float tile[32][33];
    int bx = blockIdx.x * 32;
    int by = blockIdx.y * 32;
    int tx = threadIdx.x & 31;
    int ty = threadIdx.x >> 5;
    #pragma unroll
    for (int i = 0; i < 32; i += 8)
        tile[ty + i][tx] = in[(size_t)(by + ty + i) * Cin + bx + tx];
    __syncthreads();
    #pragma unroll
    for (int i = 0; i < 32; i += 8)
        out[(size_t)(bx + ty + i) * R + by + tx] = __float2half_rn(tile[tx][ty + i]);
}

// ---------------------------------------------------------------------------
// Attention mix (fused q'/k'): per (s,h) block. fp16 dash in.
// ---------------------------------------------------------------------------
__global__ __launch_bounds__(256)
void attn_mix_kernel(const __half* __restrict__ dQ, const __half* __restrict__ dK,
                     const float* __restrict__ diagQ, const float* __restrict__ diagK,
                     const float* __restrict__ kmax,
                     const __half* __restrict__ Vh, __half* __restrict__ C)
{
    int blk = blockIdx.x;
    int s = blk >> 1, h = blk & 1;
    __shared__ float q_s[4][MFEAT];
    __shared__ float k_s[4][MFEAT];
    __shared__ float red[4][8];
    __shared__ float S[4][4];
    __shared__ float rs[4];
    int tid = threadIdx.x;
    int wid = tid >> 5, lane = tid & 31;

    float qv[4], kv[4];
    int ridx[4];
    #pragma unroll
    for (int bb = 0; bb < 4; bb++) {
        size_t r = (size_t)((bb*SEQ + s)*HEADS + h);
        ridx[bb] = (int)r;
        qv[bb] = __half2float(dQ[r*MFEAT + tid]);
        kv[bb] = __half2float(dK[r*MFEAT + tid]);
    }
    #pragma unroll
    for (int bb = 0; bb < 4; bb++) {
        float m = qv[bb];
        #pragma unroll
        for (int off = 16; off; off >>= 1)
            m = fmaxf(m, __shfl_xor_sync(0xffffffff, m, off));
        if (lane == 0) red[bb][wid] = m;
    }
    __syncthreads();
    #pragma unroll
    for (int bb = 0; bb < 4; bb++) {
        float qm = red[bb][0];
        #pragma unroll
        for (int w = 1; w < 8; w++) qm = fmaxf(qm, red[bb][w]);
        q_s[bb][tid] = RATIO * (expf(qv[bb] - diagQ[ridx[bb]] - qm) + EPS);
        k_s[bb][tid] = RATIO * (expf(kv[bb] - diagK[ridx[bb]] - kmax[bb*2 + h]) + EPS);
    }
    __syncthreads();

    int p = tid >> 4, lane16 = tid & 15;
    int bb = p >> 2, bp = p & 3;
    float acc = 0.f;
    #pragma unroll
    for (int m = 0; m < MFEAT; m += 16) acc += q_s[bb][m + lane16] * k_s[bp][m + lane16];
    #pragma unroll
    for (int off = 8; off; off >>= 1) acc += __shfl_down_sync(0xffffffff, acc, off, 16);
    if (lane16 == 0) S[bb][bp] = acc;
    __syncthreads();
    if (tid < 4) rs[tid] = S[tid][0] + S[tid][1] + S[tid][2] + S[tid][3];
    __syncthreads();

    float s00=S[0][0],s01=S[0][1],s02=S[0][2],s03=S[0][3];
    float s10=S[1][0],s11=S[1][1],s12=S[1][2],s13=S[1][3];
    float s20=S[2][0],s21=S[2][1],s22=S[2][2],s23=S[2][3];
    float s30=S[3][0],s31=S[3][1],s32=S[3][2],s33=S[3][3];
    float r0 = 1.f/rs[0], r1 = 1.f/rs[1], r2 = 1.f/rs[2], r3 = 1.f/rs[3];

    const __half2* V2 = reinterpret_cast<const __half2*>(Vh);
    __half2* C2 = reinterpret_cast<__half2*>(C);
    size_t cb2 = ((size_t)s*4096 + (size_t)h*2048) >> 1;
    int d2 = tid;
    {
        float2 v0 = __half22float2(V2[(size_t)((0*SEQ + s)*HEADS + h)*(DEPTH/2) + d2]);
        float2 v1 = __half22float2(V2[(size_t)((1*SEQ + s)*HEADS + h)*(DEPTH/2) + d2]);
        float2 v2 = __half22float2(V2[(size_t)((2*SEQ + s)*HEADS + h)*(DEPTH/2) + d2]);
        float2 v3 = __half22float2(V2[(size_t)((3*SEQ + s)*HEADS + h)*(DEPTH/2) + d2]);
        C2[cb2 + 0*256 + d2] = __floats2half2_rn((s00*v0.x + s01*v1.x + s02*v2.x + s03*v3.x) * r0,
                                                 (s00*v0.y + s01*v1.y + s02*v2.y + s03*v3.y) * r0);
        C2[cb2 + 1*256 + d2] = __floats2half2_rn((s10*v0.x + s11*v1.x + s12*v2.x + s13*v3.x) * r1,
                                                 (s10*v0.y + s11*v1.y + s12*v2.y + s13*v3.y) * r1);
        C2[cb2 + 2*256 + d2] = __floats2half2_rn((s20*v0.x + s21*v1.x + s22*v2.x + s23*v3.x) * r2,
                                                 (s20*v0.y + s21*v1.y + s22*v2.y + s23*v3.y) * r2);
        C2[cb2 + 3*256 + d2] = __floats2half2_rn((s30*v0.x + s31*v1.x + s32*v2.x + s33*v3.x) * r3,
                                                 (s30*v0.y + s31*v1.y + s32*v2.y + s33*v3.y) * r3);
    }
}

// ---------------------------------------------------------------------------
// Launch
// ---------------------------------------------------------------------------
extern "C" void kernel_launch(void* const* d_in, const int* in_sizes, int n_in,
                              void* d_out, int out_size)
{
    const float* query = (const float*)d_in[0];
    const float* key   = (const float*)d_in[1];
    const float* value = (const float*)d_in[2];
    const float* Wq = (const float*)d_in[4];
    const float* bq = (const float*)d_in[5];
    const float* Wk = (const float*)d_in[6];
    const float* bk = (const float*)d_in[7];
    const float* Wv = (const float*)d_in[8];
    const float* bv = (const float*)d_in[9];
    const float* Wo = (const float*)d_in[10];
    const float* bo = (const float*)d_in[11];
    const float* feats = (const float*)d_in[12];   // [256, 512] == [N, K]
    float* out = (float*)d_out;

    float *diagQ, *diagK, *rmxp, *kmax, *sqpQ, *sqpK;
    __half *dQh, *dKh, *A0, *A1, *A2, *Qh, *Kh, *Vh, *W0, *W1, *W2, *fh, *Ch;
    cudaGetSymbolAddress((void**)&dQh,   g_dQh);
    cudaGetSymbolAddress((void**)&dKh,   g_dKh);
    cudaGetSymbolAddress((void**)&diagQ, g_diagQ);
    cudaGetSymbolAddress((void**)&diagK, g_diagK);
    cudaGetSymbolAddress((void**)&rmxp,  g_rmxp);
    cudaGetSymbolAddress((void**)&kmax,  g_kmax);
    cudaGetSymbolAddress((void**)&sqpQ,  g_sqpQ);
    cudaGetSymbolAddress((void**)&sqpK,  g_sqpK);
    cudaGetSymbolAddress((void**)&A0,    g_A0);
    cudaGetSymbolAddress((void**)&A1,    g_A1);
    cudaGetSymbolAddress((void**)&A2,    g_A2);
    cudaGetSymbolAddress((void**)&Qh,    g_Qh);
    cudaGetSymbolAddress((void**)&Kh,    g_Kh);
    cudaGetSymbolAddress((void**)&Vh,    g_Vh);
    cudaGetSymbolAddress((void**)&W0,    g_W0);
    cudaGetSymbolAddress((void**)&W1,    g_W1);
    cudaGetSymbolAddress((void**)&W2,    g_W2);
    cudaGetSymbolAddress((void**)&fh,    g_fh);
    cudaGetSymbolAddress((void**)&Ch,    g_Ch);

    cudaFuncSetAttribute(hgemm, cudaFuncAttributeMaxDynamicSharedMemorySize, HSMEM);

    const size_t NELEM = (size_t)ROWS * DMODEL;
    const unsigned gConv = (unsigned)((NELEM/8 + 255) / 256);
    const unsigned gR2   = (ROWS2 + 255) / 256;

    // 0: all fp16 conversions (inputs batched, weights batched, feats)
    {
        dim3 g(gConv, 3);
        f2h3_kernel<<<g, 256>>>(query, A0, key, A1, value, A2, NELEM);
        dim3 gT(DMODEL/32, DMODEL/32, 3);
        tconv3_kernel<<<gT, 256>>>(Wq, W0, Wk, W1, Wv, W2);
        f2h_kernel<<<(unsigned)((MFEAT*DEPTH/8 + 255)/256), 256>>>(feats, fh, MFEAT*DEPTH);
    }

    // 1: batched Q/K/V projections (one launch, z = 3)
    {
        GemmJobs jobs;
        jobs.j[0] = { A0, W0, bq, nullptr, Qh, sqpQ, nullptr };
        jobs.j[1] = { A1, W1, bk, nullptr, Kh, sqpK, nullptr };
        jobs.j[2] = { A2, W2, bv, nullptr, Vh, nullptr, nullptr };
        dim3 g(DMODEL/64, ROWS/128, 3);
        hgemm<<<g, 128, HSMEM>>>(jobs, ROWS, DMODEL, DMODEL, 1.f);
    }
    sqreduce_kernel<<<gR2, 256>>>(sqpQ, diagQ, sqpK, diagK);

    // 2: batched feature projections (z = 2), fp16 dash outputs
    {
        GemmJobs jobs;
        jobs.j[0] = { Qh, fh, nullptr, nullptr, dQh, nullptr, nullptr };
        jobs.j[1] = { Kh, fh, nullptr, nullptr, dKh, nullptr, rmxp };
        jobs.j[2] = jobs.j[0];
        dim3 g(MFEAT/64, ROWS2/128, 2);
        hgemm<<<g, 128, HSMEM>>>(jobs, ROWS2, MFEAT, DEPTH, FSCALE);
    }
    kmax_kernel<<<BATCH*HEADS, 256>>>(rmxp, kmax);

    // 3: fused q'/k' + attention mix -> fp16 concat
    attn_mix_kernel<<<SEQ*HEADS, 256>>>(dQh, dKh, diagQ, diagK, kmax, Vh, Ch);

    // 4: out = C @ Wo + bo
    tconv_kernel<<<dim3(DMODEL/32, DMODEL/32), 256>>>(Wo, W2, DMODEL, DMODEL);
    {
        GemmJobs jobs;
        jobs.j[0] = { Ch, W2, bo, out, nullptr, nullptr, nullptr };
        jobs.j[1] = jobs.j[0];
        jobs.j[2] = jobs.j[0];
        dim3 g(DMODEL/64, ROWS/128, 1);
        hgemm<<<g, 128, HSMEM>>>(jobs, ROWS, DMODEL, DMODEL, 1.f);
    }
}